// round 1
// baseline (speedup 1.0000x reference)
#include <cuda_runtime.h>
#include <math.h>

// ---------------- problem constants ----------------
#define BATCH 16
#define NPTS  4096
#define DFEAT 64
#define SPTS  1024
#define NSAMP 32
#define CH0   67          // 3 + DFEAT
#define CH1   64
#define CH2   128
#define CH3   256
#define MTOT  (BATCH*SPTS*NSAMP)   // 524288 rows through the MLP
#define MBLK  (MTOT/128)           // 4096 M-blocks (BM=128)
#define RAD2  0.04f                // f32(0.04) — matches jnp weak-typed compare
#define BNEPS 1e-5f

// ---------------- device scratch (static: no allocs allowed) ----------------
__device__ float g_x0[(size_t)MTOT*CH0];   // gathered+concat features
__device__ float g_y1[(size_t)MTOT*CH1];   // raw (pre-BN) layer outputs
__device__ float g_y2[(size_t)MTOT*CH2];
__device__ float g_y3[(size_t)MTOT*CH3];
__device__ int   g_gidx[BATCH*SPTS*NSAMP];
__device__ float g_part[2*(size_t)MBLK*CH3];  // per-Mblock column partials (sum, sumsq)
__device__ float g_scale[CH3];
__device__ float g_shift[CH3];

// ---------------- FPS: one block per batch, dist in registers ----------------
__global__ __launch_bounds__(256) void fps_kernel(const float* __restrict__ xyz,
                                                  float* __restrict__ new_xyz)
{
    const int b   = blockIdx.x;
    const int tid = threadIdx.x;
    const float* X = xyz + (size_t)b * NPTS * 3;

    float px[16], py[16], pz[16], dist[16];
#pragma unroll
    for (int t = 0; t < 16; t++) {
        int j = tid + t * 256;
        px[t] = X[3*j]; py[t] = X[3*j+1]; pz[t] = X[3*j+2];
        dist[t] = 1e10f;
    }

    __shared__ float s_val[8];
    __shared__ int   s_idx[8];
    __shared__ int   s_far;

    const int lane = tid & 31, wid = tid >> 5;
    int far = 0;

    for (int i = 0; i < SPTS; i++) {
        float cx = X[3*far], cy = X[3*far+1], cz = X[3*far+2];
        if (tid == 0) {
            float* o = new_xyz + ((size_t)b * SPTS + i) * 3;
            o[0] = cx; o[1] = cy; o[2] = cz;
        }
        if (i == SPTS - 1) break;

        float bv = -1.0f; int bi = 0;
#pragma unroll
        for (int t = 0; t < 16; t++) {
            float dx = px[t]-cx, dy = py[t]-cy, dz = pz[t]-cz;
            float d  = dx*dx + dy*dy + dz*dz;
            float nd = fminf(dist[t], d);
            dist[t]  = nd;
            if (nd > bv) { bv = nd; bi = tid + t*256; }  // ascending idx in t -> first-max kept
        }
        // warp argmax (lowest index on ties)
#pragma unroll
        for (int off = 16; off > 0; off >>= 1) {
            float ov = __shfl_down_sync(0xffffffffu, bv, off);
            int   oi = __shfl_down_sync(0xffffffffu, bi, off);
            if (ov > bv || (ov == bv && oi < bi)) { bv = ov; bi = oi; }
        }
        if (lane == 0) { s_val[wid] = bv; s_idx[wid] = bi; }
        __syncthreads();
        if (tid == 0) {
            bv = s_val[0]; bi = s_idx[0];
#pragma unroll
            for (int w = 1; w < 8; w++)
                if (s_val[w] > bv || (s_val[w] == bv && s_idx[w] < bi)) { bv = s_val[w]; bi = s_idx[w]; }
            s_far = bi;
        }
        __syncthreads();
        far = s_far;
    }
}

// ---------------- ball query: warp per centroid, ballot-ranked collection ----------------
__global__ __launch_bounds__(256) void ballquery_kernel(const float* __restrict__ xyz,
                                                        const float* __restrict__ new_xyz,
                                                        int* __restrict__ gidx)
{
    const int w    = blockIdx.x * 8 + (threadIdx.x >> 5);   // centroid id, 0..B*SPTS-1
    const int lane = threadIdx.x & 31;
    const int b    = w >> 10;
    const float* X = xyz + (size_t)b * NPTS * 3;

    const float cx = new_xyz[(size_t)w*3+0];
    const float cy = new_xyz[(size_t)w*3+1];
    const float cz = new_xyz[(size_t)w*3+2];
    const float ss = cx*cx + cy*cy + cz*cz;

    int cnt = 0, firstIdx = 0;
    int* out = gidx + (size_t)w * NSAMP;

    for (int base = 0; base < NPTS && cnt < NSAMP; base += 32) {
        const int j = base + lane;
        const float x = X[3*j], y = X[3*j+1], z = X[3*j+2];
        const float pp  = x*x + y*y + z*z;
        const float dot = x*cx + y*cy + z*cz;
        const float d   = (-2.0f*dot + ss) + pp;   // mirrors reference add order
        const bool  in  = !(d > RAD2);
        unsigned mask = __ballot_sync(0xffffffffu, in);
        if (cnt == 0 && mask) firstIdx = base + (__ffs(mask) - 1);
        int rank = __popc(mask & ((1u << lane) - 1u));
        int slot = cnt + rank;
        if (in && slot < NSAMP) out[slot] = j;
        cnt += __popc(mask);
    }
    for (int t = cnt + lane; t < NSAMP; t += 32) out[t] = firstIdx;  // pad with first
}

// ---------------- gather + concat -> x0 (row-major M x 67) ----------------
__global__ __launch_bounds__(128) void gather_kernel(const float* __restrict__ xyz,
                                                     const float* __restrict__ points,
                                                     const float* __restrict__ new_xyz,
                                                     const int* __restrict__ gidx,
                                                     float* __restrict__ x0)
{
    const int g   = blockIdx.x;        // (b,s) group 0..16383
    const int b   = g >> 10;
    const int tid = threadIdx.x;

    __shared__ int   sIdx[NSAMP];
    __shared__ float sc[3];
    if (tid < NSAMP) sIdx[tid] = gidx[(size_t)g*NSAMP + tid];
    if (tid < 3)     sc[tid]   = new_xyz[(size_t)g*3 + tid];
    __syncthreads();

    float* dst = x0 + (size_t)g * NSAMP * CH0;
    const float* P = points + (size_t)b * NPTS * DFEAT;
    const float* X = xyz    + (size_t)b * NPTS * 3;

    for (int e = tid; e < NSAMP * CH0; e += 128) {
        int k = e / CH0;
        int c = e - k * CH0;
        int j = sIdx[k];
        float v = (c < 3) ? (X[3*j + c] - sc[c]) : P[(size_t)j * DFEAT + (c - 3)];
        dst[e] = v;
    }
}

// ---------------- GEMM (+fused BN/ReLU on A-load, +bias, +deterministic col partials) ----------------
template<int BM, int BN, int BK, int TM, int TN, bool TRANSFORM, bool KGUARD>
__global__ __launch_bounds__((BM/TM)*(BN/TN)) void gemm_bn_kernel(
    const float* __restrict__ A, int lda, int K,
    const float* __restrict__ W, int N,
    const float* __restrict__ bias,
    const float* __restrict__ scale, const float* __restrict__ shift,
    float* __restrict__ Y,
    float* __restrict__ partSum, float* __restrict__ partSq)
{
    constexpr int NT    = (BM/TM)*(BN/TN);   // 256
    constexpr int SA    = BK*(BM+4);
    constexpr int SB    = BK*BN;
    constexpr int RROWS = BM/TM;
    constexpr int SRED  = RROWS*BN;
    constexpr int SSZ   = (SA+SB) > 2*SRED ? (SA+SB) : 2*SRED;
    __shared__ float smem[SSZ];
    float (*As)[BM+4] = (float(*)[BM+4])smem;
    float (*Bs)[BN]   = (float(*)[BN])(smem + SA);

    const int tid = threadIdx.x;
    const int nb  = blockIdx.x, mb = blockIdx.y;
    const int m0  = mb * BM,    n0 = nb * BN;

    const int tCol = tid % (BN/TN);
    const int tRow = tid / (BN/TN);

    float acc[TM][TN];
#pragma unroll
    for (int i = 0; i < TM; i++)
#pragma unroll
        for (int j = 0; j < TN; j++) acc[i][j] = 0.f;

    const int aCol  = tid % BK;
    const int aRow0 = tid / BK;
    constexpr int AROWS = NT / BK;    // 32 rows per pass
    const int bCol0 = tid % 32;
    const int bRow  = tid / 32;       // == BK rows when NT/32 == BK

    const int KT = KGUARD ? (K + BK - 1) / BK : K / BK;
    for (int kt = 0; kt < KT; kt++) {
        const int k0 = kt * BK;
        // load A tile (transposed into shared), apply BN+ReLU of previous layer if requested
#pragma unroll
        for (int r = 0; r < BM/AROWS; r++) {
            int m  = aRow0 + r*AROWS;
            int kk = k0 + aCol;
            float v = 0.f;
            if (!KGUARD || kk < K) {
                v = A[(size_t)(m0 + m) * lda + kk];
                if (TRANSFORM) v = fmaxf(v * scale[kk] + shift[kk], 0.f);
            }
            As[aCol][m] = v;
        }
        // load B tile
#pragma unroll
        for (int c = 0; c < BN/32; c++) {
            int n  = bCol0 + c*32;
            int kk = k0 + bRow;
            float v = 0.f;
            if (!KGUARD || kk < K) v = W[(size_t)kk * N + n0 + n];
            Bs[bRow][n] = v;
        }
        __syncthreads();
#pragma unroll
        for (int kk = 0; kk < BK; kk++) {
            float ra[TM], rb[TN];
#pragma unroll
            for (int i = 0; i < TM; i++) ra[i] = As[kk][tRow*TM + i];
#pragma unroll
            for (int j = 0; j < TN; j++) rb[j] = Bs[kk][tCol*TN + j];
#pragma unroll
            for (int i = 0; i < TM; i++)
#pragma unroll
                for (int j = 0; j < TN; j++) acc[i][j] += ra[i] * rb[j];
        }
        __syncthreads();
    }

    // epilogue: bias, write Y, per-thread column partials
    float csum[TN], csq[TN];
#pragma unroll
    for (int j = 0; j < TN; j++) { csum[j] = 0.f; csq[j] = 0.f; }
#pragma unroll
    for (int i = 0; i < TM; i++) {
        const int m = m0 + tRow*TM + i;
        float* yrow = Y + (size_t)m * N + n0 + tCol*TN;
#pragma unroll
        for (int j = 0; j < TN; j++) {
            float v = acc[i][j] + bias[n0 + tCol*TN + j];
            yrow[j] = v;
            csum[j] += v;
            csq[j]  += v * v;
        }
    }
    // deterministic tree reduce over the RROWS thread-rows per column
    __syncthreads();
    float* rs = smem;
    float* rq = smem + SRED;
#pragma unroll
    for (int j = 0; j < TN; j++) {
        rs[tRow*BN + tCol*TN + j] = csum[j];
        rq[tRow*BN + tCol*TN + j] = csq[j];
    }
    __syncthreads();
#pragma unroll
    for (int s = RROWS/2; s > 0; s >>= 1) {
        if (tRow < s) {
#pragma unroll
            for (int j = 0; j < TN; j++) {
                int idx = tRow*BN + tCol*TN + j;
                rs[idx] += rs[idx + s*BN];
                rq[idx] += rq[idx + s*BN];
            }
        }
        __syncthreads();
    }
    if (tRow == 0) {
#pragma unroll
        for (int j = 0; j < TN; j++) {
            int n = tCol*TN + j;
            partSum[(size_t)mb * N + n0 + n] = rs[n];
            partSq [(size_t)mb * N + n0 + n] = rq[n];
        }
    }
}

// ---------------- fold partials into per-channel scale/shift (deterministic) ----------------
__global__ __launch_bounds__(256) void stats_kernel(const float* __restrict__ partSum,
                                                    const float* __restrict__ partSq,
                                                    int N,
                                                    const float* __restrict__ g,
                                                    const float* __restrict__ bt,
                                                    float* __restrict__ scale,
                                                    float* __restrict__ shift)
{
    const int c = blockIdx.x;
    const int tid = threadIdx.x;
    __shared__ float ss[256], sq[256];
    float a = 0.f, b2 = 0.f;
    for (int mb = tid; mb < MBLK; mb += 256) {
        a  += partSum[(size_t)mb * N + c];
        b2 += partSq [(size_t)mb * N + c];
    }
    ss[tid] = a; sq[tid] = b2;
    __syncthreads();
    for (int s = 128; s > 0; s >>= 1) {
        if (tid < s) { ss[tid] += ss[tid+s]; sq[tid] += sq[tid+s]; }
        __syncthreads();
    }
    if (tid == 0) {
        const float invM = 1.0f / (float)MTOT;
        float mean = ss[0] * invM;
        float var  = sq[0] * invM - mean * mean;
        float sc   = g[c] / sqrtf(var + BNEPS);
        scale[c] = sc;
        shift[c] = bt[c] - mean * sc;
    }
}

// ---------------- final BN+ReLU + max over k=32 ----------------
__global__ __launch_bounds__(256) void maxpool_kernel(const float* __restrict__ Y3,
                                                      const float* __restrict__ scale,
                                                      const float* __restrict__ shift,
                                                      float* __restrict__ out)
{
    const int g = blockIdx.x;       // (b,s)
    const int c = threadIdx.x;      // channel 0..255
    const float* src = Y3 + (size_t)g * NSAMP * CH3 + c;
    const float sc = scale[c], sh = shift[c];
    float m = 0.0f;                 // relu outputs are >= 0
#pragma unroll 8
    for (int k = 0; k < NSAMP; k++) {
        float v = fmaxf(src[(size_t)k * CH3] * sc + sh, 0.f);
        m = fmaxf(m, v);
    }
    out[(size_t)g * CH3 + c] = m;
}

// ---------------- launch ----------------
extern "C" void kernel_launch(void* const* d_in, const int* in_sizes, int n_in,
                              void* d_out, int out_size)
{
    const float* xyz    = (const float*)d_in[0];
    const float* points = (const float*)d_in[1];
    const float* w0  = (const float*)d_in[2];
    const float* b0  = (const float*)d_in[3];
    const float* g0  = (const float*)d_in[4];
    const float* bt0 = (const float*)d_in[5];
    const float* w1  = (const float*)d_in[6];
    const float* b1  = (const float*)d_in[7];
    const float* g1  = (const float*)d_in[8];
    const float* bt1 = (const float*)d_in[9];
    const float* w2  = (const float*)d_in[10];
    const float* b2  = (const float*)d_in[11];
    const float* g2  = (const float*)d_in[12];
    const float* bt2 = (const float*)d_in[13];

    float* out        = (float*)d_out;
    float* new_xyz    = out;                       // B*SPTS*3
    float* new_points = out + (size_t)BATCH*SPTS*3;

    float *x0, *y1, *y2, *y3, *part, *scale, *shift;
    int*   gidx;
    cudaGetSymbolAddress((void**)&x0,    g_x0);
    cudaGetSymbolAddress((void**)&y1,    g_y1);
    cudaGetSymbolAddress((void**)&y2,    g_y2);
    cudaGetSymbolAddress((void**)&y3,    g_y3);
    cudaGetSymbolAddress((void**)&part,  g_part);
    cudaGetSymbolAddress((void**)&scale, g_scale);
    cudaGetSymbolAddress((void**)&shift, g_shift);
    cudaGetSymbolAddress((void**)&gidx,  g_gidx);

    float* partSum = part;
    float* partSq  = part + (size_t)MBLK * CH3;

    fps_kernel<<<BATCH, 256>>>(xyz, new_xyz);
    ballquery_kernel<<<BATCH*SPTS/8, 256>>>(xyz, new_xyz, gidx);
    gather_kernel<<<BATCH*SPTS, 128>>>(xyz, points, new_xyz, gidx, x0);

    // layer 1: 67 -> 64 (raw A)
    gemm_bn_kernel<128, 64, 8, 8, 4, false, true>
        <<<dim3(CH1/64, MBLK), 256>>>(x0, CH0, CH0, w0, CH1, b0, nullptr, nullptr,
                                      y1, partSum, partSq);
    stats_kernel<<<CH1, 256>>>(partSum, partSq, CH1, g0, bt0, scale, shift);

    // layer 2: 64 -> 128 (BN+ReLU of layer1 fused on A-load)
    gemm_bn_kernel<128, 128, 8, 8, 8, true, false>
        <<<dim3(CH2/128, MBLK), 256>>>(y1, CH1, CH1, w1, CH2, b1, scale, shift,
                                       y2, partSum, partSq);
    stats_kernel<<<CH2, 256>>>(partSum, partSq, CH2, g1, bt1, scale, shift);

    // layer 3: 128 -> 256
    gemm_bn_kernel<128, 128, 8, 8, 8, true, false>
        <<<dim3(CH3/128, MBLK), 256>>>(y2, CH2, CH2, w2, CH3, b2, scale, shift,
                                       y3, partSum, partSq);
    stats_kernel<<<CH3, 256>>>(partSum, partSq, CH3, g2, bt2, scale, shift);

    maxpool_kernel<<<BATCH*SPTS, 256>>>(y3, scale, shift, new_points);
}

// round 2
// speedup vs baseline: 1.0004x; 1.0004x over previous
#include <cuda_runtime.h>
#include <math.h>

// ---------------- problem constants ----------------
#define BATCH 16
#define NPTS  4096
#define DFEAT 64
#define SPTS  1024
#define NSAMP 32
#define CH0   67          // 3 + DFEAT
#define CH1   64
#define CH2   128
#define CH3   256
#define MTOT  (BATCH*SPTS*NSAMP)   // 524288 rows through the MLP
#define MBLK  (MTOT/128)           // 4096 M-blocks (BM=128)
#define RAD2  0.04f                // f32(0.04) — matches jnp weak-typed compare
#define BNEPS 1e-5f

// ---------------- device scratch (static: no allocs allowed) ----------------
__device__ float g_x0[(size_t)MTOT*CH0];   // gathered+concat features
__device__ float g_y1[(size_t)MTOT*CH1];   // raw (pre-BN) layer outputs
__device__ float g_y2[(size_t)MTOT*CH2];
__device__ float g_y3[(size_t)MTOT*CH3];
__device__ int   g_gidx[BATCH*SPTS*NSAMP];
__device__ float g_part[2*(size_t)MBLK*CH3];  // per-Mblock column partials (sum, sumsq)
__device__ float g_scale[CH3];
__device__ float g_shift[CH3];

// ---------------- FPS: one block per batch, dist in registers ----------------
__global__ __launch_bounds__(256) void fps_kernel(const float* __restrict__ xyz,
                                                  float* __restrict__ new_xyz)
{
    const int b   = blockIdx.x;
    const int tid = threadIdx.x;
    const float* X = xyz + (size_t)b * NPTS * 3;

    float px[16], py[16], pz[16], dist[16];
#pragma unroll
    for (int t = 0; t < 16; t++) {
        int j = tid + t * 256;
        px[t] = X[3*j]; py[t] = X[3*j+1]; pz[t] = X[3*j+2];
        dist[t] = 1e10f;
    }

    __shared__ float s_val[8];
    __shared__ int   s_idx[8];
    __shared__ int   s_far;

    const int lane = tid & 31, wid = tid >> 5;
    int far = 0;

    for (int i = 0; i < SPTS; i++) {
        float cx = X[3*far], cy = X[3*far+1], cz = X[3*far+2];
        if (tid == 0) {
            float* o = new_xyz + ((size_t)b * SPTS + i) * 3;
            o[0] = cx; o[1] = cy; o[2] = cz;
        }
        if (i == SPTS - 1) break;

        float bv = -1.0f; int bi = 0;
#pragma unroll
        for (int t = 0; t < 16; t++) {
            float dx = px[t]-cx, dy = py[t]-cy, dz = pz[t]-cz;
            float d  = dx*dx + dy*dy + dz*dz;
            float nd = fminf(dist[t], d);
            dist[t]  = nd;
            if (nd > bv) { bv = nd; bi = tid + t*256; }  // ascending idx in t -> first-max kept
        }
        // warp argmax (lowest index on ties)
#pragma unroll
        for (int off = 16; off > 0; off >>= 1) {
            float ov = __shfl_down_sync(0xffffffffu, bv, off);
            int   oi = __shfl_down_sync(0xffffffffu, bi, off);
            if (ov > bv || (ov == bv && oi < bi)) { bv = ov; bi = oi; }
        }
        if (lane == 0) { s_val[wid] = bv; s_idx[wid] = bi; }
        __syncthreads();
        if (tid == 0) {
            bv = s_val[0]; bi = s_idx[0];
#pragma unroll
            for (int w = 1; w < 8; w++)
                if (s_val[w] > bv || (s_val[w] == bv && s_idx[w] < bi)) { bv = s_val[w]; bi = s_idx[w]; }
            s_far = bi;
        }
        __syncthreads();
        far = s_far;
    }
}

// ---------------- ball query: warp per centroid, ballot-ranked collection ----------------
__global__ __launch_bounds__(256) void ballquery_kernel(const float* __restrict__ xyz,
                                                        const float* __restrict__ new_xyz,
                                                        int* __restrict__ gidx)
{
    const int w    = blockIdx.x * 8 + (threadIdx.x >> 5);   // centroid id, 0..B*SPTS-1
    const int lane = threadIdx.x & 31;
    const int b    = w >> 10;
    const float* X = xyz + (size_t)b * NPTS * 3;

    const float cx = new_xyz[(size_t)w*3+0];
    const float cy = new_xyz[(size_t)w*3+1];
    const float cz = new_xyz[(size_t)w*3+2];
    const float ss = cx*cx + cy*cy + cz*cz;

    int cnt = 0, firstIdx = 0;
    int* out = gidx + (size_t)w * NSAMP;

    for (int base = 0; base < NPTS && cnt < NSAMP; base += 32) {
        const int j = base + lane;
        const float x = X[3*j], y = X[3*j+1], z = X[3*j+2];
        const float pp  = x*x + y*y + z*z;
        const float dot = x*cx + y*cy + z*cz;
        const float d   = (-2.0f*dot + ss) + pp;   // mirrors reference add order
        const bool  in  = !(d > RAD2);
        unsigned mask = __ballot_sync(0xffffffffu, in);
        if (cnt == 0 && mask) firstIdx = base + (__ffs(mask) - 1);
        int rank = __popc(mask & ((1u << lane) - 1u));
        int slot = cnt + rank;
        if (in && slot < NSAMP) out[slot] = j;
        cnt += __popc(mask);
    }
    for (int t = cnt + lane; t < NSAMP; t += 32) out[t] = firstIdx;  // pad with first
}

// ---------------- gather + concat -> x0 (row-major M x 67) ----------------
__global__ __launch_bounds__(128) void gather_kernel(const float* __restrict__ xyz,
                                                     const float* __restrict__ points,
                                                     const float* __restrict__ new_xyz,
                                                     const int* __restrict__ gidx,
                                                     float* __restrict__ x0)
{
    const int g   = blockIdx.x;        // (b,s) group 0..16383
    const int b   = g >> 10;
    const int tid = threadIdx.x;

    __shared__ int   sIdx[NSAMP];
    __shared__ float sc[3];
    if (tid < NSAMP) sIdx[tid] = gidx[(size_t)g*NSAMP + tid];
    if (tid < 3)     sc[tid]   = new_xyz[(size_t)g*3 + tid];
    __syncthreads();

    float* dst = x0 + (size_t)g * NSAMP * CH0;
    const float* P = points + (size_t)b * NPTS * DFEAT;
    const float* X = xyz    + (size_t)b * NPTS * 3;

    for (int e = tid; e < NSAMP * CH0; e += 128) {
        int k = e / CH0;
        int c = e - k * CH0;
        int j = sIdx[k];
        float v = (c < 3) ? (X[3*j + c] - sc[c]) : P[(size_t)j * DFEAT + (c - 3)];
        dst[e] = v;
    }
}

// ---------------- GEMM (+fused BN/ReLU on A-load, +bias, +deterministic col partials) ----------------
template<int BM, int BN, int BK, int TM, int TN, bool TRANSFORM, bool KGUARD>
__global__ __launch_bounds__((BM/TM)*(BN/TN)) void gemm_bn_kernel(
    const float* __restrict__ A, int lda, int K,
    const float* __restrict__ W, int N,
    const float* __restrict__ bias,
    const float* __restrict__ scale, const float* __restrict__ shift,
    float* __restrict__ Y,
    float* __restrict__ partSum, float* __restrict__ partSq)
{
    constexpr int NT    = (BM/TM)*(BN/TN);   // 256
    constexpr int SA    = BK*(BM+4);
    constexpr int SB    = BK*BN;
    constexpr int RROWS = BM/TM;
    constexpr int SRED  = RROWS*BN;
    constexpr int SSZ   = (SA+SB) > 2*SRED ? (SA+SB) : 2*SRED;
    __shared__ float smem[SSZ];
    float (*As)[BM+4] = (float(*)[BM+4])smem;
    float (*Bs)[BN]   = (float(*)[BN])(smem + SA);

    const int tid = threadIdx.x;
    const int nb  = blockIdx.x, mb = blockIdx.y;
    const int m0  = mb * BM,    n0 = nb * BN;

    const int tCol = tid % (BN/TN);
    const int tRow = tid / (BN/TN);

    float acc[TM][TN];
#pragma unroll
    for (int i = 0; i < TM; i++)
#pragma unroll
        for (int j = 0; j < TN; j++) acc[i][j] = 0.f;

    const int aCol  = tid % BK;
    const int aRow0 = tid / BK;
    constexpr int AROWS = NT / BK;    // 32 rows per pass
    const int bCol0 = tid % 32;
    const int bRow  = tid / 32;       // == BK rows when NT/32 == BK

    const int KT = KGUARD ? (K + BK - 1) / BK : K / BK;
    for (int kt = 0; kt < KT; kt++) {
        const int k0 = kt * BK;
        // load A tile (transposed into shared), apply BN+ReLU of previous layer if requested
#pragma unroll
        for (int r = 0; r < BM/AROWS; r++) {
            int m  = aRow0 + r*AROWS;
            int kk = k0 + aCol;
            float v = 0.f;
            if (!KGUARD || kk < K) {
                v = A[(size_t)(m0 + m) * lda + kk];
                if (TRANSFORM) v = fmaxf(v * scale[kk] + shift[kk], 0.f);
            }
            As[aCol][m] = v;
        }
        // load B tile
#pragma unroll
        for (int c = 0; c < BN/32; c++) {
            int n  = bCol0 + c*32;
            int kk = k0 + bRow;
            float v = 0.f;
            if (!KGUARD || kk < K) v = W[(size_t)kk * N + n0 + n];
            Bs[bRow][n] = v;
        }
        __syncthreads();
#pragma unroll
        for (int kk = 0; kk < BK; kk++) {
            float ra[TM], rb[TN];
#pragma unroll
            for (int i = 0; i < TM; i++) ra[i] = As[kk][tRow*TM + i];
#pragma unroll
            for (int j = 0; j < TN; j++) rb[j] = Bs[kk][tCol*TN + j];
#pragma unroll
            for (int i = 0; i < TM; i++)
#pragma unroll
                for (int j = 0; j < TN; j++) acc[i][j] += ra[i] * rb[j];
        }
        __syncthreads();
    }

    // epilogue: bias, write Y, per-thread column partials
    float csum[TN], csq[TN];
#pragma unroll
    for (int j = 0; j < TN; j++) { csum[j] = 0.f; csq[j] = 0.f; }
#pragma unroll
    for (int i = 0; i < TM; i++) {
        const int m = m0 + tRow*TM + i;
        float* yrow = Y + (size_t)m * N + n0 + tCol*TN;
#pragma unroll
        for (int j = 0; j < TN; j++) {
            float v = acc[i][j] + bias[n0 + tCol*TN + j];
            yrow[j] = v;
            csum[j] += v;
            csq[j]  += v * v;
        }
    }
    // deterministic tree reduce over the RROWS thread-rows per column
    __syncthreads();
    float* rs = smem;
    float* rq = smem + SRED;
#pragma unroll
    for (int j = 0; j < TN; j++) {
        rs[tRow*BN + tCol*TN + j] = csum[j];
        rq[tRow*BN + tCol*TN + j] = csq[j];
    }
    __syncthreads();
#pragma unroll
    for (int s = RROWS/2; s > 0; s >>= 1) {
        if (tRow < s) {
#pragma unroll
            for (int j = 0; j < TN; j++) {
                int idx = tRow*BN + tCol*TN + j;
                rs[idx] += rs[idx + s*BN];
                rq[idx] += rq[idx + s*BN];
            }
        }
        __syncthreads();
    }
    if (tRow == 0) {
#pragma unroll
        for (int j = 0; j < TN; j++) {
            int n = tCol*TN + j;
            partSum[(size_t)mb * N + n0 + n] = rs[n];
            partSq [(size_t)mb * N + n0 + n] = rq[n];
        }
    }
}

// ---------------- fold partials into per-channel scale/shift (deterministic) ----------------
__global__ __launch_bounds__(256) void stats_kernel(const float* __restrict__ partSum,
                                                    const float* __restrict__ partSq,
                                                    int N,
                                                    const float* __restrict__ g,
                                                    const float* __restrict__ bt,
                                                    float* __restrict__ scale,
                                                    float* __restrict__ shift)
{
    const int c = blockIdx.x;
    const int tid = threadIdx.x;
    __shared__ float ss[256], sq[256];
    float a = 0.f, b2 = 0.f;
    for (int mb = tid; mb < MBLK; mb += 256) {
        a  += partSum[(size_t)mb * N + c];
        b2 += partSq [(size_t)mb * N + c];
    }
    ss[tid] = a; sq[tid] = b2;
    __syncthreads();
    for (int s = 128; s > 0; s >>= 1) {
        if (tid < s) { ss[tid] += ss[tid+s]; sq[tid] += sq[tid+s]; }
        __syncthreads();
    }
    if (tid == 0) {
        const float invM = 1.0f / (float)MTOT;
        float mean = ss[0] * invM;
        float var  = sq[0] * invM - mean * mean;
        float sc   = g[c] / sqrtf(var + BNEPS);
        scale[c] = sc;
        shift[c] = bt[c] - mean * sc;
    }
}

// ---------------- final BN+ReLU + max over k=32 ----------------
__global__ __launch_bounds__(256) void maxpool_kernel(const float* __restrict__ Y3,
                                                      const float* __restrict__ scale,
                                                      const float* __restrict__ shift,
                                                      float* __restrict__ out)
{
    const int g = blockIdx.x;       // (b,s)
    const int c = threadIdx.x;      // channel 0..255
    const float* src = Y3 + (size_t)g * NSAMP * CH3 + c;
    const float sc = scale[c], sh = shift[c];
    float m = 0.0f;                 // relu outputs are >= 0
#pragma unroll 8
    for (int k = 0; k < NSAMP; k++) {
        float v = fmaxf(src[(size_t)k * CH3] * sc + sh, 0.f);
        m = fmaxf(m, v);
    }
    out[(size_t)g * CH3 + c] = m;
}

// ---------------- launch ----------------
extern "C" void kernel_launch(void* const* d_in, const int* in_sizes, int n_in,
                              void* d_out, int out_size)
{
    const float* xyz    = (const float*)d_in[0];
    const float* points = (const float*)d_in[1];
    const float* w0  = (const float*)d_in[2];
    const float* b0  = (const float*)d_in[3];
    const float* g0  = (const float*)d_in[4];
    const float* bt0 = (const float*)d_in[5];
    const float* w1  = (const float*)d_in[6];
    const float* b1  = (const float*)d_in[7];
    const float* g1  = (const float*)d_in[8];
    const float* bt1 = (const float*)d_in[9];
    const float* w2  = (const float*)d_in[10];
    const float* b2  = (const float*)d_in[11];
    const float* g2  = (const float*)d_in[12];
    const float* bt2 = (const float*)d_in[13];

    float* out        = (float*)d_out;
    float* new_xyz    = out;                       // B*SPTS*3
    float* new_points = out + (size_t)BATCH*SPTS*3;

    float *x0, *y1, *y2, *y3, *part, *scale, *shift;
    int*   gidx;
    cudaGetSymbolAddress((void**)&x0,    g_x0);
    cudaGetSymbolAddress((void**)&y1,    g_y1);
    cudaGetSymbolAddress((void**)&y2,    g_y2);
    cudaGetSymbolAddress((void**)&y3,    g_y3);
    cudaGetSymbolAddress((void**)&part,  g_part);
    cudaGetSymbolAddress((void**)&scale, g_scale);
    cudaGetSymbolAddress((void**)&shift, g_shift);
    cudaGetSymbolAddress((void**)&gidx,  g_gidx);

    float* partSum = part;
    float* partSq  = part + (size_t)MBLK * CH3;

    fps_kernel<<<BATCH, 256>>>(xyz, new_xyz);
    ballquery_kernel<<<BATCH*SPTS/8, 256>>>(xyz, new_xyz, gidx);
    gather_kernel<<<BATCH*SPTS, 128>>>(xyz, points, new_xyz, gidx, x0);

    // layer 1: 67 -> 64 (raw A)
    gemm_bn_kernel<128, 64, 8, 8, 4, false, true>
        <<<dim3(CH1/64, MBLK), 256>>>(x0, CH0, CH0, w0, CH1, b0, nullptr, nullptr,
                                      y1, partSum, partSq);
    stats_kernel<<<CH1, 256>>>(partSum, partSq, CH1, g0, bt0, scale, shift);

    // layer 2: 64 -> 128 (BN+ReLU of layer1 fused on A-load)
    gemm_bn_kernel<128, 128, 8, 8, 8, true, false>
        <<<dim3(CH2/128, MBLK), 256>>>(y1, CH1, CH1, w1, CH2, b1, scale, shift,
                                       y2, partSum, partSq);
    stats_kernel<<<CH2, 256>>>(partSum, partSq, CH2, g1, bt1, scale, shift);

    // layer 3: 128 -> 256
    gemm_bn_kernel<128, 128, 8, 8, 8, true, false>
        <<<dim3(CH3/128, MBLK), 256>>>(y2, CH2, CH2, w2, CH3, b2, scale, shift,
                                       y3, partSum, partSq);
    stats_kernel<<<CH3, 256>>>(partSum, partSq, CH3, g2, bt2, scale, shift);

    maxpool_kernel<<<BATCH*SPTS, 256>>>(y3, scale, shift, new_points);
}

// round 4
// speedup vs baseline: 1.3212x; 1.3206x over previous
#include <cuda_runtime.h>
#include <cuda_bf16.h>
#include <math.h>
#include <stdint.h>

// ---------------- problem constants ----------------
#define BATCH 16
#define NPTS  4096
#define DFEAT 64
#define SPTS  1024
#define NSAMP 32
#define CH0   67
#define CH1   64
#define CH2   128
#define CH3   256
#define MTOT  (BATCH*SPTS*NSAMP)   // 524288
#define MBLK  (MTOT/128)           // 4096
#define RAD2  0.04f
#define BNEPS 1e-5f

// ---------------- device scratch ----------------
__device__ float g_x0[(size_t)MTOT*CH0];
__device__ float g_y1[(size_t)MTOT*CH1];
__device__ float g_y2[(size_t)MTOT*CH2];
__device__ int   g_gidx[BATCH*SPTS*NSAMP];
__device__ float g_part[2*(size_t)MBLK*CH3];
__device__ float g_scale[CH3];
__device__ float g_shift[CH3];
__device__ float g_gmax[(size_t)BATCH*SPTS*CH3];
__device__ float g_gmin[(size_t)BATCH*SPTS*CH3];
// weights prepped k-major [KPAD][N], bf16 hi/lo
__device__ __nv_bfloat16 g_bh0[80*64],   g_bl0[80*64];
__device__ __nv_bfloat16 g_bh1[64*128],  g_bl1[64*128];
__device__ __nv_bfloat16 g_bh2[128*256], g_bl2[128*256];

// ---------------- helpers ----------------
__device__ __forceinline__ uint32_t smem_u32(const void* p) {
    uint32_t a;
    asm("{ .reg .u64 t; cvta.to.shared.u64 t, %1; cvt.u32.u64 %0, t; }" : "=r"(a) : "l"(p));
    return a;
}
__device__ __forceinline__ void ldsm4(uint32_t* r, uint32_t a) {
    asm volatile("ldmatrix.sync.aligned.m8n8.x4.shared.b16 {%0,%1,%2,%3}, [%4];"
                 : "=r"(r[0]), "=r"(r[1]), "=r"(r[2]), "=r"(r[3]) : "r"(a));
}
__device__ __forceinline__ void ldsm4t(uint32_t* r, uint32_t a) {
    asm volatile("ldmatrix.sync.aligned.m8n8.x4.trans.shared.b16 {%0,%1,%2,%3}, [%4];"
                 : "=r"(r[0]), "=r"(r[1]), "=r"(r[2]), "=r"(r[3]) : "r"(a));
}
__device__ __forceinline__ void mma_bf16(float* c, const uint32_t* a, uint32_t b0, uint32_t b1) {
    asm volatile(
        "mma.sync.aligned.m16n8k16.row.col.f32.bf16.bf16.f32 "
        "{%0,%1,%2,%3}, {%4,%5,%6,%7}, {%8,%9}, {%0,%1,%2,%3};"
        : "+f"(c[0]), "+f"(c[1]), "+f"(c[2]), "+f"(c[3])
        : "r"(a[0]), "r"(a[1]), "r"(a[2]), "r"(a[3]), "r"(b0), "r"(b1));
}

// ---------------- FPS ----------------
__global__ __launch_bounds__(256) void fps_kernel(const float* __restrict__ xyz,
                                                  float* __restrict__ new_xyz)
{
    const int b = blockIdx.x, tid = threadIdx.x;
    const float* X = xyz + (size_t)b * NPTS * 3;

    float px[16], py[16], pz[16], dist[16];
#pragma unroll
    for (int t = 0; t < 16; t++) {
        int j = tid + t * 256;
        px[t] = X[3*j]; py[t] = X[3*j+1]; pz[t] = X[3*j+2];
        dist[t] = 1e10f;
    }
    __shared__ unsigned s_val[2][8], s_low[2][8];
    const int lane = tid & 31, wid = tid >> 5;
    int far = 0;

    for (int i = 0; i < SPTS; i++) {
        float cx = X[3*far], cy = X[3*far+1], cz = X[3*far+2];
        if (tid == 0) {
            float* o = new_xyz + ((size_t)b * SPTS + i) * 3;
            o[0] = cx; o[1] = cy; o[2] = cz;
        }
        if (i == SPTS - 1) break;

        unsigned long long best = 0ull;
#pragma unroll
        for (int t = 0; t < 16; t++) {
            float dx = px[t]-cx, dy = py[t]-cy, dz = pz[t]-cz;
            float d  = dx*dx + dy*dy + dz*dz;
            float nd = fminf(dist[t], d);
            dist[t]  = nd;
            unsigned long long key =
                ((unsigned long long)__float_as_uint(nd) << 32) |
                (unsigned)(0xFFFFu - (tid + t*256));
            best = key > best ? key : best;
        }
        unsigned vb = (unsigned)(best >> 32);
        unsigned m  = __reduce_max_sync(0xffffffffu, vb);
        unsigned lw = __reduce_max_sync(0xffffffffu, (vb == m) ? (unsigned)best : 0u);
        const int buf = i & 1;
        if (lane == 0) { s_val[buf][wid] = m; s_low[buf][wid] = lw; }
        __syncthreads();
        unsigned bm = s_val[buf][0], bl = s_low[buf][0];
#pragma unroll
        for (int w = 1; w < 8; w++) {
            unsigned wm = s_val[buf][w], wl = s_low[buf][w];
            if (wm > bm || (wm == bm && wl > bl)) { bm = wm; bl = wl; }
        }
        far = (int)(0xFFFFu - bl);
    }
}

// ---------------- ball query ----------------
__global__ __launch_bounds__(256) void ballquery_kernel(const float* __restrict__ xyz,
                                                        const float* __restrict__ new_xyz,
                                                        int* __restrict__ gidx)
{
    const int w    = blockIdx.x * 8 + (threadIdx.x >> 5);
    const int lane = threadIdx.x & 31;
    const int b    = w >> 10;
    const float* X = xyz + (size_t)b * NPTS * 3;

    const float cx = new_xyz[(size_t)w*3+0];
    const float cy = new_xyz[(size_t)w*3+1];
    const float cz = new_xyz[(size_t)w*3+2];
    const float ss = cx*cx + cy*cy + cz*cz;

    int cnt = 0, firstIdx = 0;
    int* out = gidx + (size_t)w * NSAMP;

    for (int base = 0; base < NPTS && cnt < NSAMP; base += 32) {
        const int j = base + lane;
        const float x = X[3*j], y = X[3*j+1], z = X[3*j+2];
        const float pp  = x*x + y*y + z*z;
        const float dot = x*cx + y*cy + z*cz;
        const float d   = (-2.0f*dot + ss) + pp;
        const bool  in  = !(d > RAD2);
        unsigned mask = __ballot_sync(0xffffffffu, in);
        if (cnt == 0 && mask) firstIdx = base + (__ffs(mask) - 1);
        int rank = __popc(mask & ((1u << lane) - 1u));
        int slot = cnt + rank;
        if (in && slot < NSAMP) out[slot] = j;
        cnt += __popc(mask);
    }
    for (int t = cnt + lane; t < NSAMP; t += 32) out[t] = firstIdx;
}

// ---------------- gather + concat ----------------
__global__ __launch_bounds__(128) void gather_kernel(const float* __restrict__ xyz,
                                                     const float* __restrict__ points,
                                                     const float* __restrict__ new_xyz,
                                                     const int* __restrict__ gidx,
                                                     float* __restrict__ x0)
{
    const int g = blockIdx.x, b = g >> 10, tid = threadIdx.x;
    __shared__ int   sIdx[NSAMP];
    __shared__ float sc[3];
    if (tid < NSAMP) sIdx[tid] = gidx[(size_t)g*NSAMP + tid];
    if (tid < 3)     sc[tid]   = new_xyz[(size_t)g*3 + tid];
    __syncthreads();

    float* dst = x0 + (size_t)g * NSAMP * CH0;
    const float* P = points + (size_t)b * NPTS * DFEAT;
    const float* X = xyz    + (size_t)b * NPTS * 3;
    for (int e = tid; e < NSAMP * CH0; e += 128) {
        int k = e / CH0, c = e - k * CH0;
        int j = sIdx[k];
        dst[e] = (c < 3) ? (X[3*j + c] - sc[c]) : P[(size_t)j * DFEAT + (c - 3)];
    }
}

// ---------------- weight prep: W[K][N] f32 -> [KPAD][N] bf16 hi/lo (k-major) ----------------
__global__ __launch_bounds__(256) void prep_kernel(const float* __restrict__ W, int K, int N,
                                                   int KPAD,
                                                   __nv_bfloat16* __restrict__ bh,
                                                   __nv_bfloat16* __restrict__ bl)
{
    int i = blockIdx.x * 256 + threadIdx.x;
    if (i >= N * KPAD) return;
    int k = i / N, n = i - k * N;
    float v = (k < K) ? W[(size_t)k * N + n] : 0.f;
    __nv_bfloat16 h = __float2bfloat16(v);
    bh[i] = h;
    bl[i] = __float2bfloat16(v - __bfloat162float(h));
}

// ---------------- HMMA GEMM (bf16 split-3, full-K staged) ----------------
// BM=128 rows, BN columns. 8 warps = 4(m) x 2(n). Warp tile: 32 x BN/2.
template<int BN, int NTOT, int KPAD, int KORIG, bool TRANSFORM, bool STORE_Y, bool FUSED_MAX>
__global__ void __launch_bounds__(256, 1) gemm_mma(
    const float* __restrict__ A,
    const __nv_bfloat16* __restrict__ BH, const __nv_bfloat16* __restrict__ BL,
    const float* __restrict__ bias,
    const float* __restrict__ scale, const float* __restrict__ shift,
    float* __restrict__ Y,
    float* __restrict__ partSum, float* __restrict__ partSq,
    float* __restrict__ gmax, float* __restrict__ gmin)
{
    extern __shared__ __align__(16) char dyn[];
    constexpr int LDA = KPAD + 8;   // bf16 units
    constexpr int LDB = BN + 8;
    __nv_bfloat16* aHi = (__nv_bfloat16*)dyn;
    __nv_bfloat16* aLo = aHi + 128 * LDA;
    __nv_bfloat16* bHi = aLo + 128 * LDA;
    __nv_bfloat16* bLo = bHi + KPAD * LDB;

    const int tid = threadIdx.x;
    const int nb = blockIdx.x, mb = blockIdx.y;
    const int m0 = mb * 128, n0 = nb * BN;

    // ---- stage A (f32 -> bf16 hi/lo, optional BN+ReLU transform) ----
    constexpr int AIT = 128 * (KPAD / 2);
    for (int idx = tid; idx < AIT; idx += 256) {
        const int r  = idx / (KPAD / 2);
        const int p  = idx - r * (KPAD / 2);
        const int kk = 2 * p;
        float v0 = 0.f, v1 = 0.f;
        if ((KORIG % 2 == 0) && kk + 2 <= KORIG) {
            float2 f = *(const float2*)(A + (size_t)(m0 + r) * KORIG + kk);
            v0 = f.x; v1 = f.y;
        } else {
            if (kk < KORIG)     v0 = A[(size_t)(m0 + r) * KORIG + kk];
            if (kk + 1 < KORIG) v1 = A[(size_t)(m0 + r) * KORIG + kk + 1];
        }
        if (TRANSFORM) {
            if (kk < KORIG)     v0 = fmaxf(fmaf(v0, __ldg(scale + kk),     __ldg(shift + kk)),     0.f);
            if (kk + 1 < KORIG) v1 = fmaxf(fmaf(v1, __ldg(scale + kk + 1), __ldg(shift + kk + 1)), 0.f);
        }
        __nv_bfloat16 h0 = __float2bfloat16(v0), h1 = __float2bfloat16(v1);
        __nv_bfloat16 l0 = __float2bfloat16(v0 - __bfloat162float(h0));
        __nv_bfloat16 l1 = __float2bfloat16(v1 - __bfloat162float(h1));
        *(__nv_bfloat162*)(aHi + r * LDA + kk) = __halves2bfloat162(h0, h1);
        *(__nv_bfloat162*)(aLo + r * LDA + kk) = __halves2bfloat162(l0, l1);
    }
    // ---- stage B (prepped bf16, straight copy) ----
    constexpr int BIT = KPAD * (BN / 2);
    for (int idx = tid; idx < BIT; idx += 256) {
        const int k = idx / (BN / 2);
        const int n = 2 * (idx - k * (BN / 2));
        *(uint32_t*)(bHi + k * LDB + n) = *(const uint32_t*)(BH + (size_t)k * NTOT + n0 + n);
        *(uint32_t*)(bLo + k * LDB + n) = *(const uint32_t*)(BL + (size_t)k * NTOT + n0 + n);
    }
    __syncthreads();

    // ---- compute ----
    const int wid = tid >> 5, lane = tid & 31;
    const int wm = wid >> 1, wn = wid & 1;
    const int mW = wm * 32, nW = wn * (BN / 2);
    constexpr int NT = BN / 16;           // n8-tiles per warp
    constexpr int KSTEPS = KPAD / 16;

    float acc[2][NT][4];
#pragma unroll
    for (int i = 0; i < 2; i++)
#pragma unroll
        for (int j = 0; j < NT; j++)
#pragma unroll
            for (int q = 0; q < 4; q++) acc[i][j][q] = 0.f;

    const uint32_t aHiU = smem_u32(aHi) + (uint32_t)(mW + (lane & 15)) * (LDA * 2) + (lane >> 4) * 16;
    const uint32_t aLoU = smem_u32(aLo) + (uint32_t)(mW + (lane & 15)) * (LDA * 2) + (lane >> 4) * 16;
    const uint32_t bHiU = smem_u32(bHi) + (uint32_t)(lane & 15) * (LDB * 2) + (uint32_t)nW * 2 + (lane >> 4) * 16;
    const uint32_t bLoU = smem_u32(bLo) + (uint32_t)(lane & 15) * (LDB * 2) + (uint32_t)nW * 2 + (lane >> 4) * 16;

#pragma unroll
    for (int ks = 0; ks < KSTEPS; ks++) {
        uint32_t ah[2][4], al[2][4];
        ldsm4(ah[0], aHiU + ks * 32);
        ldsm4(ah[1], aHiU + 16 * LDA * 2 + ks * 32);
        ldsm4(al[0], aLoU + ks * 32);
        ldsm4(al[1], aLoU + 16 * LDA * 2 + ks * 32);
#pragma unroll
        for (int ng = 0; ng < NT / 2; ng++) {
            uint32_t bh[4], bl[4];
            const uint32_t bo = (uint32_t)ks * (16 * LDB * 2) + ng * 32;
            ldsm4t(bh, bHiU + bo);
            ldsm4t(bl, bLoU + bo);
#pragma unroll
            for (int mt = 0; mt < 2; mt++) {
                mma_bf16(acc[mt][ng*2+0], ah[mt], bh[0], bh[1]);
                mma_bf16(acc[mt][ng*2+0], ah[mt], bl[0], bl[1]);
                mma_bf16(acc[mt][ng*2+0], al[mt], bh[0], bh[1]);
                mma_bf16(acc[mt][ng*2+1], ah[mt], bh[2], bh[3]);
                mma_bf16(acc[mt][ng*2+1], ah[mt], bl[2], bl[3]);
                mma_bf16(acc[mt][ng*2+1], al[mt], bh[2], bh[3]);
            }
        }
    }
    __syncthreads();   // done with staged tiles; reuse smem for reductions

    // ---- epilogue: bias, optional Y store, BN partials, optional group min/max ----
    float* sSum = (float*)dyn;            // [4][BN]
    float* sSq  = sSum + 4 * BN;          // [4][BN]

    const int r0 = lane >> 2;             // 0..7
#pragma unroll
    for (int nt = 0; nt < NT; nt++) {
        const int colLocal = nW + nt * 8 + (lane & 3) * 2;
        const float b0 = __ldg(bias + n0 + colLocal);
        const float b1 = __ldg(bias + n0 + colLocal + 1);
        float v0 = acc[0][nt][0] + b0, v1 = acc[0][nt][1] + b1;
        float v2 = acc[0][nt][2] + b0, v3 = acc[0][nt][3] + b1;
        float v4 = acc[1][nt][0] + b0, v5 = acc[1][nt][1] + b1;
        float v6 = acc[1][nt][2] + b0, v7 = acc[1][nt][3] + b1;
        if (STORE_Y) {
            const size_t base = (size_t)(m0 + mW + r0) * NTOT + n0 + colLocal;
            *(float2*)(Y + base)             = make_float2(v0, v1);
            *(float2*)(Y + base +  8*NTOT)   = make_float2(v2, v3);
            *(float2*)(Y + base + 16*NTOT)   = make_float2(v4, v5);
            *(float2*)(Y + base + 24*NTOT)   = make_float2(v6, v7);
        }
        float s0 = v0+v2+v4+v6,              s1 = v1+v3+v5+v7;
        float q0 = v0*v0+v2*v2+v4*v4+v6*v6,  q1 = v1*v1+v3*v3+v5*v5+v7*v7;
        float mx0 = fmaxf(fmaxf(v0,v2), fmaxf(v4,v6)), mx1 = fmaxf(fmaxf(v1,v3), fmaxf(v5,v7));
        float mn0 = fminf(fminf(v0,v2), fminf(v4,v6)), mn1 = fminf(fminf(v1,v3), fminf(v5,v7));
#pragma unroll
        for (int d = 4; d < 32; d <<= 1) {
            s0 += __shfl_xor_sync(0xffffffffu, s0, d);
            s1 += __shfl_xor_sync(0xffffffffu, s1, d);
            q0 += __shfl_xor_sync(0xffffffffu, q0, d);
            q1 += __shfl_xor_sync(0xffffffffu, q1, d);
            mx0 = fmaxf(mx0, __shfl_xor_sync(0xffffffffu, mx0, d));
            mx1 = fmaxf(mx1, __shfl_xor_sync(0xffffffffu, mx1, d));
            mn0 = fminf(mn0, __shfl_xor_sync(0xffffffffu, mn0, d));
            mn1 = fminf(mn1, __shfl_xor_sync(0xffffffffu, mn1, d));
        }
        if (lane < 4) {
            sSum[wm*BN + colLocal] = s0;  sSum[wm*BN + colLocal + 1] = s1;
            sSq [wm*BN + colLocal] = q0;  sSq [wm*BN + colLocal + 1] = q1;
            if (FUSED_MAX) {
                const size_t grp = (size_t)(mb * 4 + wm) * CH3 + n0 + colLocal;
                gmax[grp]     = mx0;  gmax[grp + 1] = mx1;
                gmin[grp]     = mn0;  gmin[grp + 1] = mn1;
            }
        }
    }
    __syncthreads();
    for (int n = tid; n < BN; n += 256) {
        float s = sSum[n] + sSum[BN + n] + sSum[2*BN + n] + sSum[3*BN + n];
        float q = sSq [n] + sSq [BN + n] + sSq [2*BN + n] + sSq [3*BN + n];
        partSum[(size_t)mb * NTOT + n0 + n] = s;
        partSq [(size_t)mb * NTOT + n0 + n] = q;
    }
}

// ---------------- fold partials -> scale/shift ----------------
__global__ __launch_bounds__(256) void stats_kernel(const float* __restrict__ partSum,
                                                    const float* __restrict__ partSq,
                                                    int N,
                                                    const float* __restrict__ g,
                                                    const float* __restrict__ bt,
                                                    float* __restrict__ scale,
                                                    float* __restrict__ shift)
{
    const int c = blockIdx.x, tid = threadIdx.x;
    __shared__ float ss[256], sq[256];
    float a = 0.f, b2 = 0.f;
    for (int mb = tid; mb < MBLK; mb += 256) {
        a  += partSum[(size_t)mb * N + c];
        b2 += partSq [(size_t)mb * N + c];
    }
    ss[tid] = a; sq[tid] = b2;
    __syncthreads();
    for (int s = 128; s > 0; s >>= 1) {
        if (tid < s) { ss[tid] += ss[tid+s]; sq[tid] += sq[tid+s]; }
        __syncthreads();
    }
    if (tid == 0) {
        const float invM = 1.0f / (float)MTOT;
        float mean = ss[0] * invM;
        float var  = sq[0] * invM - mean * mean;
        float sc   = g[c] / sqrtf(var + BNEPS);
        scale[c] = sc;
        shift[c] = bt[c] - mean * sc;
    }
}

// ---------------- final: pick max/min by sign(scale), affine+relu ----------------
__global__ __launch_bounds__(256) void finalpool_kernel(const float* __restrict__ gmax,
                                                        const float* __restrict__ gmin,
                                                        const float* __restrict__ scale,
                                                        const float* __restrict__ shift,
                                                        float* __restrict__ out)
{
    const int g = blockIdx.x, c = threadIdx.x;
    const float sc = scale[c], sh = shift[c];
    const float v = (sc >= 0.f) ? gmax[(size_t)g * CH3 + c] : gmin[(size_t)g * CH3 + c];
    out[(size_t)g * CH3 + c] = fmaxf(fmaf(v, sc, sh), 0.f);
}

// ---------------- launch ----------------
extern "C" void kernel_launch(void* const* d_in, const int* in_sizes, int n_in,
                              void* d_out, int out_size)
{
    const float* xyz    = (const float*)d_in[0];
    const float* points = (const float*)d_in[1];
    const float* w0  = (const float*)d_in[2];
    const float* b0  = (const float*)d_in[3];
    const float* g0  = (const float*)d_in[4];
    const float* bt0 = (const float*)d_in[5];
    const float* w1  = (const float*)d_in[6];
    const float* b1  = (const float*)d_in[7];
    const float* g1  = (const float*)d_in[8];
    const float* bt1 = (const float*)d_in[9];
    const float* w2  = (const float*)d_in[10];
    const float* b2  = (const float*)d_in[11];
    const float* g2  = (const float*)d_in[12];
    const float* bt2 = (const float*)d_in[13];

    float* out        = (float*)d_out;
    float* new_xyz    = out;
    float* new_points = out + (size_t)BATCH*SPTS*3;

    float *x0, *y1, *y2, *part, *scale, *shift, *gmax, *gmin;
    int* gidx;
    __nv_bfloat16 *bh0, *bl0, *bh1, *bl1, *bh2, *bl2;
    cudaGetSymbolAddress((void**)&x0,    g_x0);
    cudaGetSymbolAddress((void**)&y1,    g_y1);
    cudaGetSymbolAddress((void**)&y2,    g_y2);
    cudaGetSymbolAddress((void**)&part,  g_part);
    cudaGetSymbolAddress((void**)&scale, g_scale);
    cudaGetSymbolAddress((void**)&shift, g_shift);
    cudaGetSymbolAddress((void**)&gidx,  g_gidx);
    cudaGetSymbolAddress((void**)&gmax,  g_gmax);
    cudaGetSymbolAddress((void**)&gmin,  g_gmin);
    cudaGetSymbolAddress((void**)&bh0,   g_bh0);
    cudaGetSymbolAddress((void**)&bl0,   g_bl0);
    cudaGetSymbolAddress((void**)&bh1,   g_bh1);
    cudaGetSymbolAddress((void**)&bl1,   g_bl1);
    cudaGetSymbolAddress((void**)&bh2,   g_bh2);
    cudaGetSymbolAddress((void**)&bl2,   g_bl2);

    float* partSum = part;
    float* partSq  = part + (size_t)MBLK * CH3;

    // smem bytes: 2*(2*128*LDA + 2*KPAD*LDB)
    constexpr int SM1 = (2*128*(80+8)  + 2*80 *(64+8))  * 2;  //  68,096
    constexpr int SM2 = (2*128*(64+8)  + 2*64 *(128+8)) * 2;  //  71,680
    constexpr int SM3 = (2*128*(128+8) + 2*128*(128+8)) * 2;  // 139,264

    static bool attrDone = false;
    if (!attrDone) {
        cudaFuncSetAttribute(gemm_mma<64, 64, 80, 67, false, true, false>,
                             cudaFuncAttributeMaxDynamicSharedMemorySize, SM1);
        cudaFuncSetAttribute(gemm_mma<128, 128, 64, 64, true, true, false>,
                             cudaFuncAttributeMaxDynamicSharedMemorySize, SM2);
        cudaFuncSetAttribute(gemm_mma<128, 256, 128, 128, true, false, true>,
                             cudaFuncAttributeMaxDynamicSharedMemorySize, SM3);
        attrDone = true;
    }

    prep_kernel<<<(80*64 + 255)/256, 256>>>(w0, CH0, CH1, 80, bh0, bl0);
    prep_kernel<<<(64*128 + 255)/256, 256>>>(w1, CH1, CH2, 64, bh1, bl1);
    prep_kernel<<<(128*256 + 255)/256, 256>>>(w2, CH2, CH3, 128, bh2, bl2);

    fps_kernel<<<BATCH, 256>>>(xyz, new_xyz);
    ballquery_kernel<<<BATCH*SPTS/8, 256>>>(xyz, new_xyz, gidx);
    gather_kernel<<<BATCH*SPTS, 128>>>(xyz, points, new_xyz, gidx, x0);

    // layer 1: 67 -> 64
    gemm_mma<64, 64, 80, 67, false, true, false><<<dim3(1, MBLK), 256, SM1>>>(
        x0, bh0, bl0, b0, nullptr, nullptr, y1, partSum, partSq, nullptr, nullptr);
    stats_kernel<<<CH1, 256>>>(partSum, partSq, CH1, g0, bt0, scale, shift);

    // layer 2: 64 -> 128
    gemm_mma<128, 128, 64, 64, true, true, false><<<dim3(1, MBLK), 256, SM2>>>(
        y1, bh1, bl1, b1, scale, shift, y2, partSum, partSq, nullptr, nullptr);
    stats_kernel<<<CH2, 256>>>(partSum, partSq, CH2, g1, bt1, scale, shift);

    // layer 3: 128 -> 256 (no Y store; fused per-group min/max)
    gemm_mma<128, 256, 128, 128, true, false, true><<<dim3(2, MBLK), 256, SM3>>>(
        y2, bh2, bl2, b2, scale, shift, nullptr, partSum, partSq, gmax, gmin);
    stats_kernel<<<CH3, 256>>>(partSum, partSq, CH3, g2, bt2, scale, shift);

    finalpool_kernel<<<BATCH*SPTS, 256>>>(gmax, gmin, scale, shift, new_points);
}

// round 5
// speedup vs baseline: 1.4690x; 1.1119x over previous
#include <cuda_runtime.h>
#include <cuda_bf16.h>
#include <math.h>
#include <stdint.h>

// ---------------- problem constants ----------------
#define BATCH 16
#define NPTS  4096
#define DFEAT 64
#define SPTS  1024
#define NSAMP 32
#define CH0   67
#define CH1   64
#define CH2   128
#define CH3   256
#define MTOT  (BATCH*SPTS*NSAMP)   // 524288
#define MBLK  (MTOT/128)           // 4096
#define RAD2  0.04f
#define BNEPS 1e-5f

// ---------------- device scratch ----------------
__device__ float g_x0[(size_t)MTOT*CH0];
__device__ float g_y1[(size_t)MTOT*CH1];
__device__ float g_y2[(size_t)MTOT*CH2];
__device__ int   g_gidx[BATCH*SPTS*NSAMP];
__device__ float g_part[2*(size_t)MBLK*CH3];
__device__ float g_scale[CH3];
__device__ float g_shift[CH3];
__device__ float g_gmax[(size_t)BATCH*SPTS*CH3];
__device__ float g_gmin[(size_t)BATCH*SPTS*CH3];
// weights prepped k-major [KPAD][N], bf16 hi/lo
__device__ __nv_bfloat16 g_bh0[80*64],   g_bl0[80*64];
__device__ __nv_bfloat16 g_bh1[64*128],  g_bl1[64*128];
__device__ __nv_bfloat16 g_bh2[128*256], g_bl2[128*256];

// ---------------- helpers ----------------
__device__ __forceinline__ uint32_t smem_u32(const void* p) {
    uint32_t a;
    asm("{ .reg .u64 t; cvta.to.shared.u64 t, %1; cvt.u32.u64 %0, t; }" : "=r"(a) : "l"(p));
    return a;
}
__device__ __forceinline__ void ldsm4(uint32_t* r, uint32_t a) {
    asm volatile("ldmatrix.sync.aligned.m8n8.x4.shared.b16 {%0,%1,%2,%3}, [%4];"
                 : "=r"(r[0]), "=r"(r[1]), "=r"(r[2]), "=r"(r[3]) : "r"(a));
}
__device__ __forceinline__ void ldsm4t(uint32_t* r, uint32_t a) {
    asm volatile("ldmatrix.sync.aligned.m8n8.x4.trans.shared.b16 {%0,%1,%2,%3}, [%4];"
                 : "=r"(r[0]), "=r"(r[1]), "=r"(r[2]), "=r"(r[3]) : "r"(a));
}
__device__ __forceinline__ void mma_bf16(float* c, const uint32_t* a, uint32_t b0, uint32_t b1) {
    asm volatile(
        "mma.sync.aligned.m16n8k16.row.col.f32.bf16.bf16.f32 "
        "{%0,%1,%2,%3}, {%4,%5,%6,%7}, {%8,%9}, {%0,%1,%2,%3};"
        : "+f"(c[0]), "+f"(c[1]), "+f"(c[2]), "+f"(c[3])
        : "r"(a[0]), "r"(a[1]), "r"(a[2]), "r"(a[3]), "r"(b0), "r"(b1));
}

// ---------------- FPS v3: smem point cache + tree reductions ----------------
__global__ __launch_bounds__(256) void fps_kernel(const float* __restrict__ xyz,
                                                  float* __restrict__ new_xyz)
{
    __shared__ float sx[NPTS], sy[NPTS], sz[NPTS];
    __shared__ unsigned long long s_key[2][8];
    const int b = blockIdx.x, tid = threadIdx.x;
    const int lane = tid & 31, wid = tid >> 5;
    const float* X = xyz + (size_t)b * NPTS * 3;

    float px[16], py[16], pz[16], dist[16];
#pragma unroll
    for (int t = 0; t < 16; t++) {
        int j = tid + t * 256;
        float x = X[3*j], y = X[3*j+1], z = X[3*j+2];
        px[t] = x; py[t] = y; pz[t] = z;
        sx[j] = x; sy[j] = y; sz[j] = z;
        dist[t] = 1e10f;
    }
    __syncthreads();

    int far = 0;
    for (int i = 0; i < SPTS; i++) {
        const float cx = sx[far], cy = sy[far], cz = sz[far];
        if (tid == 0) {
            float* o = new_xyz + ((size_t)b * SPTS + i) * 3;
            o[0] = cx; o[1] = cy; o[2] = cz;
        }
        if (i == SPTS - 1) break;

        unsigned long long kk[16];
#pragma unroll
        for (int t = 0; t < 16; t++) {
            float dx = px[t]-cx, dy = py[t]-cy, dz = pz[t]-cz;
            float d  = dx*dx + dy*dy + dz*dz;       // same contraction as validated R4
            float nd = fminf(dist[t], d);
            dist[t]  = nd;
            kk[t] = ((unsigned long long)__float_as_uint(nd) << 32)
                  | (unsigned)(0xFFFFu - (unsigned)(tid + (t << 8)));
        }
#pragma unroll
        for (int s = 8; s > 0; s >>= 1)
#pragma unroll
            for (int t = 0; t < s; t++) kk[t] = kk[t] > kk[t+s] ? kk[t] : kk[t+s];

        const unsigned vb = (unsigned)(kk[0] >> 32);
        const unsigned m  = __reduce_max_sync(0xffffffffu, vb);
        const unsigned lw = __reduce_max_sync(0xffffffffu, (vb == m) ? (unsigned)kk[0] : 0u);
        const int buf = i & 1;
        if (lane == 0) s_key[buf][wid] = ((unsigned long long)m << 32) | lw;
        __syncthreads();
        unsigned long long q[8];
#pragma unroll
        for (int w = 0; w < 8; w++) q[w] = s_key[buf][w];
#pragma unroll
        for (int s = 4; s > 0; s >>= 1)
#pragma unroll
            for (int w = 0; w < s; w++) q[w] = q[w] > q[w+s] ? q[w] : q[w+s];
        far = 0xFFFF - (int)(q[0] & 0xFFFFull);
    }
}

// ---------------- ball query ----------------
__global__ __launch_bounds__(256) void ballquery_kernel(const float* __restrict__ xyz,
                                                        const float* __restrict__ new_xyz,
                                                        int* __restrict__ gidx)
{
    const int w    = blockIdx.x * 8 + (threadIdx.x >> 5);
    const int lane = threadIdx.x & 31;
    const int b    = w >> 10;
    const float* X = xyz + (size_t)b * NPTS * 3;

    const float cx = new_xyz[(size_t)w*3+0];
    const float cy = new_xyz[(size_t)w*3+1];
    const float cz = new_xyz[(size_t)w*3+2];
    const float ss = cx*cx + cy*cy + cz*cz;

    int cnt = 0, firstIdx = 0;
    int* out = gidx + (size_t)w * NSAMP;

    for (int base = 0; base < NPTS && cnt < NSAMP; base += 32) {
        const int j = base + lane;
        const float x = X[3*j], y = X[3*j+1], z = X[3*j+2];
        const float pp  = x*x + y*y + z*z;
        const float dot = x*cx + y*cy + z*cz;
        const float d   = (-2.0f*dot + ss) + pp;
        const bool  in  = !(d > RAD2);
        unsigned mask = __ballot_sync(0xffffffffu, in);
        if (cnt == 0 && mask) firstIdx = base + (__ffs(mask) - 1);
        int rank = __popc(mask & ((1u << lane) - 1u));
        int slot = cnt + rank;
        if (in && slot < NSAMP) out[slot] = j;
        cnt += __popc(mask);
    }
    for (int t = cnt + lane; t < NSAMP; t += 32) out[t] = firstIdx;
}

// ---------------- gather + concat ----------------
__global__ __launch_bounds__(128) void gather_kernel(const float* __restrict__ xyz,
                                                     const float* __restrict__ points,
                                                     const float* __restrict__ new_xyz,
                                                     const int* __restrict__ gidx,
                                                     float* __restrict__ x0)
{
    const int g = blockIdx.x, b = g >> 10, tid = threadIdx.x;
    __shared__ int   sIdx[NSAMP];
    __shared__ float sc[3];
    if (tid < NSAMP) sIdx[tid] = gidx[(size_t)g*NSAMP + tid];
    if (tid < 3)     sc[tid]   = new_xyz[(size_t)g*3 + tid];
    __syncthreads();

    float* dst = x0 + (size_t)g * NSAMP * CH0;
    const float* P = points + (size_t)b * NPTS * DFEAT;
    const float* X = xyz    + (size_t)b * NPTS * 3;
    for (int e = tid; e < NSAMP * CH0; e += 128) {
        int k = e / CH0, c = e - k * CH0;
        int j = sIdx[k];
        dst[e] = (c < 3) ? (X[3*j + c] - sc[c]) : P[(size_t)j * DFEAT + (c - 3)];
    }
}

// ---------------- weight prep: W[K][N] f32 -> [KPAD][N] bf16 hi/lo (k-major) ----------------
__global__ __launch_bounds__(256) void prep_kernel(const float* __restrict__ W, int K, int N,
                                                   int KPAD,
                                                   __nv_bfloat16* __restrict__ bh,
                                                   __nv_bfloat16* __restrict__ bl)
{
    int i = blockIdx.x * 256 + threadIdx.x;
    if (i >= N * KPAD) return;
    int k = i / N, n = i - k * N;
    float v = (k < K) ? W[(size_t)k * N + n] : 0.f;
    __nv_bfloat16 h = __float2bfloat16(v);
    bh[i] = h;
    bl[i] = __float2bfloat16(v - __bfloat162float(h));
}

// ---------------- HMMA GEMM (bf16 split-3, full-K staged) ----------------
// BM=128 rows, BN columns. 8 warps = 4(m) x 2(n). Warp tile: 32 x BN/2.
template<int BN, int NTOT, int KPAD, int KORIG, bool TRANSFORM, bool STORE_Y, bool FUSED_MAX, int MINB>
__global__ void __launch_bounds__(256, MINB) gemm_mma(
    const float* __restrict__ A,
    const __nv_bfloat16* __restrict__ BH, const __nv_bfloat16* __restrict__ BL,
    const float* __restrict__ bias,
    const float* __restrict__ scale, const float* __restrict__ shift,
    float* __restrict__ Y,
    float* __restrict__ partSum, float* __restrict__ partSq,
    float* __restrict__ gmax, float* __restrict__ gmin)
{
    extern __shared__ __align__(16) char dyn[];
    constexpr int LDA = KPAD + 8;   // bf16 units
    constexpr int LDB = BN + 8;
    __nv_bfloat16* aHi = (__nv_bfloat16*)dyn;
    __nv_bfloat16* aLo = aHi + 128 * LDA;
    __nv_bfloat16* bHi = aLo + 128 * LDA;
    __nv_bfloat16* bLo = bHi + KPAD * LDB;

    const int tid = threadIdx.x;
    const int nb = blockIdx.x, mb = blockIdx.y;
    const int m0 = mb * 128, n0 = nb * BN;

    // ---- stage A (f32 -> bf16 hi/lo, optional BN+ReLU transform) ----
    constexpr int AIT = 128 * (KPAD / 2);
    for (int idx = tid; idx < AIT; idx += 256) {
        const int r  = idx / (KPAD / 2);
        const int p  = idx - r * (KPAD / 2);
        const int kk = 2 * p;
        float v0 = 0.f, v1 = 0.f;
        if ((KORIG % 2 == 0) && kk + 2 <= KORIG) {
            float2 f = *(const float2*)(A + (size_t)(m0 + r) * KORIG + kk);
            v0 = f.x; v1 = f.y;
        } else {
            if (kk < KORIG)     v0 = A[(size_t)(m0 + r) * KORIG + kk];
            if (kk + 1 < KORIG) v1 = A[(size_t)(m0 + r) * KORIG + kk + 1];
        }
        if (TRANSFORM) {
            if (kk < KORIG)     v0 = fmaxf(fmaf(v0, __ldg(scale + kk),     __ldg(shift + kk)),     0.f);
            if (kk + 1 < KORIG) v1 = fmaxf(fmaf(v1, __ldg(scale + kk + 1), __ldg(shift + kk + 1)), 0.f);
        }
        __nv_bfloat16 h0 = __float2bfloat16(v0), h1 = __float2bfloat16(v1);
        __nv_bfloat16 l0 = __float2bfloat16(v0 - __bfloat162float(h0));
        __nv_bfloat16 l1 = __float2bfloat16(v1 - __bfloat162float(h1));
        *(__nv_bfloat162*)(aHi + r * LDA + kk) = __halves2bfloat162(h0, h1);
        *(__nv_bfloat162*)(aLo + r * LDA + kk) = __halves2bfloat162(l0, l1);
    }
    // ---- stage B (prepped bf16, straight copy) ----
    constexpr int BIT = KPAD * (BN / 2);
    for (int idx = tid; idx < BIT; idx += 256) {
        const int k = idx / (BN / 2);
        const int n = 2 * (idx - k * (BN / 2));
        *(uint32_t*)(bHi + k * LDB + n) = *(const uint32_t*)(BH + (size_t)k * NTOT + n0 + n);
        *(uint32_t*)(bLo + k * LDB + n) = *(const uint32_t*)(BL + (size_t)k * NTOT + n0 + n);
    }
    __syncthreads();

    // ---- compute ----
    const int wid = tid >> 5, lane = tid & 31;
    const int wm = wid >> 1, wn = wid & 1;
    const int mW = wm * 32, nW = wn * (BN / 2);
    constexpr int NT = BN / 16;           // n8-tiles per warp
    constexpr int KSTEPS = KPAD / 16;

    float acc[2][NT][4];
#pragma unroll
    for (int i = 0; i < 2; i++)
#pragma unroll
        for (int j = 0; j < NT; j++)
#pragma unroll
            for (int q = 0; q < 4; q++) acc[i][j][q] = 0.f;

    const uint32_t aHiU = smem_u32(aHi) + (uint32_t)(mW + (lane & 15)) * (LDA * 2) + (lane >> 4) * 16;
    const uint32_t aLoU = smem_u32(aLo) + (uint32_t)(mW + (lane & 15)) * (LDA * 2) + (lane >> 4) * 16;
    const uint32_t bHiU = smem_u32(bHi) + (uint32_t)(lane & 15) * (LDB * 2) + (uint32_t)nW * 2 + (lane >> 4) * 16;
    const uint32_t bLoU = smem_u32(bLo) + (uint32_t)(lane & 15) * (LDB * 2) + (uint32_t)nW * 2 + (lane >> 4) * 16;

#pragma unroll
    for (int ks = 0; ks < KSTEPS; ks++) {
        uint32_t ah[2][4], al[2][4];
        ldsm4(ah[0], aHiU + ks * 32);
        ldsm4(ah[1], aHiU + 16 * LDA * 2 + ks * 32);
        ldsm4(al[0], aLoU + ks * 32);
        ldsm4(al[1], aLoU + 16 * LDA * 2 + ks * 32);
#pragma unroll
        for (int ng = 0; ng < NT / 2; ng++) {
            uint32_t bh[4], bl[4];
            const uint32_t bo = (uint32_t)ks * (16 * LDB * 2) + ng * 32;
            ldsm4t(bh, bHiU + bo);
            ldsm4t(bl, bLoU + bo);
#pragma unroll
            for (int mt = 0; mt < 2; mt++) {
                mma_bf16(acc[mt][ng*2+0], ah[mt], bh[0], bh[1]);
                mma_bf16(acc[mt][ng*2+0], ah[mt], bl[0], bl[1]);
                mma_bf16(acc[mt][ng*2+0], al[mt], bh[0], bh[1]);
                mma_bf16(acc[mt][ng*2+1], ah[mt], bh[2], bh[3]);
                mma_bf16(acc[mt][ng*2+1], ah[mt], bl[2], bl[3]);
                mma_bf16(acc[mt][ng*2+1], al[mt], bh[2], bh[3]);
            }
        }
    }
    __syncthreads();   // done with staged tiles; reuse smem for reductions

    // ---- epilogue: bias, optional Y store, BN partials, optional group min/max ----
    float* sSum = (float*)dyn;            // [4][BN]
    float* sSq  = sSum + 4 * BN;          // [4][BN]

    const int r0 = lane >> 2;             // 0..7
#pragma unroll
    for (int nt = 0; nt < NT; nt++) {
        const int colLocal = nW + nt * 8 + (lane & 3) * 2;
        const float b0 = __ldg(bias + n0 + colLocal);
        const float b1 = __ldg(bias + n0 + colLocal + 1);
        float v0 = acc[0][nt][0] + b0, v1 = acc[0][nt][1] + b1;
        float v2 = acc[0][nt][2] + b0, v3 = acc[0][nt][3] + b1;
        float v4 = acc[1][nt][0] + b0, v5 = acc[1][nt][1] + b1;
        float v6 = acc[1][nt][2] + b0, v7 = acc[1][nt][3] + b1;
        if (STORE_Y) {
            const size_t base = (size_t)(m0 + mW + r0) * NTOT + n0 + colLocal;
            *(float2*)(Y + base)             = make_float2(v0, v1);
            *(float2*)(Y + base +  8*NTOT)   = make_float2(v2, v3);
            *(float2*)(Y + base + 16*NTOT)   = make_float2(v4, v5);
            *(float2*)(Y + base + 24*NTOT)   = make_float2(v6, v7);
        }
        float s0 = v0+v2+v4+v6,              s1 = v1+v3+v5+v7;
        float q0 = v0*v0+v2*v2+v4*v4+v6*v6,  q1 = v1*v1+v3*v3+v5*v5+v7*v7;
        float mx0 = fmaxf(fmaxf(v0,v2), fmaxf(v4,v6)), mx1 = fmaxf(fmaxf(v1,v3), fmaxf(v5,v7));
        float mn0 = fminf(fminf(v0,v2), fminf(v4,v6)), mn1 = fminf(fminf(v1,v3), fminf(v5,v7));
#pragma unroll
        for (int d = 4; d < 32; d <<= 1) {
            s0 += __shfl_xor_sync(0xffffffffu, s0, d);
            s1 += __shfl_xor_sync(0xffffffffu, s1, d);
            q0 += __shfl_xor_sync(0xffffffffu, q0, d);
            q1 += __shfl_xor_sync(0xffffffffu, q1, d);
            mx0 = fmaxf(mx0, __shfl_xor_sync(0xffffffffu, mx0, d));
            mx1 = fmaxf(mx1, __shfl_xor_sync(0xffffffffu, mx1, d));
            mn0 = fminf(mn0, __shfl_xor_sync(0xffffffffu, mn0, d));
            mn1 = fminf(mn1, __shfl_xor_sync(0xffffffffu, mn1, d));
        }
        if (lane < 4) {
            sSum[wm*BN + colLocal] = s0;  sSum[wm*BN + colLocal + 1] = s1;
            sSq [wm*BN + colLocal] = q0;  sSq [wm*BN + colLocal + 1] = q1;
            if (FUSED_MAX) {
                const size_t grp = (size_t)(mb * 4 + wm) * CH3 + n0 + colLocal;
                gmax[grp]     = mx0;  gmax[grp + 1] = mx1;
                gmin[grp]     = mn0;  gmin[grp + 1] = mn1;
            }
        }
    }
    __syncthreads();
    for (int n = tid; n < BN; n += 256) {
        float s = sSum[n] + sSum[BN + n] + sSum[2*BN + n] + sSum[3*BN + n];
        float q = sSq [n] + sSq [BN + n] + sSq [2*BN + n] + sSq [3*BN + n];
        partSum[(size_t)mb * NTOT + n0 + n] = s;
        partSq [(size_t)mb * NTOT + n0 + n] = q;
    }
}

// ---------------- fold partials -> scale/shift ----------------
__global__ __launch_bounds__(256) void stats_kernel(const float* __restrict__ partSum,
                                                    const float* __restrict__ partSq,
                                                    int N,
                                                    const float* __restrict__ g,
                                                    const float* __restrict__ bt,
                                                    float* __restrict__ scale,
                                                    float* __restrict__ shift)
{
    const int c = blockIdx.x, tid = threadIdx.x;
    __shared__ float ss[256], sq[256];
    float a = 0.f, b2 = 0.f;
    for (int mb = tid; mb < MBLK; mb += 256) {
        a  += partSum[(size_t)mb * N + c];
        b2 += partSq [(size_t)mb * N + c];
    }
    ss[tid] = a; sq[tid] = b2;
    __syncthreads();
    for (int s = 128; s > 0; s >>= 1) {
        if (tid < s) { ss[tid] += ss[tid+s]; sq[tid] += sq[tid+s]; }
        __syncthreads();
    }
    if (tid == 0) {
        const float invM = 1.0f / (float)MTOT;
        float mean = ss[0] * invM;
        float var  = sq[0] * invM - mean * mean;
        float sc   = g[c] / sqrtf(var + BNEPS);
        scale[c] = sc;
        shift[c] = bt[c] - mean * sc;
    }
}

// ---------------- final: pick max/min by sign(scale), affine+relu ----------------
__global__ __launch_bounds__(256) void finalpool_kernel(const float* __restrict__ gmax,
                                                        const float* __restrict__ gmin,
                                                        const float* __restrict__ scale,
                                                        const float* __restrict__ shift,
                                                        float* __restrict__ out)
{
    const int g = blockIdx.x, c = threadIdx.x;
    const float sc = scale[c], sh = shift[c];
    const float v = (sc >= 0.f) ? gmax[(size_t)g * CH3 + c] : gmin[(size_t)g * CH3 + c];
    out[(size_t)g * CH3 + c] = fmaxf(fmaf(v, sc, sh), 0.f);
}

// ---------------- launch ----------------
extern "C" void kernel_launch(void* const* d_in, const int* in_sizes, int n_in,
                              void* d_out, int out_size)
{
    const float* xyz    = (const float*)d_in[0];
    const float* points = (const float*)d_in[1];
    const float* w0  = (const float*)d_in[2];
    const float* b0  = (const float*)d_in[3];
    const float* g0  = (const float*)d_in[4];
    const float* bt0 = (const float*)d_in[5];
    const float* w1  = (const float*)d_in[6];
    const float* b1  = (const float*)d_in[7];
    const float* g1  = (const float*)d_in[8];
    const float* bt1 = (const float*)d_in[9];
    const float* w2  = (const float*)d_in[10];
    const float* b2  = (const float*)d_in[11];
    const float* g2  = (const float*)d_in[12];
    const float* bt2 = (const float*)d_in[13];

    float* out        = (float*)d_out;
    float* new_xyz    = out;
    float* new_points = out + (size_t)BATCH*SPTS*3;

    float *x0, *y1, *y2, *part, *scale, *shift, *gmax, *gmin;
    int* gidx;
    __nv_bfloat16 *bh0, *bl0, *bh1, *bl1, *bh2, *bl2;
    cudaGetSymbolAddress((void**)&x0,    g_x0);
    cudaGetSymbolAddress((void**)&y1,    g_y1);
    cudaGetSymbolAddress((void**)&y2,    g_y2);
    cudaGetSymbolAddress((void**)&part,  g_part);
    cudaGetSymbolAddress((void**)&scale, g_scale);
    cudaGetSymbolAddress((void**)&shift, g_shift);
    cudaGetSymbolAddress((void**)&gidx,  g_gidx);
    cudaGetSymbolAddress((void**)&gmax,  g_gmax);
    cudaGetSymbolAddress((void**)&gmin,  g_gmin);
    cudaGetSymbolAddress((void**)&bh0,   g_bh0);
    cudaGetSymbolAddress((void**)&bl0,   g_bl0);
    cudaGetSymbolAddress((void**)&bh1,   g_bh1);
    cudaGetSymbolAddress((void**)&bl1,   g_bl1);
    cudaGetSymbolAddress((void**)&bh2,   g_bh2);
    cudaGetSymbolAddress((void**)&bl2,   g_bl2);

    float* partSum = part;
    float* partSq  = part + (size_t)MBLK * CH3;

    // smem bytes: 2*(2*128*LDA + 2*KPAD*LDB)
    constexpr int SM1 = (2*128*(80+8)  + 2*80 *(64+8))  * 2;  //  68,096
    constexpr int SM2 = (2*128*(64+8)  + 2*64 *(128+8)) * 2;  //  71,680
    constexpr int SM3 = (2*128*(128+8) + 2*128*(128+8)) * 2;  // 139,264

    static bool attrDone = false;
    if (!attrDone) {
        cudaFuncSetAttribute(gemm_mma<64, 64, 80, 67, false, true, false, 2>,
                             cudaFuncAttributeMaxDynamicSharedMemorySize, SM1);
        cudaFuncSetAttribute(gemm_mma<128, 128, 64, 64, true, true, false, 2>,
                             cudaFuncAttributeMaxDynamicSharedMemorySize, SM2);
        cudaFuncSetAttribute(gemm_mma<128, 256, 128, 128, true, false, true, 1>,
                             cudaFuncAttributeMaxDynamicSharedMemorySize, SM3);
        attrDone = true;
    }

    prep_kernel<<<(80*64 + 255)/256, 256>>>(w0, CH0, CH1, 80, bh0, bl0);
    prep_kernel<<<(64*128 + 255)/256, 256>>>(w1, CH1, CH2, 64, bh1, bl1);
    prep_kernel<<<(128*256 + 255)/256, 256>>>(w2, CH2, CH3, 128, bh2, bl2);

    fps_kernel<<<BATCH, 256>>>(xyz, new_xyz);
    ballquery_kernel<<<BATCH*SPTS/8, 256>>>(xyz, new_xyz, gidx);
    gather_kernel<<<BATCH*SPTS, 128>>>(xyz, points, new_xyz, gidx, x0);

    // layer 1: 67 -> 64
    gemm_mma<64, 64, 80, 67, false, true, false, 2><<<dim3(1, MBLK), 256, SM1>>>(
        x0, bh0, bl0, b0, nullptr, nullptr, y1, partSum, partSq, nullptr, nullptr);
    stats_kernel<<<CH1, 256>>>(partSum, partSq, CH1, g0, bt0, scale, shift);

    // layer 2: 64 -> 128
    gemm_mma<128, 128, 64, 64, true, true, false, 2><<<dim3(1, MBLK), 256, SM2>>>(
        y1, bh1, bl1, b1, scale, shift, y2, partSum, partSq, nullptr, nullptr);
    stats_kernel<<<CH2, 256>>>(partSum, partSq, CH2, g1, bt1, scale, shift);

    // layer 3: 128 -> 256 (no Y store; fused per-group min/max)
    gemm_mma<128, 256, 128, 128, true, false, true, 1><<<dim3(2, MBLK), 256, SM3>>>(
        y2, bh2, bl2, b2, scale, shift, nullptr, partSum, partSq, gmax, gmin);
    stats_kernel<<<CH3, 256>>>(partSum, partSq, CH3, g2, bt2, scale, shift);

    finalpool_kernel<<<BATCH*SPTS, 256>>>(gmax, gmin, scale, shift, new_points);
}

// round 6
// speedup vs baseline: 1.5252x; 1.0382x over previous
#include <cuda_runtime.h>
#include <cuda_bf16.h>
#include <math.h>
#include <stdint.h>

// ---------------- problem constants ----------------
#define BATCH 16
#define NPTS  4096
#define DFEAT 64
#define SPTS  1024
#define NSAMP 32
#define CH0   67
#define X0LD  80            // padded row stride for x0
#define CH1   64
#define CH2   128
#define CH3   256
#define MTOT  (BATCH*SPTS*NSAMP)   // 524288
#define MBLK  (MTOT/128)           // 4096
#define RAD2  0.04f
#define BNEPS 1e-5f

typedef unsigned long long ull;

// ---------------- device scratch ----------------
__device__ float g_x0[(size_t)MTOT*X0LD];
__device__ float g_y1[(size_t)MTOT*CH1];
__device__ float g_y2[(size_t)MTOT*CH2];
__device__ int   g_gidx[BATCH*SPTS*NSAMP];
__device__ float g_part[2*(size_t)MBLK*CH3];
__device__ float g_scale[CH3];
__device__ float g_shift[CH3];
__device__ float g_gmax[(size_t)BATCH*SPTS*CH3];
__device__ float g_gmin[(size_t)BATCH*SPTS*CH3];
// weights prepped k-major [KPAD][N], bf16 hi/lo
__device__ __nv_bfloat16 g_bh0[80*64],   g_bl0[80*64];
__device__ __nv_bfloat16 g_bh1[64*128],  g_bl1[64*128];
__device__ __nv_bfloat16 g_bh2[128*256], g_bl2[128*256];

// ---------------- helpers ----------------
__device__ __forceinline__ uint32_t smem_u32(const void* p) {
    uint32_t a;
    asm("{ .reg .u64 t; cvta.to.shared.u64 t, %1; cvt.u32.u64 %0, t; }" : "=r"(a) : "l"(p));
    return a;
}
__device__ __forceinline__ void ldsm4(uint32_t* r, uint32_t a) {
    asm volatile("ldmatrix.sync.aligned.m8n8.x4.shared.b16 {%0,%1,%2,%3}, [%4];"
                 : "=r"(r[0]), "=r"(r[1]), "=r"(r[2]), "=r"(r[3]) : "r"(a));
}
__device__ __forceinline__ void ldsm4t(uint32_t* r, uint32_t a) {
    asm volatile("ldmatrix.sync.aligned.m8n8.x4.trans.shared.b16 {%0,%1,%2,%3}, [%4];"
                 : "=r"(r[0]), "=r"(r[1]), "=r"(r[2]), "=r"(r[3]) : "r"(a));
}
__device__ __forceinline__ void mma_bf16(float* c, const uint32_t* a, uint32_t b0, uint32_t b1) {
    asm volatile(
        "mma.sync.aligned.m16n8k16.row.col.f32.bf16.bf16.f32 "
        "{%0,%1,%2,%3}, {%4,%5,%6,%7}, {%8,%9}, {%0,%1,%2,%3};"
        : "+f"(c[0]), "+f"(c[1]), "+f"(c[2]), "+f"(c[3])
        : "r"(a[0]), "r"(a[1]), "r"(a[2]), "r"(a[3]), "r"(b0), "r"(b1));
}

// ---------------- FPS v4: 512 threads, packed f32x2 distances, shfl-tree scan ----------------
__global__ __launch_bounds__(512) void fps_kernel(const float* __restrict__ xyz,
                                                  float* __restrict__ new_xyz)
{
    __shared__ float sx[NPTS], sy[NPTS], sz[NPTS];
    __shared__ ull s_key[2][16];
    const int b = blockIdx.x, tid = threadIdx.x;
    const int lane = tid & 31, wid = tid >> 5;
    const float* X = xyz + (size_t)b * NPTS * 3;

    ull pxp[4], pyp[4], pzp[4];
    float dist[8];
#pragma unroll
    for (int t = 0; t < 8; t++) dist[t] = 1e10f;
#pragma unroll
    for (int t = 0; t < 4; t++) {
        const int j0 = tid + (2*t) * 512, j1 = tid + (2*t+1) * 512;
        float x0 = X[3*j0], y0 = X[3*j0+1], z0 = X[3*j0+2];
        float x1 = X[3*j1], y1 = X[3*j1+1], z1 = X[3*j1+2];
        sx[j0] = x0; sy[j0] = y0; sz[j0] = z0;
        sx[j1] = x1; sy[j1] = y1; sz[j1] = z1;
        asm("mov.b64 %0, {%1,%2};" : "=l"(pxp[t]) : "f"(x0), "f"(x1));
        asm("mov.b64 %0, {%1,%2};" : "=l"(pyp[t]) : "f"(y0), "f"(y1));
        asm("mov.b64 %0, {%1,%2};" : "=l"(pzp[t]) : "f"(z0), "f"(z1));
    }
    __syncthreads();

    int far = 0;
    for (int i = 0; i < SPTS; i++) {
        const float cx = sx[far], cy = sy[far], cz = sz[far];
        if (tid == 0) {
            float* o = new_xyz + ((size_t)b * SPTS + i) * 3;
            o[0] = cx; o[1] = cy; o[2] = cz;
        }
        if (i == SPTS - 1) break;

        const float mx = -cx, my = -cy, mz = -cz;
        ull ncx, ncy, ncz;
        asm("mov.b64 %0, {%1,%1};" : "=l"(ncx) : "f"(mx));
        asm("mov.b64 %0, {%1,%1};" : "=l"(ncy) : "f"(my));
        asm("mov.b64 %0, {%1,%1};" : "=l"(ncz) : "f"(mz));

        ull key[8];
#pragma unroll
        for (int t = 0; t < 4; t++) {
            ull dx, dy, dz, dd;
            asm("add.rn.f32x2 %0, %1, %2;" : "=l"(dx) : "l"(pxp[t]), "l"(ncx));
            asm("add.rn.f32x2 %0, %1, %2;" : "=l"(dy) : "l"(pyp[t]), "l"(ncy));
            asm("add.rn.f32x2 %0, %1, %2;" : "=l"(dz) : "l"(pzp[t]), "l"(ncz));
            asm("mul.rn.f32x2 %0, %1, %2;" : "=l"(dd) : "l"(dx), "l"(dx));
            asm("fma.rn.f32x2 %0, %1, %2, %3;" : "=l"(dd) : "l"(dy), "l"(dy), "l"(dd));
            asm("fma.rn.f32x2 %0, %1, %2, %3;" : "=l"(dd) : "l"(dz), "l"(dz), "l"(dd));
            float d0, d1;
            asm("mov.b64 {%0,%1}, %2;" : "=f"(d0), "=f"(d1) : "l"(dd));
            const float nd0 = fminf(dist[2*t],   d0);
            const float nd1 = fminf(dist[2*t+1], d1);
            dist[2*t]   = nd0;
            dist[2*t+1] = nd1;
            key[2*t]   = ((ull)__float_as_uint(nd0) << 32) | (unsigned)(0xFFFFu - (unsigned)(tid + (2*t)*512));
            key[2*t+1] = ((ull)__float_as_uint(nd1) << 32) | (unsigned)(0xFFFFu - (unsigned)(tid + (2*t+1)*512));
        }
#pragma unroll
        for (int s = 4; s > 0; s >>= 1)
#pragma unroll
            for (int t = 0; t < s; t++) key[t] = key[t] > key[t+s] ? key[t] : key[t+s];

        const unsigned vb = (unsigned)(key[0] >> 32);
        const unsigned m  = __reduce_max_sync(0xffffffffu, vb);
        const unsigned lw = __reduce_max_sync(0xffffffffu, (vb == m) ? (unsigned)key[0] : 0u);
        const int buf = i & 1;
        if (lane == 0) s_key[buf][wid] = ((ull)m << 32) | lw;
        __syncthreads();

        ull q = s_key[buf][lane & 15];
#pragma unroll
        for (int d = 8; d > 0; d >>= 1) {
            ull o = __shfl_down_sync(0xffffffffu, q, d);
            if (o > q) q = o;
        }
        q = __shfl_sync(0xffffffffu, q, 0);
        far = 0xFFFF - (int)(q & 0xFFFFull);
    }
}

// ---------------- ball query ----------------
__global__ __launch_bounds__(256) void ballquery_kernel(const float* __restrict__ xyz,
                                                        const float* __restrict__ new_xyz,
                                                        int* __restrict__ gidx)
{
    const int w    = blockIdx.x * 8 + (threadIdx.x >> 5);
    const int lane = threadIdx.x & 31;
    const int b    = w >> 10;
    const float* X = xyz + (size_t)b * NPTS * 3;

    const float cx = new_xyz[(size_t)w*3+0];
    const float cy = new_xyz[(size_t)w*3+1];
    const float cz = new_xyz[(size_t)w*3+2];
    const float ss = cx*cx + cy*cy + cz*cz;

    int cnt = 0, firstIdx = 0;
    int* out = gidx + (size_t)w * NSAMP;

    for (int base = 0; base < NPTS && cnt < NSAMP; base += 32) {
        const int j = base + lane;
        const float x = X[3*j], y = X[3*j+1], z = X[3*j+2];
        const float pp  = x*x + y*y + z*z;
        const float dot = x*cx + y*cy + z*cz;
        const float d   = (-2.0f*dot + ss) + pp;
        const bool  in  = !(d > RAD2);
        unsigned mask = __ballot_sync(0xffffffffu, in);
        if (cnt == 0 && mask) firstIdx = base + (__ffs(mask) - 1);
        int rank = __popc(mask & ((1u << lane) - 1u));
        int slot = cnt + rank;
        if (in && slot < NSAMP) out[slot] = j;
        cnt += __popc(mask);
    }
    for (int t = cnt + lane; t < NSAMP; t += 32) out[t] = firstIdx;
}

// ---------------- gather + concat (row stride X0LD, pad cols stay 0) ----------------
__global__ __launch_bounds__(128) void gather_kernel(const float* __restrict__ xyz,
                                                     const float* __restrict__ points,
                                                     const float* __restrict__ new_xyz,
                                                     const int* __restrict__ gidx,
                                                     float* __restrict__ x0)
{
    const int g = blockIdx.x, b = g >> 10, tid = threadIdx.x;
    __shared__ int   sIdx[NSAMP];
    __shared__ float sc[3];
    if (tid < NSAMP) sIdx[tid] = gidx[(size_t)g*NSAMP + tid];
    if (tid < 3)     sc[tid]   = new_xyz[(size_t)g*3 + tid];
    __syncthreads();

    float* dst = x0 + (size_t)g * NSAMP * X0LD;
    const float* P = points + (size_t)b * NPTS * DFEAT;
    const float* X = xyz    + (size_t)b * NPTS * 3;
    for (int e = tid; e < NSAMP * CH0; e += 128) {
        int k = e / CH0, c = e - k * CH0;
        int j = sIdx[k];
        dst[k * X0LD + c] = (c < 3) ? (X[3*j + c] - sc[c]) : P[(size_t)j * DFEAT + (c - 3)];
    }
}

// ---------------- weight prep: W[K][N] f32 -> [KPAD][N] bf16 hi/lo (k-major) ----------------
__global__ __launch_bounds__(256) void prep_kernel(const float* __restrict__ W, int K, int N,
                                                   int KPAD,
                                                   __nv_bfloat16* __restrict__ bh,
                                                   __nv_bfloat16* __restrict__ bl)
{
    int i = blockIdx.x * 256 + threadIdx.x;
    if (i >= N * KPAD) return;
    int k = i / N, n = i - k * N;
    float v = (k < K) ? W[(size_t)k * N + n] : 0.f;
    __nv_bfloat16 h = __float2bfloat16(v);
    bh[i] = h;
    bl[i] = __float2bfloat16(v - __bfloat162float(h));
}

// ---------------- HMMA GEMM (bf16 split-3, full-K staged) ----------------
// BM=128 rows, BN columns. 8 warps = 4(m) x 2(n). Warp tile: 32 x BN/2.
template<int BN, int NTOT, int KPAD, int KORIG, bool TRANSFORM, bool STORE_Y, bool FUSED_MAX, int MINB>
__global__ void __launch_bounds__(256, MINB) gemm_mma(
    const float* __restrict__ A,
    const __nv_bfloat16* __restrict__ BH, const __nv_bfloat16* __restrict__ BL,
    const float* __restrict__ bias,
    const float* __restrict__ scale, const float* __restrict__ shift,
    float* __restrict__ Y,
    float* __restrict__ partSum, float* __restrict__ partSq,
    float* __restrict__ gmax, float* __restrict__ gmin)
{
    extern __shared__ __align__(16) char dyn[];
    constexpr int LDA = KPAD + 8;   // bf16 units
    constexpr int LDB = BN + 8;
    __nv_bfloat16* aHi = (__nv_bfloat16*)dyn;
    __nv_bfloat16* aLo = aHi + 128 * LDA;
    __nv_bfloat16* bHi = aLo + 128 * LDA;
    __nv_bfloat16* bLo = bHi + KPAD * LDB;

    const int tid = threadIdx.x;
    const int nb = blockIdx.x, mb = blockIdx.y;
    const int m0 = mb * 128, n0 = nb * BN;

    // ---- stage A (f32 -> bf16 hi/lo, optional BN+ReLU transform) ----
    constexpr int AIT = 128 * (KPAD / 2);
    for (int idx = tid; idx < AIT; idx += 256) {
        const int r  = idx / (KPAD / 2);
        const int p  = idx - r * (KPAD / 2);
        const int kk = 2 * p;
        float v0 = 0.f, v1 = 0.f;
        if ((KORIG % 2 == 0) && kk + 2 <= KORIG) {
            float2 f = *(const float2*)(A + (size_t)(m0 + r) * KORIG + kk);
            v0 = f.x; v1 = f.y;
        } else {
            if (kk < KORIG)     v0 = A[(size_t)(m0 + r) * KORIG + kk];
            if (kk + 1 < KORIG) v1 = A[(size_t)(m0 + r) * KORIG + kk + 1];
        }
        if (TRANSFORM) {
            if (kk < KORIG)     v0 = fmaxf(fmaf(v0, __ldg(scale + kk),     __ldg(shift + kk)),     0.f);
            if (kk + 1 < KORIG) v1 = fmaxf(fmaf(v1, __ldg(scale + kk + 1), __ldg(shift + kk + 1)), 0.f);
        }
        __nv_bfloat16 h0 = __float2bfloat16(v0), h1 = __float2bfloat16(v1);
        __nv_bfloat16 l0 = __float2bfloat16(v0 - __bfloat162float(h0));
        __nv_bfloat16 l1 = __float2bfloat16(v1 - __bfloat162float(h1));
        *(__nv_bfloat162*)(aHi + r * LDA + kk) = __halves2bfloat162(h0, h1);
        *(__nv_bfloat162*)(aLo + r * LDA + kk) = __halves2bfloat162(l0, l1);
    }
    // ---- stage B (prepped bf16, straight copy) ----
    constexpr int BIT = KPAD * (BN / 2);
    for (int idx = tid; idx < BIT; idx += 256) {
        const int k = idx / (BN / 2);
        const int n = 2 * (idx - k * (BN / 2));
        *(uint32_t*)(bHi + k * LDB + n) = *(const uint32_t*)(BH + (size_t)k * NTOT + n0 + n);
        *(uint32_t*)(bLo + k * LDB + n) = *(const uint32_t*)(BL + (size_t)k * NTOT + n0 + n);
    }
    __syncthreads();

    // ---- compute ----
    const int wid = tid >> 5, lane = tid & 31;
    const int wm = wid >> 1, wn = wid & 1;
    const int mW = wm * 32, nW = wn * (BN / 2);
    constexpr int NT = BN / 16;           // n8-tiles per warp
    constexpr int KSTEPS = KPAD / 16;

    float acc[2][NT][4];
#pragma unroll
    for (int i = 0; i < 2; i++)
#pragma unroll
        for (int j = 0; j < NT; j++)
#pragma unroll
            for (int q = 0; q < 4; q++) acc[i][j][q] = 0.f;

    const uint32_t aHiU = smem_u32(aHi) + (uint32_t)(mW + (lane & 15)) * (LDA * 2) + (lane >> 4) * 16;
    const uint32_t aLoU = smem_u32(aLo) + (uint32_t)(mW + (lane & 15)) * (LDA * 2) + (lane >> 4) * 16;
    const uint32_t bHiU = smem_u32(bHi) + (uint32_t)(lane & 15) * (LDB * 2) + (uint32_t)nW * 2 + (lane >> 4) * 16;
    const uint32_t bLoU = smem_u32(bLo) + (uint32_t)(lane & 15) * (LDB * 2) + (uint32_t)nW * 2 + (lane >> 4) * 16;

#pragma unroll
    for (int ks = 0; ks < KSTEPS; ks++) {
        uint32_t ah[2][4], al[2][4];
        ldsm4(ah[0], aHiU + ks * 32);
        ldsm4(ah[1], aHiU + 16 * LDA * 2 + ks * 32);
        ldsm4(al[0], aLoU + ks * 32);
        ldsm4(al[1], aLoU + 16 * LDA * 2 + ks * 32);
#pragma unroll
        for (int ng = 0; ng < NT / 2; ng++) {
            uint32_t bh[4], bl[4];
            const uint32_t bo = (uint32_t)ks * (16 * LDB * 2) + ng * 32;
            ldsm4t(bh, bHiU + bo);
            ldsm4t(bl, bLoU + bo);
#pragma unroll
            for (int mt = 0; mt < 2; mt++) {
                mma_bf16(acc[mt][ng*2+0], ah[mt], bh[0], bh[1]);
                mma_bf16(acc[mt][ng*2+0], ah[mt], bl[0], bl[1]);
                mma_bf16(acc[mt][ng*2+0], al[mt], bh[0], bh[1]);
                mma_bf16(acc[mt][ng*2+1], ah[mt], bh[2], bh[3]);
                mma_bf16(acc[mt][ng*2+1], ah[mt], bl[2], bl[3]);
                mma_bf16(acc[mt][ng*2+1], al[mt], bh[2], bh[3]);
            }
        }
    }
    __syncthreads();   // done with staged tiles; reuse smem for reductions

    // ---- epilogue: bias, optional Y store, BN partials, optional group min/max ----
    float* sSum = (float*)dyn;            // [4][BN]
    float* sSq  = sSum + 4 * BN;          // [4][BN]

    const int r0 = lane >> 2;             // 0..7
#pragma unroll
    for (int nt = 0; nt < NT; nt++) {
        const int colLocal = nW + nt * 8 + (lane & 3) * 2;
        const float b0 = __ldg(bias + n0 + colLocal);
        const float b1 = __ldg(bias + n0 + colLocal + 1);
        float v0 = acc[0][nt][0] + b0, v1 = acc[0][nt][1] + b1;
        float v2 = acc[0][nt][2] + b0, v3 = acc[0][nt][3] + b1;
        float v4 = acc[1][nt][0] + b0, v5 = acc[1][nt][1] + b1;
        float v6 = acc[1][nt][2] + b0, v7 = acc[1][nt][3] + b1;
        if (STORE_Y) {
            const size_t base = (size_t)(m0 + mW + r0) * NTOT + n0 + colLocal;
            *(float2*)(Y + base)             = make_float2(v0, v1);
            *(float2*)(Y + base +  8*NTOT)   = make_float2(v2, v3);
            *(float2*)(Y + base + 16*NTOT)   = make_float2(v4, v5);
            *(float2*)(Y + base + 24*NTOT)   = make_float2(v6, v7);
        }
        float s0 = v0+v2+v4+v6,              s1 = v1+v3+v5+v7;
        float q0 = v0*v0+v2*v2+v4*v4+v6*v6,  q1 = v1*v1+v3*v3+v5*v5+v7*v7;
        float mx0 = fmaxf(fmaxf(v0,v2), fmaxf(v4,v6)), mx1 = fmaxf(fmaxf(v1,v3), fmaxf(v5,v7));
        float mn0 = fminf(fminf(v0,v2), fminf(v4,v6)), mn1 = fminf(fminf(v1,v3), fminf(v5,v7));
#pragma unroll
        for (int d = 4; d < 32; d <<= 1) {
            s0 += __shfl_xor_sync(0xffffffffu, s0, d);
            s1 += __shfl_xor_sync(0xffffffffu, s1, d);
            q0 += __shfl_xor_sync(0xffffffffu, q0, d);
            q1 += __shfl_xor_sync(0xffffffffu, q1, d);
            mx0 = fmaxf(mx0, __shfl_xor_sync(0xffffffffu, mx0, d));
            mx1 = fmaxf(mx1, __shfl_xor_sync(0xffffffffu, mx1, d));
            mn0 = fminf(mn0, __shfl_xor_sync(0xffffffffu, mn0, d));
            mn1 = fminf(mn1, __shfl_xor_sync(0xffffffffu, mn1, d));
        }
        if (lane < 4) {
            sSum[wm*BN + colLocal] = s0;  sSum[wm*BN + colLocal + 1] = s1;
            sSq [wm*BN + colLocal] = q0;  sSq [wm*BN + colLocal + 1] = q1;
            if (FUSED_MAX) {
                const size_t grp = (size_t)(mb * 4 + wm) * CH3 + n0 + colLocal;
                gmax[grp]     = mx0;  gmax[grp + 1] = mx1;
                gmin[grp]     = mn0;  gmin[grp + 1] = mn1;
            }
        }
    }
    __syncthreads();
    for (int n = tid; n < BN; n += 256) {
        float s = sSum[n] + sSum[BN + n] + sSum[2*BN + n] + sSum[3*BN + n];
        float q = sSq [n] + sSq [BN + n] + sSq [2*BN + n] + sSq [3*BN + n];
        partSum[(size_t)mb * NTOT + n0 + n] = s;
        partSq [(size_t)mb * NTOT + n0 + n] = q;
    }
}

// ---------------- fold partials -> scale/shift ----------------
__global__ __launch_bounds__(256) void stats_kernel(const float* __restrict__ partSum,
                                                    const float* __restrict__ partSq,
                                                    int N,
                                                    const float* __restrict__ g,
                                                    const float* __restrict__ bt,
                                                    float* __restrict__ scale,
                                                    float* __restrict__ shift)
{
    const int c = blockIdx.x, tid = threadIdx.x;
    __shared__ float ss[256], sq[256];
    float a = 0.f, b2 = 0.f;
    for (int mb = tid; mb < MBLK; mb += 256) {
        a  += partSum[(size_t)mb * N + c];
        b2 += partSq [(size_t)mb * N + c];
    }
    ss[tid] = a; sq[tid] = b2;
    __syncthreads();
    for (int s = 128; s > 0; s >>= 1) {
        if (tid < s) { ss[tid] += ss[tid+s]; sq[tid] += sq[tid+s]; }
        __syncthreads();
    }
    if (tid == 0) {
        const float invM = 1.0f / (float)MTOT;
        float mean = ss[0] * invM;
        float var  = sq[0] * invM - mean * mean;
        float sc   = g[c] / sqrtf(var + BNEPS);
        scale[c] = sc;
        shift[c] = bt[c] - mean * sc;
    }
}

// ---------------- final: pick max/min by sign(scale), affine+relu ----------------
__global__ __launch_bounds__(256) void finalpool_kernel(const float* __restrict__ gmax,
                                                        const float* __restrict__ gmin,
                                                        const float* __restrict__ scale,
                                                        const float* __restrict__ shift,
                                                        float* __restrict__ out)
{
    const int g = blockIdx.x, c = threadIdx.x;
    const float sc = scale[c], sh = shift[c];
    const float v = (sc >= 0.f) ? gmax[(size_t)g * CH3 + c] : gmin[(size_t)g * CH3 + c];
    out[(size_t)g * CH3 + c] = fmaxf(fmaf(v, sc, sh), 0.f);
}

// ---------------- launch ----------------
extern "C" void kernel_launch(void* const* d_in, const int* in_sizes, int n_in,
                              void* d_out, int out_size)
{
    const float* xyz    = (const float*)d_in[0];
    const float* points = (const float*)d_in[1];
    const float* w0  = (const float*)d_in[2];
    const float* b0  = (const float*)d_in[3];
    const float* g0  = (const float*)d_in[4];
    const float* bt0 = (const float*)d_in[5];
    const float* w1  = (const float*)d_in[6];
    const float* b1  = (const float*)d_in[7];
    const float* g1  = (const float*)d_in[8];
    const float* bt1 = (const float*)d_in[9];
    const float* w2  = (const float*)d_in[10];
    const float* b2  = (const float*)d_in[11];
    const float* g2  = (const float*)d_in[12];
    const float* bt2 = (const float*)d_in[13];

    float* out        = (float*)d_out;
    float* new_xyz    = out;
    float* new_points = out + (size_t)BATCH*SPTS*3;

    float *x0, *y1, *y2, *part, *scale, *shift, *gmax, *gmin;
    int* gidx;
    __nv_bfloat16 *bh0, *bl0, *bh1, *bl1, *bh2, *bl2;
    cudaGetSymbolAddress((void**)&x0,    g_x0);
    cudaGetSymbolAddress((void**)&y1,    g_y1);
    cudaGetSymbolAddress((void**)&y2,    g_y2);
    cudaGetSymbolAddress((void**)&part,  g_part);
    cudaGetSymbolAddress((void**)&scale, g_scale);
    cudaGetSymbolAddress((void**)&shift, g_shift);
    cudaGetSymbolAddress((void**)&gidx,  g_gidx);
    cudaGetSymbolAddress((void**)&gmax,  g_gmax);
    cudaGetSymbolAddress((void**)&gmin,  g_gmin);
    cudaGetSymbolAddress((void**)&bh0,   g_bh0);
    cudaGetSymbolAddress((void**)&bl0,   g_bl0);
    cudaGetSymbolAddress((void**)&bh1,   g_bh1);
    cudaGetSymbolAddress((void**)&bl1,   g_bl1);
    cudaGetSymbolAddress((void**)&bh2,   g_bh2);
    cudaGetSymbolAddress((void**)&bl2,   g_bl2);

    float* partSum = part;
    float* partSq  = part + (size_t)MBLK * CH3;

    // smem bytes: 2*(2*128*LDA + 2*KPAD*LDB)
    constexpr int SM1 = (2*128*(80+8)  + 2*80 *(64+8))  * 2;  //  68,096
    constexpr int SM2 = (2*128*(64+8)  + 2*64 *(128+8)) * 2;  //  71,680
    constexpr int SM3 = (2*128*(128+8) + 2*128*(128+8)) * 2;  // 139,264

    static bool attrDone = false;
    if (!attrDone) {
        cudaFuncSetAttribute(gemm_mma<64, 64, 80, 80, false, true, false, 2>,
                             cudaFuncAttributeMaxDynamicSharedMemorySize, SM1);
        cudaFuncSetAttribute(gemm_mma<128, 128, 64, 64, true, true, false, 2>,
                             cudaFuncAttributeMaxDynamicSharedMemorySize, SM2);
        cudaFuncSetAttribute(gemm_mma<128, 256, 128, 128, true, false, true, 1>,
                             cudaFuncAttributeMaxDynamicSharedMemorySize, SM3);
        attrDone = true;
    }

    prep_kernel<<<(80*64 + 255)/256, 256>>>(w0, CH0, CH1, 80, bh0, bl0);
    prep_kernel<<<(64*128 + 255)/256, 256>>>(w1, CH1, CH2, 64, bh1, bl1);
    prep_kernel<<<(128*256 + 255)/256, 256>>>(w2, CH2, CH3, 128, bh2, bl2);

    fps_kernel<<<BATCH, 512>>>(xyz, new_xyz);
    ballquery_kernel<<<BATCH*SPTS/8, 256>>>(xyz, new_xyz, gidx);
    gather_kernel<<<BATCH*SPTS, 128>>>(xyz, points, new_xyz, gidx, x0);

    // layer 1: 67 -> 64 (x0 padded to stride 80; pad cols are zero, weight pad rows are zero)
    gemm_mma<64, 64, 80, 80, false, true, false, 2><<<dim3(1, MBLK), 256, SM1>>>(
        x0, bh0, bl0, b0, nullptr, nullptr, y1, partSum, partSq, nullptr, nullptr);
    stats_kernel<<<CH1, 256>>>(partSum, partSq, CH1, g0, bt0, scale, shift);

    // layer 2: 64 -> 128
    gemm_mma<128, 128, 64, 64, true, true, false, 2><<<dim3(1, MBLK), 256, SM2>>>(
        y1, bh1, bl1, b1, scale, shift, y2, partSum, partSq, nullptr, nullptr);
    stats_kernel<<<CH2, 256>>>(partSum, partSq, CH2, g1, bt1, scale, shift);

    // layer 3: 128 -> 256 (no Y store; fused per-group min/max)
    gemm_mma<128, 256, 128, 128, true, false, true, 1><<<dim3(2, MBLK), 256, SM3>>>(
        y2, bh2, bl2, b2, scale, shift, nullptr, partSum, partSq, gmax, gmin);
    stats_kernel<<<CH3, 256>>>(partSum, partSq, CH3, g2, bt2, scale, shift);

    finalpool_kernel<<<BATCH*SPTS, 256>>>(gmax, gmin, scale, shift, new_points);
}

// round 7
// speedup vs baseline: 1.6128x; 1.0575x over previous
#include <cuda_runtime.h>
#include <cuda_bf16.h>
#include <math.h>
#include <stdint.h>

// ---------------- problem constants ----------------
#define BATCH 16
#define NPTS  4096
#define DFEAT 64
#define SPTS  1024
#define NSAMP 32
#define CH0   67
#define CH1   64
#define CH2   128
#define CH3   256
#define MTOT  (BATCH*SPTS*NSAMP)   // 524288
#define MBLK  (MTOT/128)           // 4096
#define RAD2  0.04f
#define BNEPS 1e-5f

typedef unsigned long long ull;

// ---------------- device scratch ----------------
__device__ uint32_t g_y1[(size_t)MTOT*CH1];   // packed bf16 hi|lo
__device__ uint32_t g_y2[(size_t)MTOT*CH2];   // packed bf16 hi|lo
__device__ int   g_gidx[BATCH*SPTS*NSAMP];
__device__ float g_part[2*(size_t)MBLK*CH3];
__device__ float g_scale[CH3];
__device__ float g_shift[CH3];
__device__ float g_gmax[(size_t)BATCH*SPTS*CH3];
__device__ float g_gmin[(size_t)BATCH*SPTS*CH3];
// weights prepped k-major [KPAD][N], bf16 hi/lo
__device__ __nv_bfloat16 g_bh0[80*64],   g_bl0[80*64];
__device__ __nv_bfloat16 g_bh1[64*128],  g_bl1[64*128];
__device__ __nv_bfloat16 g_bh2[128*256], g_bl2[128*256];

// ---------------- helpers ----------------
__device__ __forceinline__ uint32_t smem_u32(const void* p) {
    uint32_t a;
    asm("{ .reg .u64 t; cvta.to.shared.u64 t, %1; cvt.u32.u64 %0, t; }" : "=r"(a) : "l"(p));
    return a;
}
__device__ __forceinline__ void ldsm4(uint32_t* r, uint32_t a) {
    asm volatile("ldmatrix.sync.aligned.m8n8.x4.shared.b16 {%0,%1,%2,%3}, [%4];"
                 : "=r"(r[0]), "=r"(r[1]), "=r"(r[2]), "=r"(r[3]) : "r"(a));
}
__device__ __forceinline__ void ldsm4t(uint32_t* r, uint32_t a) {
    asm volatile("ldmatrix.sync.aligned.m8n8.x4.trans.shared.b16 {%0,%1,%2,%3}, [%4];"
                 : "=r"(r[0]), "=r"(r[1]), "=r"(r[2]), "=r"(r[3]) : "r"(a));
}
__device__ __forceinline__ void mma_bf16(float* c, const uint32_t* a, uint32_t b0, uint32_t b1) {
    asm volatile(
        "mma.sync.aligned.m16n8k16.row.col.f32.bf16.bf16.f32 "
        "{%0,%1,%2,%3}, {%4,%5,%6,%7}, {%8,%9}, {%0,%1,%2,%3};"
        : "+f"(c[0]), "+f"(c[1]), "+f"(c[2]), "+f"(c[3])
        : "r"(a[0]), "r"(a[1]), "r"(a[2]), "r"(a[3]), "r"(b0), "r"(b1));
}
__device__ __forceinline__ uint32_t packsplit(float v) {
    __nv_bfloat16 h = __float2bfloat16(v);
    float rl = v - __bfloat162float(h);
    __nv_bfloat16 l = __float2bfloat16(rl);
    return ((uint32_t)__bfloat16_as_ushort(h) << 16) | (uint32_t)__bfloat16_as_ushort(l);
}

// ---------------- FPS v5: scalar argmax chain + single key pack ----------------
__global__ __launch_bounds__(512) void fps_kernel(const float* __restrict__ xyz,
                                                  float* __restrict__ new_xyz)
{
    __shared__ float sx[NPTS], sy[NPTS], sz[NPTS];
    __shared__ ull s_key[2][16];
    const int b = blockIdx.x, tid = threadIdx.x;
    const int lane = tid & 31, wid = tid >> 5;
    const float* X = xyz + (size_t)b * NPTS * 3;

    ull pxp[4], pyp[4], pzp[4];
    float dist[8];
#pragma unroll
    for (int t = 0; t < 8; t++) dist[t] = 1e10f;
#pragma unroll
    for (int t = 0; t < 4; t++) {
        const int j0 = tid + (2*t) * 512, j1 = tid + (2*t+1) * 512;
        float x0 = X[3*j0], y0 = X[3*j0+1], z0 = X[3*j0+2];
        float x1 = X[3*j1], y1 = X[3*j1+1], z1 = X[3*j1+2];
        sx[j0] = x0; sy[j0] = y0; sz[j0] = z0;
        sx[j1] = x1; sy[j1] = y1; sz[j1] = z1;
        asm("mov.b64 %0, {%1,%2};" : "=l"(pxp[t]) : "f"(x0), "f"(x1));
        asm("mov.b64 %0, {%1,%2};" : "=l"(pyp[t]) : "f"(y0), "f"(y1));
        asm("mov.b64 %0, {%1,%2};" : "=l"(pzp[t]) : "f"(z0), "f"(z1));
    }
    __syncthreads();

    int far = 0;
    for (int i = 0; i < SPTS; i++) {
        const float cx = sx[far], cy = sy[far], cz = sz[far];
        if (tid == 0) {
            float* o = new_xyz + ((size_t)b * SPTS + i) * 3;
            o[0] = cx; o[1] = cy; o[2] = cz;
        }
        if (i == SPTS - 1) break;

        const float mx = -cx, my = -cy, mz = -cz;
        ull ncx, ncy, ncz;
        asm("mov.b64 %0, {%1,%1};" : "=l"(ncx) : "f"(mx));
        asm("mov.b64 %0, {%1,%1};" : "=l"(ncy) : "f"(my));
        asm("mov.b64 %0, {%1,%1};" : "=l"(ncz) : "f"(mz));

        float bv = -1.0f; int bi = 0;
#pragma unroll
        for (int t = 0; t < 4; t++) {
            ull dx, dy, dz, dd;
            asm("add.rn.f32x2 %0, %1, %2;" : "=l"(dx) : "l"(pxp[t]), "l"(ncx));
            asm("add.rn.f32x2 %0, %1, %2;" : "=l"(dy) : "l"(pyp[t]), "l"(ncy));
            asm("add.rn.f32x2 %0, %1, %2;" : "=l"(dz) : "l"(pzp[t]), "l"(ncz));
            asm("mul.rn.f32x2 %0, %1, %2;" : "=l"(dd) : "l"(dx), "l"(dx));
            asm("fma.rn.f32x2 %0, %1, %2, %3;" : "=l"(dd) : "l"(dy), "l"(dy), "l"(dd));
            asm("fma.rn.f32x2 %0, %1, %2, %3;" : "=l"(dd) : "l"(dz), "l"(dz), "l"(dd));
            float d0, d1;
            asm("mov.b64 {%0,%1}, %2;" : "=f"(d0), "=f"(d1) : "l"(dd));
            const float nd0 = fminf(dist[2*t],   d0);
            const float nd1 = fminf(dist[2*t+1], d1);
            dist[2*t]   = nd0;
            dist[2*t+1] = nd1;
            // strict > keeps first (lowest-index) max; t ascending => idx ascending
            if (nd0 > bv) { bv = nd0; bi = tid + (2*t)   * 512; }
            if (nd1 > bv) { bv = nd1; bi = tid + (2*t+1) * 512; }
        }
        const unsigned vb = __float_as_uint(bv);        // bv >= 0 => order-preserving bits
        const unsigned m  = __reduce_max_sync(0xffffffffu, vb);
        const unsigned lw = __reduce_max_sync(0xffffffffu,
                                              (vb == m) ? (0xFFFFu - (unsigned)bi) : 0u);
        const int buf = i & 1;
        if (lane == 0) s_key[buf][wid] = ((ull)m << 32) | lw;
        __syncthreads();

        ull q = s_key[buf][lane & 15];
#pragma unroll
        for (int d = 8; d > 0; d >>= 1) {
            ull o = __shfl_down_sync(0xffffffffu, q, d);
            if (o > q) q = o;
        }
        q = __shfl_sync(0xffffffffu, q, 0);
        far = 0xFFFF - (int)(q & 0xFFFFull);
    }
}

// ---------------- ball query ----------------
__global__ __launch_bounds__(256) void ballquery_kernel(const float* __restrict__ xyz,
                                                        const float* __restrict__ new_xyz,
                                                        int* __restrict__ gidx)
{
    const int w    = blockIdx.x * 8 + (threadIdx.x >> 5);
    const int lane = threadIdx.x & 31;
    const int b    = w >> 10;
    const float* X = xyz + (size_t)b * NPTS * 3;

    const float cx = new_xyz[(size_t)w*3+0];
    const float cy = new_xyz[(size_t)w*3+1];
    const float cz = new_xyz[(size_t)w*3+2];
    const float ss = cx*cx + cy*cy + cz*cz;

    int cnt = 0, firstIdx = 0;
    int* out = gidx + (size_t)w * NSAMP;

    for (int base = 0; base < NPTS && cnt < NSAMP; base += 32) {
        const int j = base + lane;
        const float x = X[3*j], y = X[3*j+1], z = X[3*j+2];
        const float pp  = x*x + y*y + z*z;
        const float dot = x*cx + y*cy + z*cz;
        const float d   = (-2.0f*dot + ss) + pp;
        const bool  in  = !(d > RAD2);
        unsigned mask = __ballot_sync(0xffffffffu, in);
        if (cnt == 0 && mask) firstIdx = base + (__ffs(mask) - 1);
        int rank = __popc(mask & ((1u << lane) - 1u));
        int slot = cnt + rank;
        if (in && slot < NSAMP) out[slot] = j;
        cnt += __popc(mask);
    }
    for (int t = cnt + lane; t < NSAMP; t += 32) out[t] = firstIdx;
}

// ---------------- weight prep: W[K][N] f32 -> [KPAD][N] bf16 hi/lo (k-major) ----------------
__global__ __launch_bounds__(256) void prep_kernel(const float* __restrict__ W, int K, int N,
                                                   int KPAD,
                                                   __nv_bfloat16* __restrict__ bh,
                                                   __nv_bfloat16* __restrict__ bl)
{
    int i = blockIdx.x * 256 + threadIdx.x;
    if (i >= N * KPAD) return;
    int k = i / N, n = i - k * N;
    float v = (k < K) ? W[(size_t)k * N + n] : 0.f;
    __nv_bfloat16 h = __float2bfloat16(v);
    bh[i] = h;
    bl[i] = __float2bfloat16(v - __bfloat162float(h));
}

// ---------------- HMMA GEMM (bf16 split-3, full-K staged) ----------------
// AMODE: 0 = gather from xyz/points (layer 1), 1 = packed bf16 hi|lo u32 input.
template<int BN, int NTOT, int KPAD, int KORIG, int AMODE,
         bool TRANSFORM, bool STORE_Y, bool FUSED_MAX, int MINB>
__global__ void __launch_bounds__(256, MINB) gemm_mma(
    const uint32_t* __restrict__ A,
    const int* __restrict__ gidxp, const float* __restrict__ xyzp,
    const float* __restrict__ pointsp, const float* __restrict__ nxyz,
    const __nv_bfloat16* __restrict__ BH, const __nv_bfloat16* __restrict__ BL,
    const float* __restrict__ bias,
    const float* __restrict__ scale, const float* __restrict__ shift,
    uint32_t* __restrict__ Y,
    float* __restrict__ partSum, float* __restrict__ partSq,
    float* __restrict__ gmax, float* __restrict__ gmin)
{
    extern __shared__ __align__(16) char dyn[];
    __shared__ int   sIdx[128];
    __shared__ float sCen[12];
    constexpr int LDA = KPAD + 8;   // bf16 units
    constexpr int LDB = BN + 8;
    __nv_bfloat16* aHi = (__nv_bfloat16*)dyn;
    __nv_bfloat16* aLo = aHi + 128 * LDA;
    __nv_bfloat16* bHi = aLo + 128 * LDA;
    __nv_bfloat16* bLo = bHi + KPAD * LDB;

    const int tid = threadIdx.x;
    const int nb = blockIdx.x, mb = blockIdx.y;
    const int m0 = mb * 128, n0 = nb * BN;

    if (AMODE == 0) {
        if (tid < 128) sIdx[tid] = gidxp[m0 + tid];
        if (tid < 12)  sCen[tid] = nxyz[(size_t)(mb * 4) * 3 + tid];
        __syncthreads();
    }

    // ---- stage A -> bf16 hi/lo tiles ----
    constexpr int AIT = 128 * (KPAD / 2);
    const int bb = m0 >> 15;
    const float* Xb = xyzp    ? xyzp    + (size_t)bb * NPTS * 3     : nullptr;
    const float* Pb = pointsp ? pointsp + (size_t)bb * NPTS * DFEAT : nullptr;
    for (int idx = tid; idx < AIT; idx += 256) {
        const int r  = idx / (KPAD / 2);
        const int p  = idx - r * (KPAD / 2);
        const int kk = 2 * p;
        float v0 = 0.f, v1 = 0.f;
        if (AMODE == 0) {
            const int j = sIdx[r];
            const int grp = (r >> 5) * 3;
            if (kk < 3)        v0 = Xb[j*3 + kk] - sCen[grp + kk];
            else if (kk < CH0) v0 = Pb[(size_t)j * DFEAT + kk - 3];
            const int c1 = kk + 1;
            if (c1 < 3)        v1 = Xb[j*3 + c1] - sCen[grp + c1];
            else if (c1 < CH0) v1 = Pb[(size_t)j * DFEAT + c1 - 3];
        } else {
            const uint2 w = *(const uint2*)(A + (size_t)(m0 + r) * KORIG + kk);
            v0 = __uint_as_float(w.x & 0xFFFF0000u) + __uint_as_float(w.x << 16);
            v1 = __uint_as_float(w.y & 0xFFFF0000u) + __uint_as_float(w.y << 16);
            if (TRANSFORM) {
                v0 = fmaxf(fmaf(v0, __ldg(scale + kk),     __ldg(shift + kk)),     0.f);
                v1 = fmaxf(fmaf(v1, __ldg(scale + kk + 1), __ldg(shift + kk + 1)), 0.f);
            }
        }
        __nv_bfloat16 h0 = __float2bfloat16(v0), h1 = __float2bfloat16(v1);
        __nv_bfloat16 l0 = __float2bfloat16(v0 - __bfloat162float(h0));
        __nv_bfloat16 l1 = __float2bfloat16(v1 - __bfloat162float(h1));
        *(__nv_bfloat162*)(aHi + r * LDA + kk) = __halves2bfloat162(h0, h1);
        *(__nv_bfloat162*)(aLo + r * LDA + kk) = __halves2bfloat162(l0, l1);
    }
    // ---- stage B (prepped bf16, straight copy) ----
    constexpr int BIT = KPAD * (BN / 2);
    for (int idx = tid; idx < BIT; idx += 256) {
        const int k = idx / (BN / 2);
        const int n = 2 * (idx - k * (BN / 2));
        *(uint32_t*)(bHi + k * LDB + n) = *(const uint32_t*)(BH + (size_t)k * NTOT + n0 + n);
        *(uint32_t*)(bLo + k * LDB + n) = *(const uint32_t*)(BL + (size_t)k * NTOT + n0 + n);
    }
    __syncthreads();

    // ---- compute ----
    const int wid = tid >> 5, lane = tid & 31;
    const int wm = wid >> 1, wn = wid & 1;
    const int mW = wm * 32, nW = wn * (BN / 2);
    constexpr int NT = BN / 16;           // n8-tiles per warp
    constexpr int KSTEPS = KPAD / 16;

    float acc[2][NT][4];
#pragma unroll
    for (int i = 0; i < 2; i++)
#pragma unroll
        for (int j = 0; j < NT; j++)
#pragma unroll
            for (int q = 0; q < 4; q++) acc[i][j][q] = 0.f;

    const uint32_t aHiU = smem_u32(aHi) + (uint32_t)(mW + (lane & 15)) * (LDA * 2) + (lane >> 4) * 16;
    const uint32_t aLoU = smem_u32(aLo) + (uint32_t)(mW + (lane & 15)) * (LDA * 2) + (lane >> 4) * 16;
    const uint32_t bHiU = smem_u32(bHi) + (uint32_t)(lane & 15) * (LDB * 2) + (uint32_t)nW * 2 + (lane >> 4) * 16;
    const uint32_t bLoU = smem_u32(bLo) + (uint32_t)(lane & 15) * (LDB * 2) + (uint32_t)nW * 2 + (lane >> 4) * 16;

#pragma unroll
    for (int ks = 0; ks < KSTEPS; ks++) {
        uint32_t ah[2][4], al[2][4];
        ldsm4(ah[0], aHiU + ks * 32);
        ldsm4(ah[1], aHiU + 16 * LDA * 2 + ks * 32);
        ldsm4(al[0], aLoU + ks * 32);
        ldsm4(al[1], aLoU + 16 * LDA * 2 + ks * 32);
#pragma unroll
        for (int ng = 0; ng < NT / 2; ng++) {
            uint32_t bh[4], bl[4];
            const uint32_t bo = (uint32_t)ks * (16 * LDB * 2) + ng * 32;
            ldsm4t(bh, bHiU + bo);
            ldsm4t(bl, bLoU + bo);
#pragma unroll
            for (int mt = 0; mt < 2; mt++) {
                mma_bf16(acc[mt][ng*2+0], ah[mt], bh[0], bh[1]);
                mma_bf16(acc[mt][ng*2+0], ah[mt], bl[0], bl[1]);
                mma_bf16(acc[mt][ng*2+0], al[mt], bh[0], bh[1]);
                mma_bf16(acc[mt][ng*2+1], ah[mt], bh[2], bh[3]);
                mma_bf16(acc[mt][ng*2+1], ah[mt], bl[2], bl[3]);
                mma_bf16(acc[mt][ng*2+1], al[mt], bh[2], bh[3]);
            }
        }
    }
    __syncthreads();   // done with staged tiles; reuse smem for reductions

    // ---- epilogue: bias, optional packed-Y store, BN partials, optional group min/max ----
    float* sSum = (float*)dyn;            // [4][BN]
    float* sSq  = sSum + 4 * BN;          // [4][BN]

    const int r0 = lane >> 2;             // 0..7
#pragma unroll
    for (int nt = 0; nt < NT; nt++) {
        const int colLocal = nW + nt * 8 + (lane & 3) * 2;
        const float b0 = __ldg(bias + n0 + colLocal);
        const float b1 = __ldg(bias + n0 + colLocal + 1);
        float v0 = acc[0][nt][0] + b0, v1 = acc[0][nt][1] + b1;
        float v2 = acc[0][nt][2] + b0, v3 = acc[0][nt][3] + b1;
        float v4 = acc[1][nt][0] + b0, v5 = acc[1][nt][1] + b1;
        float v6 = acc[1][nt][2] + b0, v7 = acc[1][nt][3] + b1;
        if (STORE_Y) {
            const size_t base = (size_t)(m0 + mW + r0) * NTOT + n0 + colLocal;
            *(uint2*)(Y + base)           = make_uint2(packsplit(v0), packsplit(v1));
            *(uint2*)(Y + base +  8*NTOT) = make_uint2(packsplit(v2), packsplit(v3));
            *(uint2*)(Y + base + 16*NTOT) = make_uint2(packsplit(v4), packsplit(v5));
            *(uint2*)(Y + base + 24*NTOT) = make_uint2(packsplit(v6), packsplit(v7));
        }
        float s0 = v0+v2+v4+v6,              s1 = v1+v3+v5+v7;
        float q0 = v0*v0+v2*v2+v4*v4+v6*v6,  q1 = v1*v1+v3*v3+v5*v5+v7*v7;
        float mx0 = fmaxf(fmaxf(v0,v2), fmaxf(v4,v6)), mx1 = fmaxf(fmaxf(v1,v3), fmaxf(v5,v7));
        float mn0 = fminf(fminf(v0,v2), fminf(v4,v6)), mn1 = fminf(fminf(v1,v3), fminf(v5,v7));
#pragma unroll
        for (int d = 4; d < 32; d <<= 1) {
            s0 += __shfl_xor_sync(0xffffffffu, s0, d);
            s1 += __shfl_xor_sync(0xffffffffu, s1, d);
            q0 += __shfl_xor_sync(0xffffffffu, q0, d);
            q1 += __shfl_xor_sync(0xffffffffu, q1, d);
            mx0 = fmaxf(mx0, __shfl_xor_sync(0xffffffffu, mx0, d));
            mx1 = fmaxf(mx1, __shfl_xor_sync(0xffffffffu, mx1, d));
            mn0 = fminf(mn0, __shfl_xor_sync(0xffffffffu, mn0, d));
            mn1 = fminf(mn1, __shfl_xor_sync(0xffffffffu, mn1, d));
        }
        if (lane < 4) {
            sSum[wm*BN + colLocal] = s0;  sSum[wm*BN + colLocal + 1] = s1;
            sSq [wm*BN + colLocal] = q0;  sSq [wm*BN + colLocal + 1] = q1;
            if (FUSED_MAX) {
                const size_t grp = (size_t)(mb * 4 + wm) * CH3 + n0 + colLocal;
                gmax[grp]     = mx0;  gmax[grp + 1] = mx1;
                gmin[grp]     = mn0;  gmin[grp + 1] = mn1;
            }
        }
    }
    __syncthreads();
    for (int n = tid; n < BN; n += 256) {
        float s = sSum[n] + sSum[BN + n] + sSum[2*BN + n] + sSum[3*BN + n];
        float q = sSq [n] + sSq [BN + n] + sSq [2*BN + n] + sSq [3*BN + n];
        partSum[(size_t)mb * NTOT + n0 + n] = s;
        partSq [(size_t)mb * NTOT + n0 + n] = q;
    }
}

// ---------------- fold partials -> scale/shift ----------------
__global__ __launch_bounds__(256) void stats_kernel(const float* __restrict__ partSum,
                                                    const float* __restrict__ partSq,
                                                    int N,
                                                    const float* __restrict__ g,
                                                    const float* __restrict__ bt,
                                                    float* __restrict__ scale,
                                                    float* __restrict__ shift)
{
    const int c = blockIdx.x, tid = threadIdx.x;
    __shared__ float ss[256], sq[256];
    float a = 0.f, b2 = 0.f;
    for (int mb = tid; mb < MBLK; mb += 256) {
        a  += partSum[(size_t)mb * N + c];
        b2 += partSq [(size_t)mb * N + c];
    }
    ss[tid] = a; sq[tid] = b2;
    __syncthreads();
    for (int s = 128; s > 0; s >>= 1) {
        if (tid < s) { ss[tid] += ss[tid+s]; sq[tid] += sq[tid+s]; }
        __syncthreads();
    }
    if (tid == 0) {
        const float invM = 1.0f / (float)MTOT;
        float mean = ss[0] * invM;
        float var  = sq[0] * invM - mean * mean;
        float sc   = g[c] / sqrtf(var + BNEPS);
        scale[c] = sc;
        shift[c] = bt[c] - mean * sc;
    }
}

// ---------------- final: pick max/min by sign(scale), affine+relu ----------------
__global__ __launch_bounds__(256) void finalpool_kernel(const float* __restrict__ gmax,
                                                        const float* __restrict__ gmin,
                                                        const float* __restrict__ scale,
                                                        const float* __restrict__ shift,
                                                        float* __restrict__ out)
{
    const int g = blockIdx.x, c = threadIdx.x;
    const float sc = scale[c], sh = shift[c];
    const float v = (sc >= 0.f) ? gmax[(size_t)g * CH3 + c] : gmin[(size_t)g * CH3 + c];
    out[(size_t)g * CH3 + c] = fmaxf(fmaf(v, sc, sh), 0.f);
}

// ---------------- launch ----------------
extern "C" void kernel_launch(void* const* d_in, const int* in_sizes, int n_in,
                              void* d_out, int out_size)
{
    const float* xyz    = (const float*)d_in[0];
    const float* points = (const float*)d_in[1];
    const float* w0  = (const float*)d_in[2];
    const float* b0  = (const float*)d_in[3];
    const float* g0  = (const float*)d_in[4];
    const float* bt0 = (const float*)d_in[5];
    const float* w1  = (const float*)d_in[6];
    const float* b1  = (const float*)d_in[7];
    const float* g1  = (const float*)d_in[8];
    const float* bt1 = (const float*)d_in[9];
    const float* w2  = (const float*)d_in[10];
    const float* b2  = (const float*)d_in[11];
    const float* g2  = (const float*)d_in[12];
    const float* bt2 = (const float*)d_in[13];

    float* out        = (float*)d_out;
    float* new_xyz    = out;
    float* new_points = out + (size_t)BATCH*SPTS*3;

    float *part, *scale, *shift, *gmax, *gmin;
    uint32_t *y1, *y2;
    int* gidx;
    __nv_bfloat16 *bh0, *bl0, *bh1, *bl1, *bh2, *bl2;
    cudaGetSymbolAddress((void**)&y1,    g_y1);
    cudaGetSymbolAddress((void**)&y2,    g_y2);
    cudaGetSymbolAddress((void**)&part,  g_part);
    cudaGetSymbolAddress((void**)&scale, g_scale);
    cudaGetSymbolAddress((void**)&shift, g_shift);
    cudaGetSymbolAddress((void**)&gidx,  g_gidx);
    cudaGetSymbolAddress((void**)&gmax,  g_gmax);
    cudaGetSymbolAddress((void**)&gmin,  g_gmin);
    cudaGetSymbolAddress((void**)&bh0,   g_bh0);
    cudaGetSymbolAddress((void**)&bl0,   g_bl0);
    cudaGetSymbolAddress((void**)&bh1,   g_bh1);
    cudaGetSymbolAddress((void**)&bl1,   g_bl1);
    cudaGetSymbolAddress((void**)&bh2,   g_bh2);
    cudaGetSymbolAddress((void**)&bl2,   g_bl2);

    float* partSum = part;
    float* partSq  = part + (size_t)MBLK * CH3;

    // smem bytes: 2*(2*128*LDA + 2*KPAD*LDB)
    constexpr int SM1 = (2*128*(80+8)  + 2*80 *(64+8))  * 2;  //  68,096
    constexpr int SM2 = (2*128*(64+8)  + 2*64 *(128+8)) * 2;  //  71,680
    constexpr int SM3 = (2*128*(128+8) + 2*128*(128+8)) * 2;  // 139,264

    static bool attrDone = false;
    if (!attrDone) {
        cudaFuncSetAttribute(gemm_mma<64, 64, 80, 67, 0, false, true, false, 2>,
                             cudaFuncAttributeMaxDynamicSharedMemorySize, SM1);
        cudaFuncSetAttribute(gemm_mma<128, 128, 64, 64, 1, true, true, false, 2>,
                             cudaFuncAttributeMaxDynamicSharedMemorySize, SM2);
        cudaFuncSetAttribute(gemm_mma<128, 256, 128, 128, 1, true, false, true, 1>,
                             cudaFuncAttributeMaxDynamicSharedMemorySize, SM3);
        attrDone = true;
    }

    prep_kernel<<<(80*64 + 255)/256, 256>>>(w0, CH0, CH1, 80, bh0, bl0);
    prep_kernel<<<(64*128 + 255)/256, 256>>>(w1, CH1, CH2, 64, bh1, bl1);
    prep_kernel<<<(128*256 + 255)/256, 256>>>(w2, CH2, CH3, 128, bh2, bl2);

    fps_kernel<<<BATCH, 512>>>(xyz, new_xyz);
    ballquery_kernel<<<BATCH*SPTS/8, 256>>>(xyz, new_xyz, gidx);

    // layer 1: 67 -> 64, gather fused into A-stage (no x0 buffer)
    gemm_mma<64, 64, 80, 67, 0, false, true, false, 2><<<dim3(1, MBLK), 256, SM1>>>(
        nullptr, gidx, xyz, points, new_xyz,
        bh0, bl0, b0, nullptr, nullptr, y1, partSum, partSq, nullptr, nullptr);
    stats_kernel<<<CH1, 256>>>(partSum, partSq, CH1, g0, bt0, scale, shift);

    // layer 2: 64 -> 128 (consumes packed y1)
    gemm_mma<128, 128, 64, 64, 1, true, true, false, 2><<<dim3(1, MBLK), 256, SM2>>>(
        y1, nullptr, nullptr, nullptr, nullptr,
        bh1, bl1, b1, scale, shift, y2, partSum, partSq, nullptr, nullptr);
    stats_kernel<<<CH2, 256>>>(partSum, partSq, CH2, g1, bt1, scale, shift);

    // layer 3: 128 -> 256 (consumes packed y2; fused per-group min/max)
    gemm_mma<128, 256, 128, 128, 1, true, false, true, 1><<<dim3(2, MBLK), 256, SM3>>>(
        y2, nullptr, nullptr, nullptr, nullptr,
        bh2, bl2, b2, scale, shift, nullptr, partSum, partSq, gmax, gmin);
    stats_kernel<<<CH3, 256>>>(partSum, partSq, CH3, g2, bt2, scale, shift);

    finalpool_kernel<<<BATCH*SPTS, 256>>>(gmax, gmin, scale, shift, new_points);
}

// round 8
// speedup vs baseline: 1.9480x; 1.2078x over previous
#include <cuda_runtime.h>
#include <cuda_bf16.h>
#include <math.h>
#include <stdint.h>

// ---------------- problem constants ----------------
#define BATCH 16
#define NPTS  4096
#define DFEAT 64
#define SPTS  1024
#define NSAMP 32
#define CH0   67
#define CH1   64
#define CH2   128
#define CH3   256
#define MTOT  (BATCH*SPTS*NSAMP)   // 524288
#define MBLK  (MTOT/128)           // 4096
#define RAD2  0.04f
#define BNEPS 1e-5f

typedef unsigned long long ull;

// ---------------- device scratch ----------------
__device__ uint32_t g_y1[(size_t)MTOT*CH1];   // packed bf16 hi|lo
__device__ uint32_t g_y2[(size_t)MTOT*CH2];   // packed bf16 hi|lo
__device__ int   g_gidx[BATCH*SPTS*NSAMP];
__device__ float g_part[2*(size_t)MBLK*CH3];
__device__ float g_scale[CH3];
__device__ float g_shift[CH3];
__device__ float g_gmax[(size_t)BATCH*SPTS*CH3];
__device__ float g_gmin[(size_t)BATCH*SPTS*CH3];
// weights prepped k-major [KPAD][N], bf16 hi/lo
__device__ __nv_bfloat16 g_bh0[80*64],   g_bl0[80*64];
__device__ __nv_bfloat16 g_bh1[64*128],  g_bl1[64*128];
__device__ __nv_bfloat16 g_bh2[128*256], g_bl2[128*256];

// ---------------- helpers ----------------
__device__ __forceinline__ uint32_t smem_u32(const void* p) {
    uint32_t a;
    asm("{ .reg .u64 t; cvta.to.shared.u64 t, %1; cvt.u32.u64 %0, t; }" : "=r"(a) : "l"(p));
    return a;
}
__device__ __forceinline__ void ldsm4(uint32_t* r, uint32_t a) {
    asm volatile("ldmatrix.sync.aligned.m8n8.x4.shared.b16 {%0,%1,%2,%3}, [%4];"
                 : "=r"(r[0]), "=r"(r[1]), "=r"(r[2]), "=r"(r[3]) : "r"(a));
}
__device__ __forceinline__ void ldsm4t(uint32_t* r, uint32_t a) {
    asm volatile("ldmatrix.sync.aligned.m8n8.x4.trans.shared.b16 {%0,%1,%2,%3}, [%4];"
                 : "=r"(r[0]), "=r"(r[1]), "=r"(r[2]), "=r"(r[3]) : "r"(a));
}
__device__ __forceinline__ void mma_bf16(float* c, const uint32_t* a, uint32_t b0, uint32_t b1) {
    asm volatile(
        "mma.sync.aligned.m16n8k16.row.col.f32.bf16.bf16.f32 "
        "{%0,%1,%2,%3}, {%4,%5,%6,%7}, {%8,%9}, {%0,%1,%2,%3};"
        : "+f"(c[0]), "+f"(c[1]), "+f"(c[2]), "+f"(c[3])
        : "r"(a[0]), "r"(a[1]), "r"(a[2]), "r"(a[3]), "r"(b0), "r"(b1));
}
__device__ __forceinline__ uint32_t packsplit(float v) {
    __nv_bfloat16 h = __float2bfloat16(v);
    float rl = v - __bfloat162float(h);
    __nv_bfloat16 l = __float2bfloat16(rl);
    return ((uint32_t)__bfloat16_as_ushort(h) << 16) | (uint32_t)__bfloat16_as_ushort(l);
}

// ---------------- FPS v6: packed distances + REDUX-only cross-warp tail ----------------
__global__ __launch_bounds__(512) void fps_kernel(const float* __restrict__ xyz,
                                                  float* __restrict__ new_xyz)
{
    __shared__ float sx[NPTS], sy[NPTS], sz[NPTS];
    __shared__ unsigned s_val[2][16], s_low[2][16];
    const int b = blockIdx.x, tid = threadIdx.x;
    const int lane = tid & 31, wid = tid >> 5;
    const float* X = xyz + (size_t)b * NPTS * 3;

    ull pxp[4], pyp[4], pzp[4];
    float dist[8];
#pragma unroll
    for (int t = 0; t < 8; t++) dist[t] = 1e10f;
#pragma unroll
    for (int t = 0; t < 4; t++) {
        const int j0 = tid + (2*t) * 512, j1 = tid + (2*t+1) * 512;
        float x0 = X[3*j0], y0 = X[3*j0+1], z0 = X[3*j0+2];
        float x1 = X[3*j1], y1 = X[3*j1+1], z1 = X[3*j1+2];
        sx[j0] = x0; sy[j0] = y0; sz[j0] = z0;
        sx[j1] = x1; sy[j1] = y1; sz[j1] = z1;
        asm("mov.b64 %0, {%1,%2};" : "=l"(pxp[t]) : "f"(x0), "f"(x1));
        asm("mov.b64 %0, {%1,%2};" : "=l"(pyp[t]) : "f"(y0), "f"(y1));
        asm("mov.b64 %0, {%1,%2};" : "=l"(pzp[t]) : "f"(z0), "f"(z1));
    }
    __syncthreads();

    int far = 0;
    for (int i = 0; i < SPTS; i++) {
        const float cx = sx[far], cy = sy[far], cz = sz[far];
        if (tid == 0) {
            float* o = new_xyz + ((size_t)b * SPTS + i) * 3;
            o[0] = cx; o[1] = cy; o[2] = cz;
        }
        if (i == SPTS - 1) break;

        const float mx = -cx, my = -cy, mz = -cz;
        ull ncx, ncy, ncz;
        asm("mov.b64 %0, {%1,%1};" : "=l"(ncx) : "f"(mx));
        asm("mov.b64 %0, {%1,%1};" : "=l"(ncy) : "f"(my));
        asm("mov.b64 %0, {%1,%1};" : "=l"(ncz) : "f"(mz));

        float bv = -1.0f; int bi = 0;
#pragma unroll
        for (int t = 0; t < 4; t++) {
            ull dx, dy, dz, dd;
            asm("add.rn.f32x2 %0, %1, %2;" : "=l"(dx) : "l"(pxp[t]), "l"(ncx));
            asm("add.rn.f32x2 %0, %1, %2;" : "=l"(dy) : "l"(pyp[t]), "l"(ncy));
            asm("add.rn.f32x2 %0, %1, %2;" : "=l"(dz) : "l"(pzp[t]), "l"(ncz));
            asm("mul.rn.f32x2 %0, %1, %2;" : "=l"(dd) : "l"(dx), "l"(dx));
            asm("fma.rn.f32x2 %0, %1, %2, %3;" : "=l"(dd) : "l"(dy), "l"(dy), "l"(dd));
            asm("fma.rn.f32x2 %0, %1, %2, %3;" : "=l"(dd) : "l"(dz), "l"(dz), "l"(dd));
            float d0, d1;
            asm("mov.b64 {%0,%1}, %2;" : "=f"(d0), "=f"(d1) : "l"(dd));
            const float nd0 = fminf(dist[2*t],   d0);
            const float nd1 = fminf(dist[2*t+1], d1);
            dist[2*t]   = nd0;
            dist[2*t+1] = nd1;
            // strict > keeps first (lowest-index) max; t ascending => idx ascending
            if (nd0 > bv) { bv = nd0; bi = tid + (2*t)   * 512; }
            if (nd1 > bv) { bv = nd1; bi = tid + (2*t+1) * 512; }
        }
        const unsigned vb = __float_as_uint(bv);        // bv >= 0 => order-preserving bits
        const unsigned m  = __reduce_max_sync(0xffffffffu, vb);
        const unsigned lw = __reduce_max_sync(0xffffffffu,
                                              (vb == m) ? (0xFFFFu - (unsigned)bi) : 0u);
        const int buf = i & 1;
        if (lane == 0) { s_val[buf][wid] = m; s_low[buf][wid] = lw; }
        __syncthreads();

        const unsigned v2 = s_val[buf][lane & 15];
        const unsigned l2 = s_low[buf][lane & 15];
        const unsigned M  = __reduce_max_sync(0xffffffffu, v2);
        const unsigned LW = __reduce_max_sync(0xffffffffu, (v2 == M) ? l2 : 0u);
        far = 0xFFFF - (int)LW;
    }
}

// ---------------- ball query ----------------
__global__ __launch_bounds__(256) void ballquery_kernel(const float* __restrict__ xyz,
                                                        const float* __restrict__ new_xyz,
                                                        int* __restrict__ gidx)
{
    const int w    = blockIdx.x * 8 + (threadIdx.x >> 5);
    const int lane = threadIdx.x & 31;
    const int b    = w >> 10;
    const float* X = xyz + (size_t)b * NPTS * 3;

    const float cx = new_xyz[(size_t)w*3+0];
    const float cy = new_xyz[(size_t)w*3+1];
    const float cz = new_xyz[(size_t)w*3+2];
    const float ss = cx*cx + cy*cy + cz*cz;

    int cnt = 0, firstIdx = 0;
    int* out = gidx + (size_t)w * NSAMP;

    for (int base = 0; base < NPTS && cnt < NSAMP; base += 32) {
        const int j = base + lane;
        const float x = X[3*j], y = X[3*j+1], z = X[3*j+2];
        const float pp  = x*x + y*y + z*z;
        const float dot = x*cx + y*cy + z*cz;
        const float d   = (-2.0f*dot + ss) + pp;
        const bool  in  = !(d > RAD2);
        unsigned mask = __ballot_sync(0xffffffffu, in);
        if (cnt == 0 && mask) firstIdx = base + (__ffs(mask) - 1);
        int rank = __popc(mask & ((1u << lane) - 1u));
        int slot = cnt + rank;
        if (in && slot < NSAMP) out[slot] = j;
        cnt += __popc(mask);
    }
    for (int t = cnt + lane; t < NSAMP; t += 32) out[t] = firstIdx;
}

// ---------------- weight prep: W[K][N] f32 -> [KPAD][N] bf16 hi/lo (k-major) ----------------
__global__ __launch_bounds__(256) void prep_kernel(const float* __restrict__ W, int K, int N,
                                                   int KPAD,
                                                   __nv_bfloat16* __restrict__ bh,
                                                   __nv_bfloat16* __restrict__ bl)
{
    int i = blockIdx.x * 256 + threadIdx.x;
    if (i >= N * KPAD) return;
    int k = i / N, n = i - k * N;
    float v = (k < K) ? W[(size_t)k * N + n] : 0.f;
    __nv_bfloat16 h = __float2bfloat16(v);
    bh[i] = h;
    bl[i] = __float2bfloat16(v - __bfloat162float(h));
}

// ---------------- HMMA GEMM (bf16 split-3, K-chunked staging) ----------------
// AMODE: 0 = gather from xyz/points (layer 1), 1 = packed bf16 hi|lo u32 input.
// K is staged in chunks of KC columns (smem sized for KC) so big-K layers fit 2 CTAs/SM.
template<int BN, int NTOT, int KPAD, int KC, int KORIG, int AMODE,
         bool TRANSFORM, bool STORE_Y, bool FUSED_MAX, int MINB>
__global__ void __launch_bounds__(256, MINB) gemm_mma(
    const uint32_t* __restrict__ A,
    const int* __restrict__ gidxp, const float* __restrict__ xyzp,
    const float* __restrict__ pointsp, const float* __restrict__ nxyz,
    const __nv_bfloat16* __restrict__ BH, const __nv_bfloat16* __restrict__ BL,
    const float* __restrict__ bias,
    const float* __restrict__ scale, const float* __restrict__ shift,
    uint32_t* __restrict__ Y,
    float* __restrict__ partSum, float* __restrict__ partSq,
    float* __restrict__ gmax, float* __restrict__ gmin)
{
    extern __shared__ __align__(16) char dyn[];
    __shared__ int   sIdx[128];
    __shared__ float sCen[12];
    constexpr int LDA = KC + 8;     // bf16 units
    constexpr int LDB = BN + 8;
    constexpr int NCHUNK = KPAD / KC;
    __nv_bfloat16* aHi = (__nv_bfloat16*)dyn;
    __nv_bfloat16* aLo = aHi + 128 * LDA;
    __nv_bfloat16* bHi = aLo + 128 * LDA;
    __nv_bfloat16* bLo = bHi + KC * LDB;

    const int tid = threadIdx.x;
    const int nb = blockIdx.x, mb = blockIdx.y;
    const int m0 = mb * 128, n0 = nb * BN;

    if (AMODE == 0) {
        if (tid < 128) sIdx[tid] = gidxp[m0 + tid];
        if (tid < 12)  sCen[tid] = nxyz[(size_t)(mb * 4) * 3 + tid];
        __syncthreads();
    }

    const int wid = tid >> 5, lane = tid & 31;
    const int wm = wid >> 1, wn = wid & 1;
    const int mW = wm * 32, nW = wn * (BN / 2);
    constexpr int NT = BN / 16;
    constexpr int KSTEPS_C = KC / 16;

    float acc[2][NT][4];
#pragma unroll
    for (int i = 0; i < 2; i++)
#pragma unroll
        for (int j = 0; j < NT; j++)
#pragma unroll
            for (int q = 0; q < 4; q++) acc[i][j][q] = 0.f;

    const uint32_t aHiU = smem_u32(aHi) + (uint32_t)(mW + (lane & 15)) * (LDA * 2) + (lane >> 4) * 16;
    const uint32_t aLoU = smem_u32(aLo) + (uint32_t)(mW + (lane & 15)) * (LDA * 2) + (lane >> 4) * 16;
    const uint32_t bHiU = smem_u32(bHi) + (uint32_t)(lane & 15) * (LDB * 2) + (uint32_t)nW * 2 + (lane >> 4) * 16;
    const uint32_t bLoU = smem_u32(bLo) + (uint32_t)(lane & 15) * (LDB * 2) + (uint32_t)nW * 2 + (lane >> 4) * 16;

    const int bb = m0 >> 15;
    const float* Xb = xyzp    ? xyzp    + (size_t)bb * NPTS * 3     : nullptr;
    const float* Pb = pointsp ? pointsp + (size_t)bb * NPTS * DFEAT : nullptr;

    for (int ch = 0; ch < NCHUNK; ch++) {
        const int kbase = ch * KC;
        if (ch > 0) __syncthreads();

        // ---- stage A chunk -> bf16 hi/lo ----
        constexpr int AIT = 128 * (KC / 2);
        for (int idx = tid; idx < AIT; idx += 256) {
            const int r  = idx / (KC / 2);
            const int p  = idx - r * (KC / 2);
            const int kl = 2 * p;
            const int kk = kbase + kl;
            float v0 = 0.f, v1 = 0.f;
            if (AMODE == 0) {
                const int j = sIdx[r];
                const int grp = (r >> 5) * 3;
                if (kk < 3)        v0 = Xb[j*3 + kk] - sCen[grp + kk];
                else if (kk < CH0) v0 = Pb[(size_t)j * DFEAT + kk - 3];
                const int c1 = kk + 1;
                if (c1 < 3)        v1 = Xb[j*3 + c1] - sCen[grp + c1];
                else if (c1 < CH0) v1 = Pb[(size_t)j * DFEAT + c1 - 3];
            } else {
                const uint2 w = *(const uint2*)(A + (size_t)(m0 + r) * KORIG + kk);
                v0 = __uint_as_float(w.x & 0xFFFF0000u) + __uint_as_float(w.x << 16);
                v1 = __uint_as_float(w.y & 0xFFFF0000u) + __uint_as_float(w.y << 16);
                if (TRANSFORM) {
                    v0 = fmaxf(fmaf(v0, __ldg(scale + kk),     __ldg(shift + kk)),     0.f);
                    v1 = fmaxf(fmaf(v1, __ldg(scale + kk + 1), __ldg(shift + kk + 1)), 0.f);
                }
            }
            __nv_bfloat16 h0 = __float2bfloat16(v0), h1 = __float2bfloat16(v1);
            __nv_bfloat16 l0 = __float2bfloat16(v0 - __bfloat162float(h0));
            __nv_bfloat16 l1 = __float2bfloat16(v1 - __bfloat162float(h1));
            *(__nv_bfloat162*)(aHi + r * LDA + kl) = __halves2bfloat162(h0, h1);
            *(__nv_bfloat162*)(aLo + r * LDA + kl) = __halves2bfloat162(l0, l1);
        }
        // ---- stage B chunk ----
        constexpr int BIT = KC * (BN / 2);
        for (int idx = tid; idx < BIT; idx += 256) {
            const int k = idx / (BN / 2);
            const int n = 2 * (idx - k * (BN / 2));
            *(uint32_t*)(bHi + k * LDB + n) = *(const uint32_t*)(BH + (size_t)(kbase + k) * NTOT + n0 + n);
            *(uint32_t*)(bLo + k * LDB + n) = *(const uint32_t*)(BL + (size_t)(kbase + k) * NTOT + n0 + n);
        }
        __syncthreads();

        // ---- compute chunk ----
#pragma unroll
        for (int ks = 0; ks < KSTEPS_C; ks++) {
            uint32_t ah[2][4], al[2][4];
            ldsm4(ah[0], aHiU + ks * 32);
            ldsm4(ah[1], aHiU + 16 * LDA * 2 + ks * 32);
            ldsm4(al[0], aLoU + ks * 32);
            ldsm4(al[1], aLoU + 16 * LDA * 2 + ks * 32);
#pragma unroll
            for (int ng = 0; ng < NT / 2; ng++) {
                uint32_t bh[4], bl[4];
                const uint32_t bo = (uint32_t)ks * (16 * LDB * 2) + ng * 32;
                ldsm4t(bh, bHiU + bo);
                ldsm4t(bl, bLoU + bo);
#pragma unroll
                for (int mt = 0; mt < 2; mt++) {
                    mma_bf16(acc[mt][ng*2+0], ah[mt], bh[0], bh[1]);
                    mma_bf16(acc[mt][ng*2+0], ah[mt], bl[0], bl[1]);
                    mma_bf16(acc[mt][ng*2+0], al[mt], bh[0], bh[1]);
                    mma_bf16(acc[mt][ng*2+1], ah[mt], bh[2], bh[3]);
                    mma_bf16(acc[mt][ng*2+1], ah[mt], bl[2], bl[3]);
                    mma_bf16(acc[mt][ng*2+1], al[mt], bh[2], bh[3]);
                }
            }
        }
    }
    __syncthreads();   // done with staged tiles; reuse smem for reductions

    // ---- epilogue: bias, optional packed-Y store, BN partials, optional group min/max ----
    float* sSum = (float*)dyn;            // [4][BN]
    float* sSq  = sSum + 4 * BN;          // [4][BN]

    const int r0 = lane >> 2;             // 0..7
#pragma unroll
    for (int nt = 0; nt < NT; nt++) {
        const int colLocal = nW + nt * 8 + (lane & 3) * 2;
        const float b0 = __ldg(bias + n0 + colLocal);
        const float b1 = __ldg(bias + n0 + colLocal + 1);
        float v0 = acc[0][nt][0] + b0, v1 = acc[0][nt][1] + b1;
        float v2 = acc[0][nt][2] + b0, v3 = acc[0][nt][3] + b1;
        float v4 = acc[1][nt][0] + b0, v5 = acc[1][nt][1] + b1;
        float v6 = acc[1][nt][2] + b0, v7 = acc[1][nt][3] + b1;
        if (STORE_Y) {
            const size_t base = (size_t)(m0 + mW + r0) * NTOT + n0 + colLocal;
            *(uint2*)(Y + base)           = make_uint2(packsplit(v0), packsplit(v1));
            *(uint2*)(Y + base +  8*NTOT) = make_uint2(packsplit(v2), packsplit(v3));
            *(uint2*)(Y + base + 16*NTOT) = make_uint2(packsplit(v4), packsplit(v5));
            *(uint2*)(Y + base + 24*NTOT) = make_uint2(packsplit(v6), packsplit(v7));
        }
        float s0 = v0+v2+v4+v6,              s1 = v1+v3+v5+v7;
        float q0 = v0*v0+v2*v2+v4*v4+v6*v6,  q1 = v1*v1+v3*v3+v5*v5+v7*v7;
        float mx0 = fmaxf(fmaxf(v0,v2), fmaxf(v4,v6)), mx1 = fmaxf(fmaxf(v1,v3), fmaxf(v5,v7));
        float mn0 = fminf(fminf(v0,v2), fminf(v4,v6)), mn1 = fminf(fminf(v1,v3), fminf(v5,v7));
#pragma unroll
        for (int d = 4; d < 32; d <<= 1) {
            s0 += __shfl_xor_sync(0xffffffffu, s0, d);
            s1 += __shfl_xor_sync(0xffffffffu, s1, d);
            q0 += __shfl_xor_sync(0xffffffffu, q0, d);
            q1 += __shfl_xor_sync(0xffffffffu, q1, d);
            mx0 = fmaxf(mx0, __shfl_xor_sync(0xffffffffu, mx0, d));
            mx1 = fmaxf(mx1, __shfl_xor_sync(0xffffffffu, mx1, d));
            mn0 = fminf(mn0, __shfl_xor_sync(0xffffffffu, mn0, d));
            mn1 = fminf(mn1, __shfl_xor_sync(0xffffffffu, mn1, d));
        }
        if (lane < 4) {
            sSum[wm*BN + colLocal] = s0;  sSum[wm*BN + colLocal + 1] = s1;
            sSq [wm*BN + colLocal] = q0;  sSq [wm*BN + colLocal + 1] = q1;
            if (FUSED_MAX) {
                const size_t grp = (size_t)(mb * 4 + wm) * CH3 + n0 + colLocal;
                gmax[grp]     = mx0;  gmax[grp + 1] = mx1;
                gmin[grp]     = mn0;  gmin[grp + 1] = mn1;
            }
        }
    }
    __syncthreads();
    for (int n = tid; n < BN; n += 256) {
        float s = sSum[n] + sSum[BN + n] + sSum[2*BN + n] + sSum[3*BN + n];
        float q = sSq [n] + sSq [BN + n] + sSq [2*BN + n] + sSq [3*BN + n];
        partSum[(size_t)mb * NTOT + n0 + n] = s;
        partSq [(size_t)mb * NTOT + n0 + n] = q;
    }
}

// ---------------- fold partials -> scale/shift ----------------
__global__ __launch_bounds__(256) void stats_kernel(const float* __restrict__ partSum,
                                                    const float* __restrict__ partSq,
                                                    int N,
                                                    const float* __restrict__ g,
                                                    const float* __restrict__ bt,
                                                    float* __restrict__ scale,
                                                    float* __restrict__ shift)
{
    const int c = blockIdx.x, tid = threadIdx.x;
    __shared__ float ss[256], sq[256];
    float a = 0.f, b2 = 0.f;
    for (int mb = tid; mb < MBLK; mb += 256) {
        a  += partSum[(size_t)mb * N + c];
        b2 += partSq [(size_t)mb * N + c];
    }
    ss[tid] = a; sq[tid] = b2;
    __syncthreads();
    for (int s = 128; s > 0; s >>= 1) {
        if (tid < s) { ss[tid] += ss[tid+s]; sq[tid] += sq[tid+s]; }
        __syncthreads();
    }
    if (tid == 0) {
        const float invM = 1.0f / (float)MTOT;
        float mean = ss[0] * invM;
        float var  = sq[0] * invM - mean * mean;
        float sc   = g[c] / sqrtf(var + BNEPS);
        scale[c] = sc;
        shift[c] = bt[c] - mean * sc;
    }
}

// ---------------- final: pick max/min by sign(scale), affine+relu ----------------
__global__ __launch_bounds__(256) void finalpool_kernel(const float* __restrict__ gmax,
                                                        const float* __restrict__ gmin,
                                                        const float* __restrict__ scale,
                                                        const float* __restrict__ shift,
                                                        float* __restrict__ out)
{
    const int g = blockIdx.x, c = threadIdx.x;
    const float sc = scale[c], sh = shift[c];
    const float v = (sc >= 0.f) ? gmax[(size_t)g * CH3 + c] : gmin[(size_t)g * CH3 + c];
    out[(size_t)g * CH3 + c] = fmaxf(fmaf(v, sc, sh), 0.f);
}

// ---------------- launch ----------------
extern "C" void kernel_launch(void* const* d_in, const int* in_sizes, int n_in,
                              void* d_out, int out_size)
{
    const float* xyz    = (const float*)d_in[0];
    const float* points = (const float*)d_in[1];
    const float* w0  = (const float*)d_in[2];
    const float* b0  = (const float*)d_in[3];
    const float* g0  = (const float*)d_in[4];
    const float* bt0 = (const float*)d_in[5];
    const float* w1  = (const float*)d_in[6];
    const float* b1  = (const float*)d_in[7];
    const float* g1  = (const float*)d_in[8];
    const float* bt1 = (const float*)d_in[9];
    const float* w2  = (const float*)d_in[10];
    const float* b2  = (const float*)d_in[11];
    const float* g2  = (const float*)d_in[12];
    const float* bt2 = (const float*)d_in[13];

    float* out        = (float*)d_out;
    float* new_xyz    = out;
    float* new_points = out + (size_t)BATCH*SPTS*3;

    float *part, *scale, *shift, *gmax, *gmin;
    uint32_t *y1, *y2;
    int* gidx;
    __nv_bfloat16 *bh0, *bl0, *bh1, *bl1, *bh2, *bl2;
    cudaGetSymbolAddress((void**)&y1,    g_y1);
    cudaGetSymbolAddress((void**)&y2,    g_y2);
    cudaGetSymbolAddress((void**)&part,  g_part);
    cudaGetSymbolAddress((void**)&scale, g_scale);
    cudaGetSymbolAddress((void**)&shift, g_shift);
    cudaGetSymbolAddress((void**)&gidx,  g_gidx);
    cudaGetSymbolAddress((void**)&gmax,  g_gmax);
    cudaGetSymbolAddress((void**)&gmin,  g_gmin);
    cudaGetSymbolAddress((void**)&bh0,   g_bh0);
    cudaGetSymbolAddress((void**)&bl0,   g_bl0);
    cudaGetSymbolAddress((void**)&bh1,   g_bh1);
    cudaGetSymbolAddress((void**)&bl1,   g_bl1);
    cudaGetSymbolAddress((void**)&bh2,   g_bh2);
    cudaGetSymbolAddress((void**)&bl2,   g_bl2);

    float* partSum = part;
    float* partSq  = part + (size_t)MBLK * CH3;

    // smem bytes: 2*(2*128*(KC+8) + 2*KC*(BN+8))
    constexpr int SM1 = (2*128*(80+8) + 2*80*(64+8))  * 2;  //  68,096
    constexpr int SM2 = (2*128*(64+8) + 2*64*(128+8)) * 2;  //  71,680
    constexpr int SM3 = (2*128*(64+8) + 2*64*(128+8)) * 2;  //  71,680 (KC=64 chunked)

    static bool attrDone = false;
    if (!attrDone) {
        cudaFuncSetAttribute(gemm_mma<64, 64, 80, 80, 67, 0, false, true, false, 2>,
                             cudaFuncAttributeMaxDynamicSharedMemorySize, SM1);
        cudaFuncSetAttribute(gemm_mma<128, 128, 64, 64, 64, 1, true, true, false, 2>,
                             cudaFuncAttributeMaxDynamicSharedMemorySize, SM2);
        cudaFuncSetAttribute(gemm_mma<128, 256, 128, 64, 128, 1, true, false, true, 2>,
                             cudaFuncAttributeMaxDynamicSharedMemorySize, SM3);
        attrDone = true;
    }

    prep_kernel<<<(80*64 + 255)/256, 256>>>(w0, CH0, CH1, 80, bh0, bl0);
    prep_kernel<<<(64*128 + 255)/256, 256>>>(w1, CH1, CH2, 64, bh1, bl1);
    prep_kernel<<<(128*256 + 255)/256, 256>>>(w2, CH2, CH3, 128, bh2, bl2);

    fps_kernel<<<BATCH, 512>>>(xyz, new_xyz);
    ballquery_kernel<<<BATCH*SPTS/8, 256>>>(xyz, new_xyz, gidx);

    // layer 1: 67 -> 64, gather fused into A-stage (no x0 buffer)
    gemm_mma<64, 64, 80, 80, 67, 0, false, true, false, 2><<<dim3(1, MBLK), 256, SM1>>>(
        nullptr, gidx, xyz, points, new_xyz,
        bh0, bl0, b0, nullptr, nullptr, y1, partSum, partSq, nullptr, nullptr);
    stats_kernel<<<CH1, 256>>>(partSum, partSq, CH1, g0, bt0, scale, shift);

    // layer 2: 64 -> 128 (consumes packed y1)
    gemm_mma<128, 128, 64, 64, 64, 1, true, true, false, 2><<<dim3(1, MBLK), 256, SM2>>>(
        y1, nullptr, nullptr, nullptr, nullptr,
        bh1, bl1, b1, scale, shift, y2, partSum, partSq, nullptr, nullptr);
    stats_kernel<<<CH2, 256>>>(partSum, partSq, CH2, g1, bt1, scale, shift);

    // layer 3: 128 -> 256, K chunked (KC=64) -> 2 CTAs/SM; fused per-group min/max
    gemm_mma<128, 256, 128, 64, 128, 1, true, false, true, 2><<<dim3(2, MBLK), 256, SM3>>>(
        y2, nullptr, nullptr, nullptr, nullptr,
        bh2, bl2, b2, scale, shift, nullptr, partSum, partSq, gmax, gmin);
    stats_kernel<<<CH3, 256>>>(partSum, partSq, CH3, g2, bt2, scale, shift);

    finalpool_kernel<<<BATCH*SPTS, 256>>>(gmax, gmin, scale, shift, new_points);
}

// round 9
// speedup vs baseline: 1.9747x; 1.0137x over previous
#include <cuda_runtime.h>
#include <cuda_bf16.h>
#include <math.h>
#include <stdint.h>

// ---------------- problem constants ----------------
#define BATCH 16
#define NPTS  4096
#define DFEAT 64
#define SPTS  1024
#define NSAMP 32
#define CH0   67
#define CH1   64
#define CH2   128
#define CH3   256
#define MTOT  (BATCH*SPTS*NSAMP)   // 524288
#define MBLK  (MTOT/128)           // 4096
#define RAD2  0.04f
#define BNEPS 1e-5f

typedef unsigned long long ull;

// ---------------- device scratch ----------------
__device__ uint32_t g_y1[(size_t)MTOT*CH1];   // packed bf16 hi|lo
__device__ uint32_t g_y2[(size_t)MTOT*CH2];   // packed bf16 hi|lo
__device__ int   g_gidx[BATCH*SPTS*NSAMP];
__device__ float g_part[2*(size_t)MBLK*CH3];
__device__ float g_scale[CH3];
__device__ float g_shift[CH3];
__device__ float g_gmax[(size_t)BATCH*SPTS*CH3];
__device__ float g_gmin[(size_t)BATCH*SPTS*CH3];
// weights prepped k-major [KPAD][N], bf16 hi/lo
__device__ __nv_bfloat16 g_bh0[80*64],   g_bl0[80*64];
__device__ __nv_bfloat16 g_bh1[64*128],  g_bl1[64*128];
__device__ __nv_bfloat16 g_bh2[128*256], g_bl2[128*256];

// ---------------- helpers ----------------
__device__ __forceinline__ uint32_t smem_u32(const void* p) {
    uint32_t a;
    asm("{ .reg .u64 t; cvta.to.shared.u64 t, %1; cvt.u32.u64 %0, t; }" : "=r"(a) : "l"(p));
    return a;
}
__device__ __forceinline__ void ldsm4(uint32_t* r, uint32_t a) {
    asm volatile("ldmatrix.sync.aligned.m8n8.x4.shared.b16 {%0,%1,%2,%3}, [%4];"
                 : "=r"(r[0]), "=r"(r[1]), "=r"(r[2]), "=r"(r[3]) : "r"(a));
}
__device__ __forceinline__ void ldsm4t(uint32_t* r, uint32_t a) {
    asm volatile("ldmatrix.sync.aligned.m8n8.x4.trans.shared.b16 {%0,%1,%2,%3}, [%4];"
                 : "=r"(r[0]), "=r"(r[1]), "=r"(r[2]), "=r"(r[3]) : "r"(a));
}
__device__ __forceinline__ void mma_bf16(float* c, const uint32_t* a, uint32_t b0, uint32_t b1) {
    asm volatile(
        "mma.sync.aligned.m16n8k16.row.col.f32.bf16.bf16.f32 "
        "{%0,%1,%2,%3}, {%4,%5,%6,%7}, {%8,%9}, {%0,%1,%2,%3};"
        : "+f"(c[0]), "+f"(c[1]), "+f"(c[2]), "+f"(c[3])
        : "r"(a[0]), "r"(a[1]), "r"(a[2]), "r"(a[3]), "r"(b0), "r"(b1));
}
__device__ __forceinline__ uint32_t packsplit(float v) {
    __nv_bfloat16 h = __float2bfloat16(v);
    float rl = v - __bfloat162float(h);
    __nv_bfloat16 l = __float2bfloat16(rl);
    return ((uint32_t)__bfloat16_as_ushort(h) << 16) | (uint32_t)__bfloat16_as_ushort(l);
}

// ---------------- FPS v6: packed distances + REDUX-only cross-warp tail ----------------
__global__ __launch_bounds__(512) void fps_kernel(const float* __restrict__ xyz,
                                                  float* __restrict__ new_xyz)
{
    __shared__ float sx[NPTS], sy[NPTS], sz[NPTS];
    __shared__ unsigned s_val[2][16], s_low[2][16];
    const int b = blockIdx.x, tid = threadIdx.x;
    const int lane = tid & 31, wid = tid >> 5;
    const float* X = xyz + (size_t)b * NPTS * 3;

    ull pxp[4], pyp[4], pzp[4];
    float dist[8];
#pragma unroll
    for (int t = 0; t < 8; t++) dist[t] = 1e10f;
#pragma unroll
    for (int t = 0; t < 4; t++) {
        const int j0 = tid + (2*t) * 512, j1 = tid + (2*t+1) * 512;
        float x0 = X[3*j0], y0 = X[3*j0+1], z0 = X[3*j0+2];
        float x1 = X[3*j1], y1 = X[3*j1+1], z1 = X[3*j1+2];
        sx[j0] = x0; sy[j0] = y0; sz[j0] = z0;
        sx[j1] = x1; sy[j1] = y1; sz[j1] = z1;
        asm("mov.b64 %0, {%1,%2};" : "=l"(pxp[t]) : "f"(x0), "f"(x1));
        asm("mov.b64 %0, {%1,%2};" : "=l"(pyp[t]) : "f"(y0), "f"(y1));
        asm("mov.b64 %0, {%1,%2};" : "=l"(pzp[t]) : "f"(z0), "f"(z1));
    }
    __syncthreads();

    int far = 0;
    for (int i = 0; i < SPTS; i++) {
        const float cx = sx[far], cy = sy[far], cz = sz[far];
        if (tid == 0) {
            float* o = new_xyz + ((size_t)b * SPTS + i) * 3;
            o[0] = cx; o[1] = cy; o[2] = cz;
        }
        if (i == SPTS - 1) break;

        const float mx = -cx, my = -cy, mz = -cz;
        ull ncx, ncy, ncz;
        asm("mov.b64 %0, {%1,%1};" : "=l"(ncx) : "f"(mx));
        asm("mov.b64 %0, {%1,%1};" : "=l"(ncy) : "f"(my));
        asm("mov.b64 %0, {%1,%1};" : "=l"(ncz) : "f"(mz));

        float bv = -1.0f; int bi = 0;
#pragma unroll
        for (int t = 0; t < 4; t++) {
            ull dx, dy, dz, dd;
            asm("add.rn.f32x2 %0, %1, %2;" : "=l"(dx) : "l"(pxp[t]), "l"(ncx));
            asm("add.rn.f32x2 %0, %1, %2;" : "=l"(dy) : "l"(pyp[t]), "l"(ncy));
            asm("add.rn.f32x2 %0, %1, %2;" : "=l"(dz) : "l"(pzp[t]), "l"(ncz));
            asm("mul.rn.f32x2 %0, %1, %2;" : "=l"(dd) : "l"(dx), "l"(dx));
            asm("fma.rn.f32x2 %0, %1, %2, %3;" : "=l"(dd) : "l"(dy), "l"(dy), "l"(dd));
            asm("fma.rn.f32x2 %0, %1, %2, %3;" : "=l"(dd) : "l"(dz), "l"(dz), "l"(dd));
            float d0, d1;
            asm("mov.b64 {%0,%1}, %2;" : "=f"(d0), "=f"(d1) : "l"(dd));
            const float nd0 = fminf(dist[2*t],   d0);
            const float nd1 = fminf(dist[2*t+1], d1);
            dist[2*t]   = nd0;
            dist[2*t+1] = nd1;
            // strict > keeps first (lowest-index) max; t ascending => idx ascending
            if (nd0 > bv) { bv = nd0; bi = tid + (2*t)   * 512; }
            if (nd1 > bv) { bv = nd1; bi = tid + (2*t+1) * 512; }
        }
        const unsigned vb = __float_as_uint(bv);        // bv >= 0 => order-preserving bits
        const unsigned m  = __reduce_max_sync(0xffffffffu, vb);
        const unsigned lw = __reduce_max_sync(0xffffffffu,
                                              (vb == m) ? (0xFFFFu - (unsigned)bi) : 0u);
        const int buf = i & 1;
        if (lane == 0) { s_val[buf][wid] = m; s_low[buf][wid] = lw; }
        __syncthreads();

        const unsigned v2 = s_val[buf][lane & 15];
        const unsigned l2 = s_low[buf][lane & 15];
        const unsigned M  = __reduce_max_sync(0xffffffffu, v2);
        const unsigned LW = __reduce_max_sync(0xffffffffu, (v2 == M) ? l2 : 0u);
        far = 0xFFFF - (int)LW;
    }
}

// ---------------- ball query ----------------
__global__ __launch_bounds__(256) void ballquery_kernel(const float* __restrict__ xyz,
                                                        const float* __restrict__ new_xyz,
                                                        int* __restrict__ gidx)
{
    const int w    = blockIdx.x * 8 + (threadIdx.x >> 5);
    const int lane = threadIdx.x & 31;
    const int b    = w >> 10;
    const float* X = xyz + (size_t)b * NPTS * 3;

    const float cx = new_xyz[(size_t)w*3+0];
    const float cy = new_xyz[(size_t)w*3+1];
    const float cz = new_xyz[(size_t)w*3+2];
    const float ss = cx*cx + cy*cy + cz*cz;

    int cnt = 0, firstIdx = 0;
    int* out = gidx + (size_t)w * NSAMP;

    for (int base = 0; base < NPTS && cnt < NSAMP; base += 32) {
        const int j = base + lane;
        const float x = X[3*j], y = X[3*j+1], z = X[3*j+2];
        const float pp  = x*x + y*y + z*z;
        const float dot = x*cx + y*cy + z*cz;
        const float d   = (-2.0f*dot + ss) + pp;
        const bool  in  = !(d > RAD2);
        unsigned mask = __ballot_sync(0xffffffffu, in);
        if (cnt == 0 && mask) firstIdx = base + (__ffs(mask) - 1);
        int rank = __popc(mask & ((1u << lane) - 1u));
        int slot = cnt + rank;
        if (in && slot < NSAMP) out[slot] = j;
        cnt += __popc(mask);
    }
    for (int t = cnt + lane; t < NSAMP; t += 32) out[t] = firstIdx;
}

// ---------------- weight prep: W[K][N] f32 -> [KPAD][N] bf16 hi/lo (k-major) ----------------
__global__ __launch_bounds__(256) void prep_kernel(const float* __restrict__ W, int K, int N,
                                                   int KPAD,
                                                   __nv_bfloat16* __restrict__ bh,
                                                   __nv_bfloat16* __restrict__ bl)
{
    int i = blockIdx.x * 256 + threadIdx.x;
    if (i >= N * KPAD) return;
    int k = i / N, n = i - k * N;
    float v = (k < K) ? W[(size_t)k * N + n] : 0.f;
    __nv_bfloat16 h = __float2bfloat16(v);
    bh[i] = h;
    bl[i] = __float2bfloat16(v - __bfloat162float(h));
}

// ---------------- HMMA GEMM (bf16 split-3, K-chunked staging), 256 threads ----------------
// AMODE: 0 = gather from xyz/points (layer 1), 1 = packed bf16 hi|lo u32 input.
template<int BN, int NTOT, int KPAD, int KC, int KORIG, int AMODE,
         bool TRANSFORM, bool STORE_Y, bool FUSED_MAX, int MINB>
__global__ void __launch_bounds__(256, MINB) gemm_mma(
    const uint32_t* __restrict__ A,
    const int* __restrict__ gidxp, const float* __restrict__ xyzp,
    const float* __restrict__ pointsp, const float* __restrict__ nxyz,
    const __nv_bfloat16* __restrict__ BH, const __nv_bfloat16* __restrict__ BL,
    const float* __restrict__ bias,
    const float* __restrict__ scale, const float* __restrict__ shift,
    uint32_t* __restrict__ Y,
    float* __restrict__ partSum, float* __restrict__ partSq,
    float* __restrict__ gmax, float* __restrict__ gmin)
{
    extern __shared__ __align__(16) char dyn[];
    __shared__ int   sIdx[128];
    __shared__ float sCen[12];
    constexpr int LDA = KC + 8;     // bf16 units
    constexpr int LDB = BN + 8;
    constexpr int NCHUNK = KPAD / KC;
    __nv_bfloat16* aHi = (__nv_bfloat16*)dyn;
    __nv_bfloat16* aLo = aHi + 128 * LDA;
    __nv_bfloat16* bHi = aLo + 128 * LDA;
    __nv_bfloat16* bLo = bHi + KC * LDB;

    const int tid = threadIdx.x;
    const int nb = blockIdx.x, mb = blockIdx.y;
    const int m0 = mb * 128, n0 = nb * BN;

    if (AMODE == 0) {
        if (tid < 128) sIdx[tid] = gidxp[m0 + tid];
        if (tid < 12)  sCen[tid] = nxyz[(size_t)(mb * 4) * 3 + tid];
        __syncthreads();
    }

    const int wid = tid >> 5, lane = tid & 31;
    const int wm = wid >> 1, wn = wid & 1;
    const int mW = wm * 32, nW = wn * (BN / 2);
    constexpr int NT = BN / 16;
    constexpr int KSTEPS_C = KC / 16;

    float acc[2][NT][4];
#pragma unroll
    for (int i = 0; i < 2; i++)
#pragma unroll
        for (int j = 0; j < NT; j++)
#pragma unroll
            for (int q = 0; q < 4; q++) acc[i][j][q] = 0.f;

    const uint32_t aHiU = smem_u32(aHi) + (uint32_t)(mW + (lane & 15)) * (LDA * 2) + (lane >> 4) * 16;
    const uint32_t aLoU = smem_u32(aLo) + (uint32_t)(mW + (lane & 15)) * (LDA * 2) + (lane >> 4) * 16;
    const uint32_t bHiU = smem_u32(bHi) + (uint32_t)(lane & 15) * (LDB * 2) + (uint32_t)nW * 2 + (lane >> 4) * 16;
    const uint32_t bLoU = smem_u32(bLo) + (uint32_t)(lane & 15) * (LDB * 2) + (uint32_t)nW * 2 + (lane >> 4) * 16;

    const int bb = m0 >> 15;
    const float* Xb = xyzp    ? xyzp    + (size_t)bb * NPTS * 3     : nullptr;
    const float* Pb = pointsp ? pointsp + (size_t)bb * NPTS * DFEAT : nullptr;

    for (int ch = 0; ch < NCHUNK; ch++) {
        const int kbase = ch * KC;
        if (ch > 0) __syncthreads();

        // ---- stage A chunk -> bf16 hi/lo ----
        constexpr int AIT = 128 * (KC / 2);
        for (int idx = tid; idx < AIT; idx += 256) {
            const int r  = idx / (KC / 2);
            const int p  = idx - r * (KC / 2);
            const int kl = 2 * p;
            const int kk = kbase + kl;
            float v0 = 0.f, v1 = 0.f;
            if (AMODE == 0) {
                const int j = sIdx[r];
                const int grp = (r >> 5) * 3;
                if (kk < 3)        v0 = Xb[j*3 + kk] - sCen[grp + kk];
                else if (kk < CH0) v0 = Pb[(size_t)j * DFEAT + kk - 3];
                const int c1 = kk + 1;
                if (c1 < 3)        v1 = Xb[j*3 + c1] - sCen[grp + c1];
                else if (c1 < CH0) v1 = Pb[(size_t)j * DFEAT + c1 - 3];
            } else {
                const uint2 w = *(const uint2*)(A + (size_t)(m0 + r) * KORIG + kk);
                v0 = __uint_as_float(w.x & 0xFFFF0000u) + __uint_as_float(w.x << 16);
                v1 = __uint_as_float(w.y & 0xFFFF0000u) + __uint_as_float(w.y << 16);
                if (TRANSFORM) {
                    v0 = fmaxf(fmaf(v0, __ldg(scale + kk),     __ldg(shift + kk)),     0.f);
                    v1 = fmaxf(fmaf(v1, __ldg(scale + kk + 1), __ldg(shift + kk + 1)), 0.f);
                }
            }
            __nv_bfloat16 h0 = __float2bfloat16(v0), h1 = __float2bfloat16(v1);
            __nv_bfloat16 l0 = __float2bfloat16(v0 - __bfloat162float(h0));
            __nv_bfloat16 l1 = __float2bfloat16(v1 - __bfloat162float(h1));
            *(__nv_bfloat162*)(aHi + r * LDA + kl) = __halves2bfloat162(h0, h1);
            *(__nv_bfloat162*)(aLo + r * LDA + kl) = __halves2bfloat162(l0, l1);
        }
        // ---- stage B chunk ----
        constexpr int BIT = KC * (BN / 2);
        for (int idx = tid; idx < BIT; idx += 256) {
            const int k = idx / (BN / 2);
            const int n = 2 * (idx - k * (BN / 2));
            *(uint32_t*)(bHi + k * LDB + n) = *(const uint32_t*)(BH + (size_t)(kbase + k) * NTOT + n0 + n);
            *(uint32_t*)(bLo + k * LDB + n) = *(const uint32_t*)(BL + (size_t)(kbase + k) * NTOT + n0 + n);
        }
        __syncthreads();

        // ---- compute chunk ----
#pragma unroll
        for (int ks = 0; ks < KSTEPS_C; ks++) {
            uint32_t ah[2][4], al[2][4];
            ldsm4(ah[0], aHiU + ks * 32);
            ldsm4(ah[1], aHiU + 16 * LDA * 2 + ks * 32);
            ldsm4(al[0], aLoU + ks * 32);
            ldsm4(al[1], aLoU + 16 * LDA * 2 + ks * 32);
#pragma unroll
            for (int ng = 0; ng < NT / 2; ng++) {
                uint32_t bh[4], bl[4];
                const uint32_t bo = (uint32_t)ks * (16 * LDB * 2) + ng * 32;
                ldsm4t(bh, bHiU + bo);
                ldsm4t(bl, bLoU + bo);
#pragma unroll
                for (int mt = 0; mt < 2; mt++) {
                    mma_bf16(acc[mt][ng*2+0], ah[mt], bh[0], bh[1]);
                    mma_bf16(acc[mt][ng*2+0], ah[mt], bl[0], bl[1]);
                    mma_bf16(acc[mt][ng*2+0], al[mt], bh[0], bh[1]);
                    mma_bf16(acc[mt][ng*2+1], ah[mt], bh[2], bh[3]);
                    mma_bf16(acc[mt][ng*2+1], ah[mt], bl[2], bl[3]);
                    mma_bf16(acc[mt][ng*2+1], al[mt], bh[2], bh[3]);
                }
            }
        }
    }
    __syncthreads();   // done with staged tiles; reuse smem for reductions

    // ---- epilogue ----
    float* sSum = (float*)dyn;            // [4][BN]
    float* sSq  = sSum + 4 * BN;          // [4][BN]

    const int r0 = lane >> 2;
#pragma unroll
    for (int nt = 0; nt < NT; nt++) {
        const int colLocal = nW + nt * 8 + (lane & 3) * 2;
        const float b0 = __ldg(bias + n0 + colLocal);
        const float b1 = __ldg(bias + n0 + colLocal + 1);
        float v0 = acc[0][nt][0] + b0, v1 = acc[0][nt][1] + b1;
        float v2 = acc[0][nt][2] + b0, v3 = acc[0][nt][3] + b1;
        float v4 = acc[1][nt][0] + b0, v5 = acc[1][nt][1] + b1;
        float v6 = acc[1][nt][2] + b0, v7 = acc[1][nt][3] + b1;
        if (STORE_Y) {
            const size_t base = (size_t)(m0 + mW + r0) * NTOT + n0 + colLocal;
            *(uint2*)(Y + base)           = make_uint2(packsplit(v0), packsplit(v1));
            *(uint2*)(Y + base +  8*NTOT) = make_uint2(packsplit(v2), packsplit(v3));
            *(uint2*)(Y + base + 16*NTOT) = make_uint2(packsplit(v4), packsplit(v5));
            *(uint2*)(Y + base + 24*NTOT) = make_uint2(packsplit(v6), packsplit(v7));
        }
        float s0 = v0+v2+v4+v6,              s1 = v1+v3+v5+v7;
        float q0 = v0*v0+v2*v2+v4*v4+v6*v6,  q1 = v1*v1+v3*v3+v5*v5+v7*v7;
        float mx0 = fmaxf(fmaxf(v0,v2), fmaxf(v4,v6)), mx1 = fmaxf(fmaxf(v1,v3), fmaxf(v5,v7));
        float mn0 = fminf(fminf(v0,v2), fminf(v4,v6)), mn1 = fminf(fminf(v1,v3), fminf(v5,v7));
#pragma unroll
        for (int d = 4; d < 32; d <<= 1) {
            s0 += __shfl_xor_sync(0xffffffffu, s0, d);
            s1 += __shfl_xor_sync(0xffffffffu, s1, d);
            q0 += __shfl_xor_sync(0xffffffffu, q0, d);
            q1 += __shfl_xor_sync(0xffffffffu, q1, d);
            mx0 = fmaxf(mx0, __shfl_xor_sync(0xffffffffu, mx0, d));
            mx1 = fmaxf(mx1, __shfl_xor_sync(0xffffffffu, mx1, d));
            mn0 = fminf(mn0, __shfl_xor_sync(0xffffffffu, mn0, d));
            mn1 = fminf(mn1, __shfl_xor_sync(0xffffffffu, mn1, d));
        }
        if (lane < 4) {
            sSum[wm*BN + colLocal] = s0;  sSum[wm*BN + colLocal + 1] = s1;
            sSq [wm*BN + colLocal] = q0;  sSq [wm*BN + colLocal + 1] = q1;
            if (FUSED_MAX) {
                const size_t grp = (size_t)(mb * 4 + wm) * CH3 + n0 + colLocal;
                gmax[grp]     = mx0;  gmax[grp + 1] = mx1;
                gmin[grp]     = mn0;  gmin[grp + 1] = mn1;
            }
        }
    }
    __syncthreads();
    for (int n = tid; n < BN; n += 256) {
        float s = sSum[n] + sSum[BN + n] + sSum[2*BN + n] + sSum[3*BN + n];
        float q = sSq [n] + sSq [BN + n] + sSq [2*BN + n] + sSq [3*BN + n];
        partSum[(size_t)mb * NTOT + n0 + n] = s;
        partSq [(size_t)mb * NTOT + n0 + n] = q;
    }
}

// ---------------- HMMA GEMM wide: 512 threads, BN=256 in ONE CTA (layer 3) ----------------
// A staged once per M-block; warps 4(m) x 4(n), warp tile 32x64.
template<int KPAD, int KC, int KORIG>
__global__ void __launch_bounds__(512, 1) gemm_mma_w3(
    const uint32_t* __restrict__ A,
    const __nv_bfloat16* __restrict__ BH, const __nv_bfloat16* __restrict__ BL,
    const float* __restrict__ bias,
    const float* __restrict__ scale, const float* __restrict__ shift,
    float* __restrict__ partSum, float* __restrict__ partSq,
    float* __restrict__ gmax, float* __restrict__ gmin)
{
    extern __shared__ __align__(16) char dyn[];
    constexpr int BN  = 256;
    constexpr int LDA = KC + 8;
    constexpr int LDB = BN + 8;
    constexpr int NCHUNK = KPAD / KC;
    __nv_bfloat16* aHi = (__nv_bfloat16*)dyn;
    __nv_bfloat16* aLo = aHi + 128 * LDA;
    __nv_bfloat16* bHi = aLo + 128 * LDA;
    __nv_bfloat16* bLo = bHi + KC * LDB;

    const int tid = threadIdx.x;
    const int mb = blockIdx.x;
    const int m0 = mb * 128;

    const int wid = tid >> 5, lane = tid & 31;
    const int wm = wid >> 2, wn = wid & 3;       // 4 x 4 warps
    const int mW = wm * 32, nW = wn * 64;
    constexpr int NT = 8;                        // 8 n8-tiles per warp (64 cols)
    constexpr int KSTEPS_C = KC / 16;

    float acc[2][NT][4];
#pragma unroll
    for (int i = 0; i < 2; i++)
#pragma unroll
        for (int j = 0; j < NT; j++)
#pragma unroll
            for (int q = 0; q < 4; q++) acc[i][j][q] = 0.f;

    const uint32_t aHiU = smem_u32(aHi) + (uint32_t)(mW + (lane & 15)) * (LDA * 2) + (lane >> 4) * 16;
    const uint32_t aLoU = smem_u32(aLo) + (uint32_t)(mW + (lane & 15)) * (LDA * 2) + (lane >> 4) * 16;
    const uint32_t bHiU = smem_u32(bHi) + (uint32_t)(lane & 15) * (LDB * 2) + (uint32_t)nW * 2 + (lane >> 4) * 16;
    const uint32_t bLoU = smem_u32(bLo) + (uint32_t)(lane & 15) * (LDB * 2) + (uint32_t)nW * 2 + (lane >> 4) * 16;

    for (int ch = 0; ch < NCHUNK; ch++) {
        const int kbase = ch * KC;
        if (ch > 0) __syncthreads();

        // ---- stage A chunk (once per M-block) ----
        constexpr int AIT = 128 * (KC / 2);
        for (int idx = tid; idx < AIT; idx += 512) {
            const int r  = idx / (KC / 2);
            const int p  = idx - r * (KC / 2);
            const int kl = 2 * p;
            const int kk = kbase + kl;
            const uint2 w = *(const uint2*)(A + (size_t)(m0 + r) * KORIG + kk);
            float v0 = __uint_as_float(w.x & 0xFFFF0000u) + __uint_as_float(w.x << 16);
            float v1 = __uint_as_float(w.y & 0xFFFF0000u) + __uint_as_float(w.y << 16);
            v0 = fmaxf(fmaf(v0, __ldg(scale + kk),     __ldg(shift + kk)),     0.f);
            v1 = fmaxf(fmaf(v1, __ldg(scale + kk + 1), __ldg(shift + kk + 1)), 0.f);
            __nv_bfloat16 h0 = __float2bfloat16(v0), h1 = __float2bfloat16(v1);
            __nv_bfloat16 l0 = __float2bfloat16(v0 - __bfloat162float(h0));
            __nv_bfloat16 l1 = __float2bfloat16(v1 - __bfloat162float(h1));
            *(__nv_bfloat162*)(aHi + r * LDA + kl) = __halves2bfloat162(h0, h1);
            *(__nv_bfloat162*)(aLo + r * LDA + kl) = __halves2bfloat162(l0, l1);
        }
        // ---- stage B chunk ----
        constexpr int BIT = KC * (BN / 2);
        for (int idx = tid; idx < BIT; idx += 512) {
            const int k = idx / (BN / 2);
            const int n = 2 * (idx - k * (BN / 2));
            *(uint32_t*)(bHi + k * LDB + n) = *(const uint32_t*)(BH + (size_t)(kbase + k) * BN + n);
            *(uint32_t*)(bLo + k * LDB + n) = *(const uint32_t*)(BL + (size_t)(kbase + k) * BN + n);
        }
        __syncthreads();

        // ---- compute chunk ----
#pragma unroll
        for (int ks = 0; ks < KSTEPS_C; ks++) {
            uint32_t ah[2][4], al[2][4];
            ldsm4(ah[0], aHiU + ks * 32);
            ldsm4(ah[1], aHiU + 16 * LDA * 2 + ks * 32);
            ldsm4(al[0], aLoU + ks * 32);
            ldsm4(al[1], aLoU + 16 * LDA * 2 + ks * 32);
#pragma unroll
            for (int ng = 0; ng < NT / 2; ng++) {
                uint32_t bh[4], bl[4];
                const uint32_t bo = (uint32_t)ks * (16 * LDB * 2) + ng * 32;
                ldsm4t(bh, bHiU + bo);
                ldsm4t(bl, bLoU + bo);
#pragma unroll
                for (int mt = 0; mt < 2; mt++) {
                    mma_bf16(acc[mt][ng*2+0], ah[mt], bh[0], bh[1]);
                    mma_bf16(acc[mt][ng*2+0], ah[mt], bl[0], bl[1]);
                    mma_bf16(acc[mt][ng*2+0], al[mt], bh[0], bh[1]);
                    mma_bf16(acc[mt][ng*2+1], ah[mt], bh[2], bh[3]);
                    mma_bf16(acc[mt][ng*2+1], ah[mt], bl[2], bl[3]);
                    mma_bf16(acc[mt][ng*2+1], al[mt], bh[2], bh[3]);
                }
            }
        }
    }
    __syncthreads();

    // ---- epilogue: bias, BN partials, per-group min/max ----
    float* sSum = (float*)dyn;            // [4][256]
    float* sSq  = sSum + 4 * BN;          // [4][256]

#pragma unroll
    for (int nt = 0; nt < NT; nt++) {
        const int colLocal = nW + nt * 8 + (lane & 3) * 2;
        const float b0 = __ldg(bias + colLocal);
        const float b1 = __ldg(bias + colLocal + 1);
        float v0 = acc[0][nt][0] + b0, v1 = acc[0][nt][1] + b1;
        float v2 = acc[0][nt][2] + b0, v3 = acc[0][nt][3] + b1;
        float v4 = acc[1][nt][0] + b0, v5 = acc[1][nt][1] + b1;
        float v6 = acc[1][nt][2] + b0, v7 = acc[1][nt][3] + b1;
        float s0 = v0+v2+v4+v6,              s1 = v1+v3+v5+v7;
        float q0 = v0*v0+v2*v2+v4*v4+v6*v6,  q1 = v1*v1+v3*v3+v5*v5+v7*v7;
        float mx0 = fmaxf(fmaxf(v0,v2), fmaxf(v4,v6)), mx1 = fmaxf(fmaxf(v1,v3), fmaxf(v5,v7));
        float mn0 = fminf(fminf(v0,v2), fminf(v4,v6)), mn1 = fminf(fminf(v1,v3), fminf(v5,v7));
#pragma unroll
        for (int d = 4; d < 32; d <<= 1) {
            s0 += __shfl_xor_sync(0xffffffffu, s0, d);
            s1 += __shfl_xor_sync(0xffffffffu, s1, d);
            q0 += __shfl_xor_sync(0xffffffffu, q0, d);
            q1 += __shfl_xor_sync(0xffffffffu, q1, d);
            mx0 = fmaxf(mx0, __shfl_xor_sync(0xffffffffu, mx0, d));
            mx1 = fmaxf(mx1, __shfl_xor_sync(0xffffffffu, mx1, d));
            mn0 = fminf(mn0, __shfl_xor_sync(0xffffffffu, mn0, d));
            mn1 = fminf(mn1, __shfl_xor_sync(0xffffffffu, mn1, d));
        }
        if (lane < 4) {
            sSum[wm*BN + colLocal] = s0;  sSum[wm*BN + colLocal + 1] = s1;
            sSq [wm*BN + colLocal] = q0;  sSq [wm*BN + colLocal + 1] = q1;
            const size_t grp = (size_t)(mb * 4 + wm) * CH3 + colLocal;
            gmax[grp]     = mx0;  gmax[grp + 1] = mx1;
            gmin[grp]     = mn0;  gmin[grp + 1] = mn1;
        }
    }
    __syncthreads();
    for (int n = tid; n < BN; n += 512) {
        float s = sSum[n] + sSum[BN + n] + sSum[2*BN + n] + sSum[3*BN + n];
        float q = sSq [n] + sSq [BN + n] + sSq [2*BN + n] + sSq [3*BN + n];
        partSum[(size_t)mb * BN + n] = s;
        partSq [(size_t)mb * BN + n] = q;
    }
}

// ---------------- fold partials -> scale/shift ----------------
__global__ __launch_bounds__(256) void stats_kernel(const float* __restrict__ partSum,
                                                    const float* __restrict__ partSq,
                                                    int N,
                                                    const float* __restrict__ g,
                                                    const float* __restrict__ bt,
                                                    float* __restrict__ scale,
                                                    float* __restrict__ shift)
{
    const int c = blockIdx.x, tid = threadIdx.x;
    __shared__ float ss[256], sq[256];
    float a = 0.f, b2 = 0.f;
    for (int mb = tid; mb < MBLK; mb += 256) {
        a  += partSum[(size_t)mb * N + c];
        b2 += partSq [(size_t)mb * N + c];
    }
    ss[tid] = a; sq[tid] = b2;
    __syncthreads();
    for (int s = 128; s > 0; s >>= 1) {
        if (tid < s) { ss[tid] += ss[tid+s]; sq[tid] += sq[tid+s]; }
        __syncthreads();
    }
    if (tid == 0) {
        const float invM = 1.0f / (float)MTOT;
        float mean = ss[0] * invM;
        float var  = sq[0] * invM - mean * mean;
        float sc   = g[c] / sqrtf(var + BNEPS);
        scale[c] = sc;
        shift[c] = bt[c] - mean * sc;
    }
}

// ---------------- final: pick max/min by sign(scale), affine+relu ----------------
__global__ __launch_bounds__(256) void finalpool_kernel(const float* __restrict__ gmax,
                                                        const float* __restrict__ gmin,
                                                        const float* __restrict__ scale,
                                                        const float* __restrict__ shift,
                                                        float* __restrict__ out)
{
    const int g = blockIdx.x, c = threadIdx.x;
    const float sc = scale[c], sh = shift[c];
    const float v = (sc >= 0.f) ? gmax[(size_t)g * CH3 + c] : gmin[(size_t)g * CH3 + c];
    out[(size_t)g * CH3 + c] = fmaxf(fmaf(v, sc, sh), 0.f);
}

// ---------------- launch ----------------
extern "C" void kernel_launch(void* const* d_in, const int* in_sizes, int n_in,
                              void* d_out, int out_size)
{
    const float* xyz    = (const float*)d_in[0];
    const float* points = (const float*)d_in[1];
    const float* w0  = (const float*)d_in[2];
    const float* b0  = (const float*)d_in[3];
    const float* g0  = (const float*)d_in[4];
    const float* bt0 = (const float*)d_in[5];
    const float* w1  = (const float*)d_in[6];
    const float* b1  = (const float*)d_in[7];
    const float* g1  = (const float*)d_in[8];
    const float* bt1 = (const float*)d_in[9];
    const float* w2  = (const float*)d_in[10];
    const float* b2  = (const float*)d_in[11];
    const float* g2  = (const float*)d_in[12];
    const float* bt2 = (const float*)d_in[13];

    float* out        = (float*)d_out;
    float* new_xyz    = out;
    float* new_points = out + (size_t)BATCH*SPTS*3;

    float *part, *scale, *shift, *gmax, *gmin;
    uint32_t *y1, *y2;
    int* gidx;
    __nv_bfloat16 *bh0, *bl0, *bh1, *bl1, *bh2, *bl2;
    cudaGetSymbolAddress((void**)&y1,    g_y1);
    cudaGetSymbolAddress((void**)&y2,    g_y2);
    cudaGetSymbolAddress((void**)&part,  g_part);
    cudaGetSymbolAddress((void**)&scale, g_scale);
    cudaGetSymbolAddress((void**)&shift, g_shift);
    cudaGetSymbolAddress((void**)&gidx,  g_gidx);
    cudaGetSymbolAddress((void**)&gmax,  g_gmax);
    cudaGetSymbolAddress((void**)&gmin,  g_gmin);
    cudaGetSymbolAddress((void**)&bh0,   g_bh0);
    cudaGetSymbolAddress((void**)&bl0,   g_bl0);
    cudaGetSymbolAddress((void**)&bh1,   g_bh1);
    cudaGetSymbolAddress((void**)&bl1,   g_bl1);
    cudaGetSymbolAddress((void**)&bh2,   g_bh2);
    cudaGetSymbolAddress((void**)&bl2,   g_bl2);

    float* partSum = part;
    float* partSq  = part + (size_t)MBLK * CH3;

    constexpr int SM1 = (2*128*(80+8) + 2*80*(64+8))  * 2;   //  68,096
    constexpr int SM2 = (2*128*(64+8) + 2*64*(128+8)) * 2;   //  71,680
    constexpr int SMW = (2*128*(64+8) + 2*64*(256+8)) * 2;   // 104,448

    static bool attrDone = false;
    if (!attrDone) {
        cudaFuncSetAttribute(gemm_mma<64, 64, 80, 80, 67, 0, false, true, false, 2>,
                             cudaFuncAttributeMaxDynamicSharedMemorySize, SM1);
        cudaFuncSetAttribute(gemm_mma<128, 128, 64, 64, 64, 1, true, true, false, 2>,
                             cudaFuncAttributeMaxDynamicSharedMemorySize, SM2);
        cudaFuncSetAttribute(gemm_mma_w3<128, 64, 128>,
                             cudaFuncAttributeMaxDynamicSharedMemorySize, SMW);
        attrDone = true;
    }

    prep_kernel<<<(80*64 + 255)/256, 256>>>(w0, CH0, CH1, 80, bh0, bl0);
    prep_kernel<<<(64*128 + 255)/256, 256>>>(w1, CH1, CH2, 64, bh1, bl1);
    prep_kernel<<<(128*256 + 255)/256, 256>>>(w2, CH2, CH3, 128, bh2, bl2);

    fps_kernel<<<BATCH, 512>>>(xyz, new_xyz);
    ballquery_kernel<<<BATCH*SPTS/8, 256>>>(xyz, new_xyz, gidx);

    // layer 1: 67 -> 64, gather fused into A-stage (no x0 buffer)
    gemm_mma<64, 64, 80, 80, 67, 0, false, true, false, 2><<<dim3(1, MBLK), 256, SM1>>>(
        nullptr, gidx, xyz, points, new_xyz,
        bh0, bl0, b0, nullptr, nullptr, y1, partSum, partSq, nullptr, nullptr);
    stats_kernel<<<CH1, 256>>>(partSum, partSq, CH1, g0, bt0, scale, shift);

    // layer 2: 64 -> 128 (consumes packed y1)
    gemm_mma<128, 128, 64, 64, 64, 1, true, true, false, 2><<<dim3(1, MBLK), 256, SM2>>>(
        y1, nullptr, nullptr, nullptr, nullptr,
        bh1, bl1, b1, scale, shift, y2, partSum, partSq, nullptr, nullptr);
    stats_kernel<<<CH2, 256>>>(partSum, partSq, CH2, g1, bt1, scale, shift);

    // layer 3: 128 -> 256 in ONE wide CTA (A staged once, y2 read once)
    gemm_mma_w3<128, 64, 128><<<MBLK, 512, SMW>>>(
        y2, bh2, bl2, b2, scale, shift, partSum, partSq, gmax, gmin);
    stats_kernel<<<CH3, 256>>>(partSum, partSq, CH3, g2, bt2, scale, shift);

    finalpool_kernel<<<BATCH*SPTS, 256>>>(gmax, gmin, scale, shift, new_points);
}

// round 10
// speedup vs baseline: 1.9814x; 1.0034x over previous
#include <cuda_runtime.h>
#include <cuda_bf16.h>
#include <math.h>
#include <stdint.h>

// ---------------- problem constants ----------------
#define BATCH 16
#define NPTS  4096
#define DFEAT 64
#define SPTS  1024
#define NSAMP 32
#define CH0   67
#define CH1   64
#define CH2   128
#define CH3   256
#define MTOT  (BATCH*SPTS*NSAMP)   // 524288
#define MBLK  (MTOT/128)           // 4096
#define RAD2  0.04f
#define BNEPS 1e-5f

typedef unsigned long long ull;

// ---------------- device scratch ----------------
__device__ uint32_t g_y1[(size_t)MTOT*CH1];   // packed bf16 hi|lo per element
__device__ uint32_t g_y2[(size_t)MTOT*CH2];
__device__ int   g_gidx[BATCH*SPTS*NSAMP];
__device__ float g_part[2*(size_t)MBLK*CH3];  // transposed: [n][MBLK]
__device__ float g_scale[CH3];
__device__ float g_shift[CH3];
__device__ float g_gmax[(size_t)BATCH*SPTS*CH3];
__device__ float g_gmin[(size_t)BATCH*SPTS*CH3];
// weights prepped k-major [KPAD][N], bf16 hi/lo
__device__ __nv_bfloat16 g_bh0[80*64],   g_bl0[80*64];
__device__ __nv_bfloat16 g_bh1[64*128],  g_bl1[64*128];
__device__ __nv_bfloat16 g_bh2[128*256], g_bl2[128*256];

// ---------------- helpers ----------------
__device__ __forceinline__ uint32_t smem_u32(const void* p) {
    uint32_t a;
    asm("{ .reg .u64 t; cvta.to.shared.u64 t, %1; cvt.u32.u64 %0, t; }" : "=r"(a) : "l"(p));
    return a;
}
__device__ __forceinline__ void ldsm4(uint32_t* r, uint32_t a) {
    asm volatile("ldmatrix.sync.aligned.m8n8.x4.shared.b16 {%0,%1,%2,%3}, [%4];"
                 : "=r"(r[0]), "=r"(r[1]), "=r"(r[2]), "=r"(r[3]) : "r"(a));
}
__device__ __forceinline__ void ldsm4t(uint32_t* r, uint32_t a) {
    asm volatile("ldmatrix.sync.aligned.m8n8.x4.trans.shared.b16 {%0,%1,%2,%3}, [%4];"
                 : "=r"(r[0]), "=r"(r[1]), "=r"(r[2]), "=r"(r[3]) : "r"(a));
}
__device__ __forceinline__ void mma_bf16(float* c, const uint32_t* a, uint32_t b0, uint32_t b1) {
    asm volatile(
        "mma.sync.aligned.m16n8k16.row.col.f32.bf16.bf16.f32 "
        "{%0,%1,%2,%3}, {%4,%5,%6,%7}, {%8,%9}, {%0,%1,%2,%3};"
        : "+f"(c[0]), "+f"(c[1]), "+f"(c[2]), "+f"(c[3])
        : "r"(a[0]), "r"(a[1]), "r"(a[2]), "r"(a[3]), "r"(b0), "r"(b1));
}
// packed bf16x2 convert: d<31:16>=rn(a), d<15:0>=rn(b). Bit-identical to 2x __float2bfloat16.
__device__ __forceinline__ uint32_t cvt2bf(float hi_elem, float lo_elem) {
    uint32_t r;
    asm("cvt.rn.bf16x2.f32 %0, %1, %2;" : "=r"(r) : "f"(hi_elem), "f"(lo_elem));
    return r;
}
// split pair (v0 -> low half, v1 -> high half): hi2/lo2 packed bf16x2 tiles
__device__ __forceinline__ void split2(float v0, float v1, uint32_t& hi2, uint32_t& lo2) {
    hi2 = cvt2bf(v1, v0);
    const float h0f = __uint_as_float(hi2 << 16);
    const float h1f = __uint_as_float(hi2 & 0xFFFF0000u);
    lo2 = cvt2bf(v1 - h1f, v0 - h0f);
}
// per-element packed (hi<<16)|lo words for a pair, via 1 cvt each + PRMT
__device__ __forceinline__ void packsplit2(float v0, float v1, uint32_t& o0, uint32_t& o1) {
    uint32_t hi2, lo2;
    split2(v0, v1, hi2, lo2);
    o0 = __byte_perm(lo2, hi2, 0x5410);   // hi0<<16 | lo0
    o1 = __byte_perm(lo2, hi2, 0x7632);   // hi1<<16 | lo1
}

// ---------------- FPS v6: packed distances + REDUX-only cross-warp tail ----------------
__global__ __launch_bounds__(512) void fps_kernel(const float* __restrict__ xyz,
                                                  float* __restrict__ new_xyz)
{
    __shared__ float sx[NPTS], sy[NPTS], sz[NPTS];
    __shared__ unsigned s_val[2][16], s_low[2][16];
    const int b = blockIdx.x, tid = threadIdx.x;
    const int lane = tid & 31, wid = tid >> 5;
    const float* X = xyz + (size_t)b * NPTS * 3;

    ull pxp[4], pyp[4], pzp[4];
    float dist[8];
#pragma unroll
    for (int t = 0; t < 8; t++) dist[t] = 1e10f;
#pragma unroll
    for (int t = 0; t < 4; t++) {
        const int j0 = tid + (2*t) * 512, j1 = tid + (2*t+1) * 512;
        float x0 = X[3*j0], y0 = X[3*j0+1], z0 = X[3*j0+2];
        float x1 = X[3*j1], y1 = X[3*j1+1], z1 = X[3*j1+2];
        sx[j0] = x0; sy[j0] = y0; sz[j0] = z0;
        sx[j1] = x1; sy[j1] = y1; sz[j1] = z1;
        asm("mov.b64 %0, {%1,%2};" : "=l"(pxp[t]) : "f"(x0), "f"(x1));
        asm("mov.b64 %0, {%1,%2};" : "=l"(pyp[t]) : "f"(y0), "f"(y1));
        asm("mov.b64 %0, {%1,%2};" : "=l"(pzp[t]) : "f"(z0), "f"(z1));
    }
    __syncthreads();

    int far = 0;
    for (int i = 0; i < SPTS; i++) {
        const float cx = sx[far], cy = sy[far], cz = sz[far];
        if (tid == 0) {
            float* o = new_xyz + ((size_t)b * SPTS + i) * 3;
            o[0] = cx; o[1] = cy; o[2] = cz;
        }
        if (i == SPTS - 1) break;

        const float mx = -cx, my = -cy, mz = -cz;
        ull ncx, ncy, ncz;
        asm("mov.b64 %0, {%1,%1};" : "=l"(ncx) : "f"(mx));
        asm("mov.b64 %0, {%1,%1};" : "=l"(ncy) : "f"(my));
        asm("mov.b64 %0, {%1,%1};" : "=l"(ncz) : "f"(mz));

        float bv = -1.0f; int bi = 0;
#pragma unroll
        for (int t = 0; t < 4; t++) {
            ull dx, dy, dz, dd;
            asm("add.rn.f32x2 %0, %1, %2;" : "=l"(dx) : "l"(pxp[t]), "l"(ncx));
            asm("add.rn.f32x2 %0, %1, %2;" : "=l"(dy) : "l"(pyp[t]), "l"(ncy));
            asm("add.rn.f32x2 %0, %1, %2;" : "=l"(dz) : "l"(pzp[t]), "l"(ncz));
            asm("mul.rn.f32x2 %0, %1, %2;" : "=l"(dd) : "l"(dx), "l"(dx));
            asm("fma.rn.f32x2 %0, %1, %2, %3;" : "=l"(dd) : "l"(dy), "l"(dy), "l"(dd));
            asm("fma.rn.f32x2 %0, %1, %2, %3;" : "=l"(dd) : "l"(dz), "l"(dz), "l"(dd));
            float d0, d1;
            asm("mov.b64 {%0,%1}, %2;" : "=f"(d0), "=f"(d1) : "l"(dd));
            const float nd0 = fminf(dist[2*t],   d0);
            const float nd1 = fminf(dist[2*t+1], d1);
            dist[2*t]   = nd0;
            dist[2*t+1] = nd1;
            if (nd0 > bv) { bv = nd0; bi = tid + (2*t)   * 512; }
            if (nd1 > bv) { bv = nd1; bi = tid + (2*t+1) * 512; }
        }
        const unsigned vb = __float_as_uint(bv);
        const unsigned m  = __reduce_max_sync(0xffffffffu, vb);
        const unsigned lw = __reduce_max_sync(0xffffffffu,
                                              (vb == m) ? (0xFFFFu - (unsigned)bi) : 0u);
        const int buf = i & 1;
        if (lane == 0) { s_val[buf][wid] = m; s_low[buf][wid] = lw; }
        __syncthreads();

        const unsigned v2 = s_val[buf][lane & 15];
        const unsigned l2 = s_low[buf][lane & 15];
        const unsigned M  = __reduce_max_sync(0xffffffffu, v2);
        const unsigned LW = __reduce_max_sync(0xffffffffu, (v2 == M) ? l2 : 0u);
        far = 0xFFFF - (int)LW;
    }
}

// ---------------- ball query ----------------
__global__ __launch_bounds__(256) void ballquery_kernel(const float* __restrict__ xyz,
                                                        const float* __restrict__ new_xyz,
                                                        int* __restrict__ gidx)
{
    const int w    = blockIdx.x * 8 + (threadIdx.x >> 5);
    const int lane = threadIdx.x & 31;
    const int b    = w >> 10;
    const float* X = xyz + (size_t)b * NPTS * 3;

    const float cx = new_xyz[(size_t)w*3+0];
    const float cy = new_xyz[(size_t)w*3+1];
    const float cz = new_xyz[(size_t)w*3+2];
    const float ss = cx*cx + cy*cy + cz*cz;

    int cnt = 0, firstIdx = 0;
    int* out = gidx + (size_t)w * NSAMP;

    for (int base = 0; base < NPTS && cnt < NSAMP; base += 32) {
        const int j = base + lane;
        const float x = X[3*j], y = X[3*j+1], z = X[3*j+2];
        const float pp  = x*x + y*y + z*z;
        const float dot = x*cx + y*cy + z*cz;
        const float d   = (-2.0f*dot + ss) + pp;
        const bool  in  = !(d > RAD2);
        unsigned mask = __ballot_sync(0xffffffffu, in);
        if (cnt == 0 && mask) firstIdx = base + (__ffs(mask) - 1);
        int rank = __popc(mask & ((1u << lane) - 1u));
        int slot = cnt + rank;
        if (in && slot < NSAMP) out[slot] = j;
        cnt += __popc(mask);
    }
    for (int t = cnt + lane; t < NSAMP; t += 32) out[t] = firstIdx;
}

// ---------------- weight prep: W[K][N] f32 -> [KPAD][N] bf16 hi/lo (k-major) ----------------
__global__ __launch_bounds__(256) void prep_kernel(const float* __restrict__ W, int K, int N,
                                                   int KPAD,
                                                   __nv_bfloat16* __restrict__ bh,
                                                   __nv_bfloat16* __restrict__ bl)
{
    int i = blockIdx.x * 256 + threadIdx.x;
    if (i >= N * KPAD) return;
    int k = i / N, n = i - k * N;
    float v = (k < K) ? W[(size_t)k * N + n] : 0.f;
    __nv_bfloat16 h = __float2bfloat16(v);
    bh[i] = h;
    bl[i] = __float2bfloat16(v - __bfloat162float(h));
}

// ---------------- HMMA GEMM (bf16 split-3, K-chunked staging), 256 threads ----------------
template<int BN, int NTOT, int KPAD, int KC, int KORIG, int AMODE,
         bool TRANSFORM, bool STORE_Y, bool FUSED_MAX, int MINB>
__global__ void __launch_bounds__(256, MINB) gemm_mma(
    const uint32_t* __restrict__ A,
    const int* __restrict__ gidxp, const float* __restrict__ xyzp,
    const float* __restrict__ pointsp, const float* __restrict__ nxyz,
    const __nv_bfloat16* __restrict__ BH, const __nv_bfloat16* __restrict__ BL,
    const float* __restrict__ bias,
    const float* __restrict__ scale, const float* __restrict__ shift,
    uint32_t* __restrict__ Y,
    float* __restrict__ partSum, float* __restrict__ partSq,
    float* __restrict__ gmax, float* __restrict__ gmin)
{
    extern __shared__ __align__(16) char dyn[];
    __shared__ int   sIdx[128];
    __shared__ float sCen[12];
    constexpr int LDA = KC + 8;     // bf16 units
    constexpr int LDB = BN + 8;
    constexpr int NCHUNK = KPAD / KC;
    __nv_bfloat16* aHi = (__nv_bfloat16*)dyn;
    __nv_bfloat16* aLo = aHi + 128 * LDA;
    __nv_bfloat16* bHi = aLo + 128 * LDA;
    __nv_bfloat16* bLo = bHi + KC * LDB;

    const int tid = threadIdx.x;
    const int nb = blockIdx.x, mb = blockIdx.y;
    const int m0 = mb * 128, n0 = nb * BN;

    if (AMODE == 0) {
        if (tid < 128) sIdx[tid] = gidxp[m0 + tid];
        if (tid < 12)  sCen[tid] = nxyz[(size_t)(mb * 4) * 3 + tid];
        __syncthreads();
    }

    const int wid = tid >> 5, lane = tid & 31;
    const int wm = wid >> 1, wn = wid & 1;
    const int mW = wm * 32, nW = wn * (BN / 2);
    constexpr int NT = BN / 16;
    constexpr int KSTEPS_C = KC / 16;

    float acc[2][NT][4];
#pragma unroll
    for (int i = 0; i < 2; i++)
#pragma unroll
        for (int j = 0; j < NT; j++)
#pragma unroll
            for (int q = 0; q < 4; q++) acc[i][j][q] = 0.f;

    const uint32_t aHiU = smem_u32(aHi) + (uint32_t)(mW + (lane & 15)) * (LDA * 2) + (lane >> 4) * 16;
    const uint32_t aLoU = smem_u32(aLo) + (uint32_t)(mW + (lane & 15)) * (LDA * 2) + (lane >> 4) * 16;
    const uint32_t bHiU = smem_u32(bHi) + (uint32_t)(lane & 15) * (LDB * 2) + (uint32_t)nW * 2 + (lane >> 4) * 16;
    const uint32_t bLoU = smem_u32(bLo) + (uint32_t)(lane & 15) * (LDB * 2) + (uint32_t)nW * 2 + (lane >> 4) * 16;

    const int bb = m0 >> 15;
    const float* Xb = xyzp    ? xyzp    + (size_t)bb * NPTS * 3     : nullptr;
    const float* Pb = pointsp ? pointsp + (size_t)bb * NPTS * DFEAT : nullptr;

    for (int ch = 0; ch < NCHUNK; ch++) {
        const int kbase = ch * KC;
        if (ch > 0) __syncthreads();

        // ---- stage A chunk -> bf16 hi/lo (paired converts) ----
        constexpr int AIT = 128 * (KC / 2);
        for (int idx = tid; idx < AIT; idx += 256) {
            const int r  = idx / (KC / 2);
            const int p  = idx - r * (KC / 2);
            const int kl = 2 * p;
            const int kk = kbase + kl;
            float v0 = 0.f, v1 = 0.f;
            if (AMODE == 0) {
                const int j = sIdx[r];
                const int grp = (r >> 5) * 3;
                if (kk < 3)        v0 = Xb[j*3 + kk] - sCen[grp + kk];
                else if (kk < CH0) v0 = Pb[(size_t)j * DFEAT + kk - 3];
                const int c1 = kk + 1;
                if (c1 < 3)        v1 = Xb[j*3 + c1] - sCen[grp + c1];
                else if (c1 < CH0) v1 = Pb[(size_t)j * DFEAT + c1 - 3];
            } else {
                const uint2 w = *(const uint2*)(A + (size_t)(m0 + r) * KORIG + kk);
                v0 = __uint_as_float(w.x & 0xFFFF0000u) + __uint_as_float(w.x << 16);
                v1 = __uint_as_float(w.y & 0xFFFF0000u) + __uint_as_float(w.y << 16);
                if (TRANSFORM) {
                    v0 = fmaxf(fmaf(v0, __ldg(scale + kk),     __ldg(shift + kk)),     0.f);
                    v1 = fmaxf(fmaf(v1, __ldg(scale + kk + 1), __ldg(shift + kk + 1)), 0.f);
                }
            }
            uint32_t hi2, lo2;
            split2(v0, v1, hi2, lo2);
            *(uint32_t*)(aHi + r * LDA + kl) = hi2;
            *(uint32_t*)(aLo + r * LDA + kl) = lo2;
        }
        // ---- stage B chunk ----
        constexpr int BIT = KC * (BN / 2);
        for (int idx = tid; idx < BIT; idx += 256) {
            const int k = idx / (BN / 2);
            const int n = 2 * (idx - k * (BN / 2));
            *(uint32_t*)(bHi + k * LDB + n) = *(const uint32_t*)(BH + (size_t)(kbase + k) * NTOT + n0 + n);
            *(uint32_t*)(bLo + k * LDB + n) = *(const uint32_t*)(BL + (size_t)(kbase + k) * NTOT + n0 + n);
        }
        __syncthreads();

        // ---- compute chunk ----
#pragma unroll
        for (int ks = 0; ks < KSTEPS_C; ks++) {
            uint32_t ah[2][4], al[2][4];
            ldsm4(ah[0], aHiU + ks * 32);
            ldsm4(ah[1], aHiU + 16 * LDA * 2 + ks * 32);
            ldsm4(al[0], aLoU + ks * 32);
            ldsm4(al[1], aLoU + 16 * LDA * 2 + ks * 32);
#pragma unroll
            for (int ng = 0; ng < NT / 2; ng++) {
                uint32_t bh[4], bl[4];
                const uint32_t bo = (uint32_t)ks * (16 * LDB * 2) + ng * 32;
                ldsm4t(bh, bHiU + bo);
                ldsm4t(bl, bLoU + bo);
#pragma unroll
                for (int mt = 0; mt < 2; mt++) {
                    mma_bf16(acc[mt][ng*2+0], ah[mt], bh[0], bh[1]);
                    mma_bf16(acc[mt][ng*2+0], ah[mt], bl[0], bl[1]);
                    mma_bf16(acc[mt][ng*2+0], al[mt], bh[0], bh[1]);
                    mma_bf16(acc[mt][ng*2+1], ah[mt], bh[2], bh[3]);
                    mma_bf16(acc[mt][ng*2+1], ah[mt], bl[2], bl[3]);
                    mma_bf16(acc[mt][ng*2+1], al[mt], bh[2], bh[3]);
                }
            }
        }
    }
    __syncthreads();

    // ---- epilogue ----
    float* sSum = (float*)dyn;            // [4][BN]
    float* sSq  = sSum + 4 * BN;          // [4][BN]

    const int r0 = lane >> 2;
#pragma unroll
    for (int nt = 0; nt < NT; nt++) {
        const int colLocal = nW + nt * 8 + (lane & 3) * 2;
        const float b0 = __ldg(bias + n0 + colLocal);
        const float b1 = __ldg(bias + n0 + colLocal + 1);
        float v0 = acc[0][nt][0] + b0, v1 = acc[0][nt][1] + b1;
        float v2 = acc[0][nt][2] + b0, v3 = acc[0][nt][3] + b1;
        float v4 = acc[1][nt][0] + b0, v5 = acc[1][nt][1] + b1;
        float v6 = acc[1][nt][2] + b0, v7 = acc[1][nt][3] + b1;
        if (STORE_Y) {
            const size_t base = (size_t)(m0 + mW + r0) * NTOT + n0 + colLocal;
            uint32_t o0, o1;
            packsplit2(v0, v1, o0, o1);
            *(uint2*)(Y + base)           = make_uint2(o0, o1);
            packsplit2(v2, v3, o0, o1);
            *(uint2*)(Y + base +  8*NTOT) = make_uint2(o0, o1);
            packsplit2(v4, v5, o0, o1);
            *(uint2*)(Y + base + 16*NTOT) = make_uint2(o0, o1);
            packsplit2(v6, v7, o0, o1);
            *(uint2*)(Y + base + 24*NTOT) = make_uint2(o0, o1);
        }
        float s0 = v0+v2+v4+v6,              s1 = v1+v3+v5+v7;
        float q0 = v0*v0+v2*v2+v4*v4+v6*v6,  q1 = v1*v1+v3*v3+v5*v5+v7*v7;
        float mx0 = fmaxf(fmaxf(v0,v2), fmaxf(v4,v6)), mx1 = fmaxf(fmaxf(v1,v3), fmaxf(v5,v7));
        float mn0 = fminf(fminf(v0,v2), fminf(v4,v6)), mn1 = fminf(fminf(v1,v3), fminf(v5,v7));
#pragma unroll
        for (int d = 4; d < 32; d <<= 1) {
            s0 += __shfl_xor_sync(0xffffffffu, s0, d);
            s1 += __shfl_xor_sync(0xffffffffu, s1, d);
            q0 += __shfl_xor_sync(0xffffffffu, q0, d);
            q1 += __shfl_xor_sync(0xffffffffu, q1, d);
            mx0 = fmaxf(mx0, __shfl_xor_sync(0xffffffffu, mx0, d));
            mx1 = fmaxf(mx1, __shfl_xor_sync(0xffffffffu, mx1, d));
            mn0 = fminf(mn0, __shfl_xor_sync(0xffffffffu, mn0, d));
            mn1 = fminf(mn1, __shfl_xor_sync(0xffffffffu, mn1, d));
        }
        if (lane < 4) {
            sSum[wm*BN + colLocal] = s0;  sSum[wm*BN + colLocal + 1] = s1;
            sSq [wm*BN + colLocal] = q0;  sSq [wm*BN + colLocal + 1] = q1;
            if (FUSED_MAX) {
                const size_t grp = (size_t)(mb * 4 + wm) * CH3 + n0 + colLocal;
                gmax[grp]     = mx0;  gmax[grp + 1] = mx1;
                gmin[grp]     = mn0;  gmin[grp + 1] = mn1;
            }
        }
    }
    __syncthreads();
    for (int n = tid; n < BN; n += 256) {
        float s = sSum[n] + sSum[BN + n] + sSum[2*BN + n] + sSum[3*BN + n];
        float q = sSq [n] + sSq [BN + n] + sSq [2*BN + n] + sSq [3*BN + n];
        partSum[(size_t)(n0 + n) * MBLK + mb] = s;   // transposed [n][MBLK]
        partSq [(size_t)(n0 + n) * MBLK + mb] = q;
    }
}

// ---------------- HMMA GEMM wide: 512 threads, BN=256 in ONE CTA (layer 3) ----------------
template<int KPAD, int KC, int KORIG>
__global__ void __launch_bounds__(512, 1) gemm_mma_w3(
    const uint32_t* __restrict__ A,
    const __nv_bfloat16* __restrict__ BH, const __nv_bfloat16* __restrict__ BL,
    const float* __restrict__ bias,
    const float* __restrict__ scale, const float* __restrict__ shift,
    float* __restrict__ partSum, float* __restrict__ partSq,
    float* __restrict__ gmax, float* __restrict__ gmin)
{
    extern __shared__ __align__(16) char dyn[];
    constexpr int BN  = 256;
    constexpr int LDA = KC + 8;
    constexpr int LDB = BN + 8;
    constexpr int NCHUNK = KPAD / KC;
    __nv_bfloat16* aHi = (__nv_bfloat16*)dyn;
    __nv_bfloat16* aLo = aHi + 128 * LDA;
    __nv_bfloat16* bHi = aLo + 128 * LDA;
    __nv_bfloat16* bLo = bHi + KC * LDB;

    const int tid = threadIdx.x;
    const int mb = blockIdx.x;
    const int m0 = mb * 128;

    const int wid = tid >> 5, lane = tid & 31;
    const int wm = wid >> 2, wn = wid & 3;
    const int mW = wm * 32, nW = wn * 64;
    constexpr int NT = 8;
    constexpr int KSTEPS_C = KC / 16;

    float acc[2][NT][4];
#pragma unroll
    for (int i = 0; i < 2; i++)
#pragma unroll
        for (int j = 0; j < NT; j++)
#pragma unroll
            for (int q = 0; q < 4; q++) acc[i][j][q] = 0.f;

    const uint32_t aHiU = smem_u32(aHi) + (uint32_t)(mW + (lane & 15)) * (LDA * 2) + (lane >> 4) * 16;
    const uint32_t aLoU = smem_u32(aLo) + (uint32_t)(mW + (lane & 15)) * (LDA * 2) + (lane >> 4) * 16;
    const uint32_t bHiU = smem_u32(bHi) + (uint32_t)(lane & 15) * (LDB * 2) + (uint32_t)nW * 2 + (lane >> 4) * 16;
    const uint32_t bLoU = smem_u32(bLo) + (uint32_t)(lane & 15) * (LDB * 2) + (uint32_t)nW * 2 + (lane >> 4) * 16;

    for (int ch = 0; ch < NCHUNK; ch++) {
        const int kbase = ch * KC;
        if (ch > 0) __syncthreads();

        constexpr int AIT = 128 * (KC / 2);
        for (int idx = tid; idx < AIT; idx += 512) {
            const int r  = idx / (KC / 2);
            const int p  = idx - r * (KC / 2);
            const int kl = 2 * p;
            const int kk = kbase + kl;
            const uint2 w = *(const uint2*)(A + (size_t)(m0 + r) * KORIG + kk);
            float v0 = __uint_as_float(w.x & 0xFFFF0000u) + __uint_as_float(w.x << 16);
            float v1 = __uint_as_float(w.y & 0xFFFF0000u) + __uint_as_float(w.y << 16);
            v0 = fmaxf(fmaf(v0, __ldg(scale + kk),     __ldg(shift + kk)),     0.f);
            v1 = fmaxf(fmaf(v1, __ldg(scale + kk + 1), __ldg(shift + kk + 1)), 0.f);
            uint32_t hi2, lo2;
            split2(v0, v1, hi2, lo2);
            *(uint32_t*)(aHi + r * LDA + kl) = hi2;
            *(uint32_t*)(aLo + r * LDA + kl) = lo2;
        }
        constexpr int BIT = KC * (BN / 2);
        for (int idx = tid; idx < BIT; idx += 512) {
            const int k = idx / (BN / 2);
            const int n = 2 * (idx - k * (BN / 2));
            *(uint32_t*)(bHi + k * LDB + n) = *(const uint32_t*)(BH + (size_t)(kbase + k) * BN + n);
            *(uint32_t*)(bLo + k * LDB + n) = *(const uint32_t*)(BL + (size_t)(kbase + k) * BN + n);
        }
        __syncthreads();

#pragma unroll
        for (int ks = 0; ks < KSTEPS_C; ks++) {
            uint32_t ah[2][4], al[2][4];
            ldsm4(ah[0], aHiU + ks * 32);
            ldsm4(ah[1], aHiU + 16 * LDA * 2 + ks * 32);
            ldsm4(al[0], aLoU + ks * 32);
            ldsm4(al[1], aLoU + 16 * LDA * 2 + ks * 32);
#pragma unroll
            for (int ng = 0; ng < NT / 2; ng++) {
                uint32_t bh[4], bl[4];
                const uint32_t bo = (uint32_t)ks * (16 * LDB * 2) + ng * 32;
                ldsm4t(bh, bHiU + bo);
                ldsm4t(bl, bLoU + bo);
#pragma unroll
                for (int mt = 0; mt < 2; mt++) {
                    mma_bf16(acc[mt][ng*2+0], ah[mt], bh[0], bh[1]);
                    mma_bf16(acc[mt][ng*2+0], ah[mt], bl[0], bl[1]);
                    mma_bf16(acc[mt][ng*2+0], al[mt], bh[0], bh[1]);
                    mma_bf16(acc[mt][ng*2+1], ah[mt], bh[2], bh[3]);
                    mma_bf16(acc[mt][ng*2+1], ah[mt], bl[2], bl[3]);
                    mma_bf16(acc[mt][ng*2+1], al[mt], bh[2], bh[3]);
                }
            }
        }
    }
    __syncthreads();

    float* sSum = (float*)dyn;
    float* sSq  = sSum + 4 * BN;

#pragma unroll
    for (int nt = 0; nt < NT; nt++) {
        const int colLocal = nW + nt * 8 + (lane & 3) * 2;
        const float b0 = __ldg(bias + colLocal);
        const float b1 = __ldg(bias + colLocal + 1);
        float v0 = acc[0][nt][0] + b0, v1 = acc[0][nt][1] + b1;
        float v2 = acc[0][nt][2] + b0, v3 = acc[0][nt][3] + b1;
        float v4 = acc[1][nt][0] + b0, v5 = acc[1][nt][1] + b1;
        float v6 = acc[1][nt][2] + b0, v7 = acc[1][nt][3] + b1;
        float s0 = v0+v2+v4+v6,              s1 = v1+v3+v5+v7;
        float q0 = v0*v0+v2*v2+v4*v4+v6*v6,  q1 = v1*v1+v3*v3+v5*v5+v7*v7;
        float mx0 = fmaxf(fmaxf(v0,v2), fmaxf(v4,v6)), mx1 = fmaxf(fmaxf(v1,v3), fmaxf(v5,v7));
        float mn0 = fminf(fminf(v0,v2), fminf(v4,v6)), mn1 = fminf(fminf(v1,v3), fminf(v5,v7));
#pragma unroll
        for (int d = 4; d < 32; d <<= 1) {
            s0 += __shfl_xor_sync(0xffffffffu, s0, d);
            s1 += __shfl_xor_sync(0xffffffffu, s1, d);
            q0 += __shfl_xor_sync(0xffffffffu, q0, d);
            q1 += __shfl_xor_sync(0xffffffffu, q1, d);
            mx0 = fmaxf(mx0, __shfl_xor_sync(0xffffffffu, mx0, d));
            mx1 = fmaxf(mx1, __shfl_xor_sync(0xffffffffu, mx1, d));
            mn0 = fminf(mn0, __shfl_xor_sync(0xffffffffu, mn0, d));
            mn1 = fminf(mn1, __shfl_xor_sync(0xffffffffu, mn1, d));
        }
        if (lane < 4) {
            sSum[wm*BN + colLocal] = s0;  sSum[wm*BN + colLocal + 1] = s1;
            sSq [wm*BN + colLocal] = q0;  sSq [wm*BN + colLocal + 1] = q1;
            const size_t grp = (size_t)(mb * 4 + wm) * CH3 + colLocal;
            gmax[grp]     = mx0;  gmax[grp + 1] = mx1;
            gmin[grp]     = mn0;  gmin[grp + 1] = mn1;
        }
    }
    __syncthreads();
    for (int n = tid; n < BN; n += 512) {
        float s = sSum[n] + sSum[BN + n] + sSum[2*BN + n] + sSum[3*BN + n];
        float q = sSq [n] + sSq [BN + n] + sSq [2*BN + n] + sSq [3*BN + n];
        partSum[(size_t)n * MBLK + mb] = s;   // transposed [n][MBLK]
        partSq [(size_t)n * MBLK + mb] = q;
    }
}

// ---------------- fold partials -> scale/shift (coalesced transposed reads) ----------------
__global__ __launch_bounds__(256) void stats_kernel(const float* __restrict__ partSum,
                                                    const float* __restrict__ partSq,
                                                    int N,
                                                    const float* __restrict__ g,
                                                    const float* __restrict__ bt,
                                                    float* __restrict__ scale,
                                                    float* __restrict__ shift)
{
    const int c = blockIdx.x, tid = threadIdx.x;
    __shared__ float ss[256], sq[256];
    float a = 0.f, b2 = 0.f;
    const float* ps = partSum + (size_t)c * MBLK;
    const float* pq = partSq  + (size_t)c * MBLK;
    for (int mb = tid; mb < MBLK; mb += 256) {
        a  += ps[mb];
        b2 += pq[mb];
    }
    ss[tid] = a; sq[tid] = b2;
    __syncthreads();
    for (int s = 128; s > 0; s >>= 1) {
        if (tid < s) { ss[tid] += ss[tid+s]; sq[tid] += sq[tid+s]; }
        __syncthreads();
    }
    if (tid == 0) {
        const float invM = 1.0f / (float)MTOT;
        float mean = ss[0] * invM;
        float var  = sq[0] * invM - mean * mean;
        float sc   = g[c] / sqrtf(var + BNEPS);
        scale[c] = sc;
        shift[c] = bt[c] - mean * sc;
    }
}

// ---------------- final: pick max/min by sign(scale), affine+relu ----------------
__global__ __launch_bounds__(256) void finalpool_kernel(const float* __restrict__ gmax,
                                                        const float* __restrict__ gmin,
                                                        const float* __restrict__ scale,
                                                        const float* __restrict__ shift,
                                                        float* __restrict__ out)
{
    const int g = blockIdx.x, c = threadIdx.x;
    const float sc = scale[c], sh = shift[c];
    const float v = (sc >= 0.f) ? gmax[(size_t)g * CH3 + c] : gmin[(size_t)g * CH3 + c];
    out[(size_t)g * CH3 + c] = fmaxf(fmaf(v, sc, sh), 0.f);
}

// ---------------- launch ----------------
extern "C" void kernel_launch(void* const* d_in, const int* in_sizes, int n_in,
                              void* d_out, int out_size)
{
    const float* xyz    = (const float*)d_in[0];
    const float* points = (const float*)d_in[1];
    const float* w0  = (const float*)d_in[2];
    const float* b0  = (const float*)d_in[3];
    const float* g0  = (const float*)d_in[4];
    const float* bt0 = (const float*)d_in[5];
    const float* w1  = (const float*)d_in[6];
    const float* b1  = (const float*)d_in[7];
    const float* g1  = (const float*)d_in[8];
    const float* bt1 = (const float*)d_in[9];
    const float* w2  = (const float*)d_in[10];
    const float* b2  = (const float*)d_in[11];
    const float* g2  = (const float*)d_in[12];
    const float* bt2 = (const float*)d_in[13];

    float* out        = (float*)d_out;
    float* new_xyz    = out;
    float* new_points = out + (size_t)BATCH*SPTS*3;

    float *part, *scale, *shift, *gmax, *gmin;
    uint32_t *y1, *y2;
    int* gidx;
    __nv_bfloat16 *bh0, *bl0, *bh1, *bl1, *bh2, *bl2;
    cudaGetSymbolAddress((void**)&y1,    g_y1);
    cudaGetSymbolAddress((void**)&y2,    g_y2);
    cudaGetSymbolAddress((void**)&part,  g_part);
    cudaGetSymbolAddress((void**)&scale, g_scale);
    cudaGetSymbolAddress((void**)&shift, g_shift);
    cudaGetSymbolAddress((void**)&gidx,  g_gidx);
    cudaGetSymbolAddress((void**)&gmax,  g_gmax);
    cudaGetSymbolAddress((void**)&gmin,  g_gmin);
    cudaGetSymbolAddress((void**)&bh0,   g_bh0);
    cudaGetSymbolAddress((void**)&bl0,   g_bl0);
    cudaGetSymbolAddress((void**)&bh1,   g_bh1);
    cudaGetSymbolAddress((void**)&bl1,   g_bl1);
    cudaGetSymbolAddress((void**)&bh2,   g_bh2);
    cudaGetSymbolAddress((void**)&bl2,   g_bl2);

    float* partSum = part;
    float* partSq  = part + (size_t)MBLK * CH3;

    constexpr int SM1 = (2*128*(80+8) + 2*80*(64+8))  * 2;   //  68,096
    constexpr int SM2 = (2*128*(64+8) + 2*64*(128+8)) * 2;   //  71,680
    constexpr int SMW = (2*128*(64+8) + 2*64*(256+8)) * 2;   // 104,448

    static bool attrDone = false;
    if (!attrDone) {
        cudaFuncSetAttribute(gemm_mma<64, 64, 80, 80, 67, 0, false, true, false, 2>,
                             cudaFuncAttributeMaxDynamicSharedMemorySize, SM1);
        cudaFuncSetAttribute(gemm_mma<128, 128, 64, 64, 64, 1, true, true, false, 2>,
                             cudaFuncAttributeMaxDynamicSharedMemorySize, SM2);
        cudaFuncSetAttribute(gemm_mma_w3<128, 64, 128>,
                             cudaFuncAttributeMaxDynamicSharedMemorySize, SMW);
        attrDone = true;
    }

    prep_kernel<<<(80*64 + 255)/256, 256>>>(w0, CH0, CH1, 80, bh0, bl0);
    prep_kernel<<<(64*128 + 255)/256, 256>>>(w1, CH1, CH2, 64, bh1, bl1);
    prep_kernel<<<(128*256 + 255)/256, 256>>>(w2, CH2, CH3, 128, bh2, bl2);

    fps_kernel<<<BATCH, 512>>>(xyz, new_xyz);
    ballquery_kernel<<<BATCH*SPTS/8, 256>>>(xyz, new_xyz, gidx);

    // layer 1: 67 -> 64, gather fused into A-stage
    gemm_mma<64, 64, 80, 80, 67, 0, false, true, false, 2><<<dim3(1, MBLK), 256, SM1>>>(
        nullptr, gidx, xyz, points, new_xyz,
        bh0, bl0, b0, nullptr, nullptr, y1, partSum, partSq, nullptr, nullptr);
    stats_kernel<<<CH1, 256>>>(partSum, partSq, CH1, g0, bt0, scale, shift);

    // layer 2: 64 -> 128
    gemm_mma<128, 128, 64, 64, 64, 1, true, true, false, 2><<<dim3(1, MBLK), 256, SM2>>>(
        y1, nullptr, nullptr, nullptr, nullptr,
        bh1, bl1, b1, scale, shift, y2, partSum, partSq, nullptr, nullptr);
    stats_kernel<<<CH2, 256>>>(partSum, partSq, CH2, g1, bt1, scale, shift);

    // layer 3: 128 -> 256 wide CTA
    gemm_mma_w3<128, 64, 128><<<MBLK, 512, SMW>>>(
        y2, bh2, bl2, b2, scale, shift, partSum, partSq, gmax, gmin);
    stats_kernel<<<CH3, 256>>>(partSum, partSq, CH3, g2, bt2, scale, shift);

    finalpool_kernel<<<BATCH*SPTS, 256>>>(gmax, gmin, scale, shift, new_points);
}

// round 11
// speedup vs baseline: 2.1082x; 1.0640x over previous
#include <cuda_runtime.h>
#include <cuda_fp16.h>
#include <math.h>
#include <stdint.h>

// ---------------- problem constants ----------------
#define BATCH 16
#define NPTS  4096
#define DFEAT 64
#define SPTS  1024
#define NSAMP 32
#define CH0   67
#define CH1   64
#define CH2   128
#define CH3   256
#define MTOT  (BATCH*SPTS*NSAMP)   // 524288
#define MBLK  (MTOT/128)           // 4096
#define RAD2  0.04f
#define BNEPS 1e-5f

typedef unsigned long long ull;

// ---------------- device scratch ----------------
__device__ uint32_t g_y1[(size_t)MTOT*CH1/2];   // fp16 pairs
__device__ uint32_t g_y2[(size_t)MTOT*CH2/2];   // fp16 pairs
__device__ int   g_gidx[BATCH*SPTS*NSAMP];
__device__ float g_part[2*(size_t)MBLK*CH3];    // transposed [n][MBLK]
__device__ float g_scale[CH3];
__device__ float g_shift[CH3];
__device__ float g_gmax[(size_t)BATCH*SPTS*CH3];
__device__ float g_gmin[(size_t)BATCH*SPTS*CH3];
// weights prepped k-major [KPAD][N], fp16 hi/lo
__device__ __half g_bh0[80*64],   g_bl0[80*64];
__device__ __half g_bh1[64*128],  g_bl1[64*128];
__device__ __half g_bh2[128*256], g_bl2[128*256];

// ---------------- helpers ----------------
__device__ __forceinline__ uint32_t smem_u32(const void* p) {
    uint32_t a;
    asm("{ .reg .u64 t; cvta.to.shared.u64 t, %1; cvt.u32.u64 %0, t; }" : "=r"(a) : "l"(p));
    return a;
}
__device__ __forceinline__ void ldsm4(uint32_t* r, uint32_t a) {
    asm volatile("ldmatrix.sync.aligned.m8n8.x4.shared.b16 {%0,%1,%2,%3}, [%4];"
                 : "=r"(r[0]), "=r"(r[1]), "=r"(r[2]), "=r"(r[3]) : "r"(a));
}
__device__ __forceinline__ void ldsm4t(uint32_t* r, uint32_t a) {
    asm volatile("ldmatrix.sync.aligned.m8n8.x4.trans.shared.b16 {%0,%1,%2,%3}, [%4];"
                 : "=r"(r[0]), "=r"(r[1]), "=r"(r[2]), "=r"(r[3]) : "r"(a));
}
__device__ __forceinline__ void mma_f16(float* c, const uint32_t* a, uint32_t b0, uint32_t b1) {
    asm volatile(
        "mma.sync.aligned.m16n8k16.row.col.f32.f16.f16.f32 "
        "{%0,%1,%2,%3}, {%4,%5,%6,%7}, {%8,%9}, {%0,%1,%2,%3};"
        : "+f"(c[0]), "+f"(c[1]), "+f"(c[2]), "+f"(c[3])
        : "r"(a[0]), "r"(a[1]), "r"(a[2]), "r"(a[3]), "r"(b0), "r"(b1));
}
__device__ __forceinline__ uint32_t packh2(float v0, float v1) {
    __half2 h = __floats2half2_rn(v0, v1);   // v0 -> low, v1 -> high
    return *(uint32_t*)&h;
}

// ---------------- FPS v7: 1024 threads, packed f32x2 distances, REDUX tails ----------------
__global__ __launch_bounds__(1024) void fps_kernel(const float* __restrict__ xyz,
                                                   float* __restrict__ new_xyz)
{
    __shared__ float sx[NPTS], sy[NPTS], sz[NPTS];
    __shared__ unsigned s_val[2][32], s_low[2][32];
    const int b = blockIdx.x, tid = threadIdx.x;
    const int lane = tid & 31, wid = tid >> 5;
    const float* X = xyz + (size_t)b * NPTS * 3;

    ull pxp[2], pyp[2], pzp[2];
    float dist[4];
#pragma unroll
    for (int t = 0; t < 4; t++) dist[t] = 1e10f;
#pragma unroll
    for (int t = 0; t < 2; t++) {
        const int j0 = tid + (2*t) * 1024, j1 = tid + (2*t+1) * 1024;
        float x0 = X[3*j0], y0 = X[3*j0+1], z0 = X[3*j0+2];
        float x1 = X[3*j1], y1 = X[3*j1+1], z1 = X[3*j1+2];
        sx[j0] = x0; sy[j0] = y0; sz[j0] = z0;
        sx[j1] = x1; sy[j1] = y1; sz[j1] = z1;
        asm("mov.b64 %0, {%1,%2};" : "=l"(pxp[t]) : "f"(x0), "f"(x1));
        asm("mov.b64 %0, {%1,%2};" : "=l"(pyp[t]) : "f"(y0), "f"(y1));
        asm("mov.b64 %0, {%1,%2};" : "=l"(pzp[t]) : "f"(z0), "f"(z1));
    }
    __syncthreads();

    int far = 0;
    for (int i = 0; i < SPTS; i++) {
        const float cx = sx[far], cy = sy[far], cz = sz[far];
        if (tid == 0) {
            float* o = new_xyz + ((size_t)b * SPTS + i) * 3;
            o[0] = cx; o[1] = cy; o[2] = cz;
        }
        if (i == SPTS - 1) break;

        const float mx = -cx, my = -cy, mz = -cz;
        ull ncx, ncy, ncz;
        asm("mov.b64 %0, {%1,%1};" : "=l"(ncx) : "f"(mx));
        asm("mov.b64 %0, {%1,%1};" : "=l"(ncy) : "f"(my));
        asm("mov.b64 %0, {%1,%1};" : "=l"(ncz) : "f"(mz));

        float bv = -1.0f; int bi = 0;
#pragma unroll
        for (int t = 0; t < 2; t++) {
            ull dx, dy, dz, dd;
            asm("add.rn.f32x2 %0, %1, %2;" : "=l"(dx) : "l"(pxp[t]), "l"(ncx));
            asm("add.rn.f32x2 %0, %1, %2;" : "=l"(dy) : "l"(pyp[t]), "l"(ncy));
            asm("add.rn.f32x2 %0, %1, %2;" : "=l"(dz) : "l"(pzp[t]), "l"(ncz));
            asm("mul.rn.f32x2 %0, %1, %2;" : "=l"(dd) : "l"(dx), "l"(dx));
            asm("fma.rn.f32x2 %0, %1, %2, %3;" : "=l"(dd) : "l"(dy), "l"(dy), "l"(dd));
            asm("fma.rn.f32x2 %0, %1, %2, %3;" : "=l"(dd) : "l"(dz), "l"(dz), "l"(dd));
            float d0, d1;
            asm("mov.b64 {%0,%1}, %2;" : "=f"(d0), "=f"(d1) : "l"(dd));
            const float nd0 = fminf(dist[2*t],   d0);
            const float nd1 = fminf(dist[2*t+1], d1);
            dist[2*t]   = nd0;
            dist[2*t+1] = nd1;
            if (nd0 > bv) { bv = nd0; bi = tid + (2*t)   * 1024; }
            if (nd1 > bv) { bv = nd1; bi = tid + (2*t+1) * 1024; }
        }
        const unsigned vb = __float_as_uint(bv);
        const unsigned m  = __reduce_max_sync(0xffffffffu, vb);
        const unsigned lw = __reduce_max_sync(0xffffffffu,
                                              (vb == m) ? (0xFFFFu - (unsigned)bi) : 0u);
        const int buf = i & 1;
        if (lane == 0) { s_val[buf][wid] = m; s_low[buf][wid] = lw; }
        __syncthreads();

        const unsigned v2 = s_val[buf][lane];
        const unsigned l2 = s_low[buf][lane];
        const unsigned M  = __reduce_max_sync(0xffffffffu, v2);
        const unsigned LW = __reduce_max_sync(0xffffffffu, (v2 == M) ? l2 : 0u);
        far = 0xFFFF - (int)LW;
    }
}

// ---------------- ball query ----------------
__global__ __launch_bounds__(256) void ballquery_kernel(const float* __restrict__ xyz,
                                                        const float* __restrict__ new_xyz,
                                                        int* __restrict__ gidx)
{
    const int w    = blockIdx.x * 8 + (threadIdx.x >> 5);
    const int lane = threadIdx.x & 31;
    const int b    = w >> 10;
    const float* X = xyz + (size_t)b * NPTS * 3;

    const float cx = new_xyz[(size_t)w*3+0];
    const float cy = new_xyz[(size_t)w*3+1];
    const float cz = new_xyz[(size_t)w*3+2];
    const float ss = cx*cx + cy*cy + cz*cz;

    int cnt = 0, firstIdx = 0;
    int* out = gidx + (size_t)w * NSAMP;

    for (int base = 0; base < NPTS && cnt < NSAMP; base += 32) {
        const int j = base + lane;
        const float x = X[3*j], y = X[3*j+1], z = X[3*j+2];
        const float pp  = x*x + y*y + z*z;
        const float dot = x*cx + y*cy + z*cz;
        const float d   = (-2.0f*dot + ss) + pp;
        const bool  in  = !(d > RAD2);
        unsigned mask = __ballot_sync(0xffffffffu, in);
        if (cnt == 0 && mask) firstIdx = base + (__ffs(mask) - 1);
        int rank = __popc(mask & ((1u << lane) - 1u));
        int slot = cnt + rank;
        if (in && slot < NSAMP) out[slot] = j;
        cnt += __popc(mask);
    }
    for (int t = cnt + lane; t < NSAMP; t += 32) out[t] = firstIdx;
}

// ---------------- weight prep: W[K][N] f32 -> [KPAD][N] fp16 hi/lo (k-major) ----------------
__global__ __launch_bounds__(256) void prep_kernel(const float* __restrict__ W, int K, int N,
                                                   int KPAD,
                                                   __half* __restrict__ bh,
                                                   __half* __restrict__ bl)
{
    int i = blockIdx.x * 256 + threadIdx.x;
    if (i >= N * KPAD) return;
    int k = i / N, n = i - k * N;
    float v = (k < K) ? W[(size_t)k * N + n] : 0.f;
    __half h = __float2half_rn(v);
    bh[i] = h;
    bl[i] = __float2half_rn(v - __half2float(h));
}

// ---------------- HMMA GEMM (fp16, A-single + B-split: 2 MMAs), 256 threads ----------------
// AMODE: 0 = gather from xyz/points (layer 1), 1 = fp16-pair u32 input.
template<int BN, int NTOT, int KPAD, int KC, int KORIG, int AMODE,
         bool TRANSFORM, bool STORE_Y, bool FUSED_MAX, int MINB>
__global__ void __launch_bounds__(256, MINB) gemm_mma(
    const uint32_t* __restrict__ A,
    const int* __restrict__ gidxp, const float* __restrict__ xyzp,
    const float* __restrict__ pointsp, const float* __restrict__ nxyz,
    const __half* __restrict__ BH, const __half* __restrict__ BL,
    const float* __restrict__ bias,
    const float* __restrict__ scale, const float* __restrict__ shift,
    uint32_t* __restrict__ Y,
    float* __restrict__ partSum, float* __restrict__ partSq,
    float* __restrict__ gmax, float* __restrict__ gmin)
{
    extern __shared__ __align__(16) char dyn[];
    __shared__ int   sIdx[128];
    __shared__ float sCen[12];
    constexpr int LDA = KC + 8;     // halfs
    constexpr int LDB = BN + 8;
    constexpr int NCHUNK = KPAD / KC;
    __half* aS  = (__half*)dyn;
    __half* bHi = aS + 128 * LDA;
    __half* bLo = bHi + KC * LDB;

    const int tid = threadIdx.x;
    const int nb = blockIdx.x, mb = blockIdx.y;
    const int m0 = mb * 128, n0 = nb * BN;

    if (AMODE == 0) {
        if (tid < 128) sIdx[tid] = gidxp[m0 + tid];
        if (tid < 12)  sCen[tid] = nxyz[(size_t)(mb * 4) * 3 + tid];
        __syncthreads();
    }

    const int wid = tid >> 5, lane = tid & 31;
    const int wm = wid >> 1, wn = wid & 1;
    const int mW = wm * 32, nW = wn * (BN / 2);
    constexpr int NT = BN / 16;
    constexpr int KSTEPS_C = KC / 16;

    float acc[2][NT][4];
#pragma unroll
    for (int i = 0; i < 2; i++)
#pragma unroll
        for (int j = 0; j < NT; j++)
#pragma unroll
            for (int q = 0; q < 4; q++) acc[i][j][q] = 0.f;

    const uint32_t aU   = smem_u32(aS)  + (uint32_t)(mW + (lane & 15)) * (LDA * 2) + (lane >> 4) * 16;
    const uint32_t bHiU = smem_u32(bHi) + (uint32_t)(lane & 15) * (LDB * 2) + (uint32_t)nW * 2 + (lane >> 4) * 16;
    const uint32_t bLoU = smem_u32(bLo) + (uint32_t)(lane & 15) * (LDB * 2) + (uint32_t)nW * 2 + (lane >> 4) * 16;

    const int bb = m0 >> 15;
    const float* Xb = xyzp    ? xyzp    + (size_t)bb * NPTS * 3     : nullptr;
    const float* Pb = pointsp ? pointsp + (size_t)bb * NPTS * DFEAT : nullptr;

    for (int ch = 0; ch < NCHUNK; ch++) {
        const int kbase = ch * KC;
        if (ch > 0) __syncthreads();

        // ---- stage A chunk -> fp16 (single) ----
        constexpr int AIT = 128 * (KC / 2);
        for (int idx = tid; idx < AIT; idx += 256) {
            const int r  = idx / (KC / 2);
            const int p  = idx - r * (KC / 2);
            const int kl = 2 * p;
            const int kk = kbase + kl;
            float v0 = 0.f, v1 = 0.f;
            if (AMODE == 0) {
                const int j = sIdx[r];
                const int grp = (r >> 5) * 3;
                if (kk < 3)        v0 = Xb[j*3 + kk] - sCen[grp + kk];
                else if (kk < CH0) v0 = Pb[(size_t)j * DFEAT + kk - 3];
                const int c1 = kk + 1;
                if (c1 < 3)        v1 = Xb[j*3 + c1] - sCen[grp + c1];
                else if (c1 < CH0) v1 = Pb[(size_t)j * DFEAT + c1 - 3];
            } else {
                const uint32_t w = A[((size_t)(m0 + r) * KORIG + kk) >> 1];
                const float2 f = __half22float2(*(const __half2*)&w);
                v0 = f.x; v1 = f.y;
                if (TRANSFORM) {
                    v0 = fmaxf(fmaf(v0, __ldg(scale + kk),     __ldg(shift + kk)),     0.f);
                    v1 = fmaxf(fmaf(v1, __ldg(scale + kk + 1), __ldg(shift + kk + 1)), 0.f);
                }
            }
            *(uint32_t*)(aS + r * LDA + kl) = packh2(v0, v1);
        }
        // ---- stage B chunk ----
        constexpr int BIT = KC * (BN / 2);
        for (int idx = tid; idx < BIT; idx += 256) {
            const int k = idx / (BN / 2);
            const int n = 2 * (idx - k * (BN / 2));
            *(uint32_t*)(bHi + k * LDB + n) = *(const uint32_t*)(BH + (size_t)(kbase + k) * NTOT + n0 + n);
            *(uint32_t*)(bLo + k * LDB + n) = *(const uint32_t*)(BL + (size_t)(kbase + k) * NTOT + n0 + n);
        }
        __syncthreads();

        // ---- compute chunk: 2 MMAs per fragment pair ----
#pragma unroll
        for (int ks = 0; ks < KSTEPS_C; ks++) {
            uint32_t a0[4], a1[4];
            ldsm4(a0, aU + ks * 32);
            ldsm4(a1, aU + 16 * LDA * 2 + ks * 32);
#pragma unroll
            for (int ng = 0; ng < NT / 2; ng++) {
                uint32_t bh[4], bl[4];
                const uint32_t bo = (uint32_t)ks * (16 * LDB * 2) + ng * 32;
                ldsm4t(bh, bHiU + bo);
                ldsm4t(bl, bLoU + bo);
                mma_f16(acc[0][ng*2+0], a0, bh[0], bh[1]);
                mma_f16(acc[0][ng*2+0], a0, bl[0], bl[1]);
                mma_f16(acc[0][ng*2+1], a0, bh[2], bh[3]);
                mma_f16(acc[0][ng*2+1], a0, bl[2], bl[3]);
                mma_f16(acc[1][ng*2+0], a1, bh[0], bh[1]);
                mma_f16(acc[1][ng*2+0], a1, bl[0], bl[1]);
                mma_f16(acc[1][ng*2+1], a1, bh[2], bh[3]);
                mma_f16(acc[1][ng*2+1], a1, bl[2], bl[3]);
            }
        }
    }
    __syncthreads();

    // ---- epilogue ----
    float* sSum = (float*)dyn;            // [4][BN]
    float* sSq  = sSum + 4 * BN;          // [4][BN]

    const int r0 = lane >> 2;
#pragma unroll
    for (int nt = 0; nt < NT; nt++) {
        const int colLocal = nW + nt * 8 + (lane & 3) * 2;
        const float b0 = __ldg(bias + n0 + colLocal);
        const float b1 = __ldg(bias + n0 + colLocal + 1);
        float v0 = acc[0][nt][0] + b0, v1 = acc[0][nt][1] + b1;
        float v2 = acc[0][nt][2] + b0, v3 = acc[0][nt][3] + b1;
        float v4 = acc[1][nt][0] + b0, v5 = acc[1][nt][1] + b1;
        float v6 = acc[1][nt][2] + b0, v7 = acc[1][nt][3] + b1;
        if (STORE_Y) {
            const size_t base = ((size_t)(m0 + mW + r0) * NTOT + n0 + colLocal) >> 1;
            const size_t rstep = (size_t)8 * NTOT >> 1;
            Y[base]             = packh2(v0, v1);
            Y[base +     rstep] = packh2(v2, v3);
            Y[base + 2 * rstep] = packh2(v4, v5);
            Y[base + 3 * rstep] = packh2(v6, v7);
        }
        float s0 = v0+v2+v4+v6,              s1 = v1+v3+v5+v7;
        float q0 = v0*v0+v2*v2+v4*v4+v6*v6,  q1 = v1*v1+v3*v3+v5*v5+v7*v7;
        float mx0 = fmaxf(fmaxf(v0,v2), fmaxf(v4,v6)), mx1 = fmaxf(fmaxf(v1,v3), fmaxf(v5,v7));
        float mn0 = fminf(fminf(v0,v2), fminf(v4,v6)), mn1 = fminf(fminf(v1,v3), fminf(v5,v7));
#pragma unroll
        for (int d = 4; d < 32; d <<= 1) {
            s0 += __shfl_xor_sync(0xffffffffu, s0, d);
            s1 += __shfl_xor_sync(0xffffffffu, s1, d);
            q0 += __shfl_xor_sync(0xffffffffu, q0, d);
            q1 += __shfl_xor_sync(0xffffffffu, q1, d);
            mx0 = fmaxf(mx0, __shfl_xor_sync(0xffffffffu, mx0, d));
            mx1 = fmaxf(mx1, __shfl_xor_sync(0xffffffffu, mx1, d));
            mn0 = fminf(mn0, __shfl_xor_sync(0xffffffffu, mn0, d));
            mn1 = fminf(mn1, __shfl_xor_sync(0xffffffffu, mn1, d));
        }
        if (lane < 4) {
            sSum[wm*BN + colLocal] = s0;  sSum[wm*BN + colLocal + 1] = s1;
            sSq [wm*BN + colLocal] = q0;  sSq [wm*BN + colLocal + 1] = q1;
            if (FUSED_MAX) {
                const size_t grp = (size_t)(mb * 4 + wm) * CH3 + n0 + colLocal;
                gmax[grp]     = mx0;  gmax[grp + 1] = mx1;
                gmin[grp]     = mn0;  gmin[grp + 1] = mn1;
            }
        }
    }
    __syncthreads();
    for (int n = tid; n < BN; n += 256) {
        float s = sSum[n] + sSum[BN + n] + sSum[2*BN + n] + sSum[3*BN + n];
        float q = sSq [n] + sSq [BN + n] + sSq [2*BN + n] + sSq [3*BN + n];
        partSum[(size_t)(n0 + n) * MBLK + mb] = s;
        partSq [(size_t)(n0 + n) * MBLK + mb] = q;
    }
}

// ---------------- HMMA GEMM wide: 512 threads, BN=256 (layer 3) ----------------
template<int KPAD, int KC, int KORIG>
__global__ void __launch_bounds__(512, 1) gemm_mma_w3(
    const uint32_t* __restrict__ A,
    const __half* __restrict__ BH, const __half* __restrict__ BL,
    const float* __restrict__ bias,
    const float* __restrict__ scale, const float* __restrict__ shift,
    float* __restrict__ partSum, float* __restrict__ partSq,
    float* __restrict__ gmax, float* __restrict__ gmin)
{
    extern __shared__ __align__(16) char dyn[];
    constexpr int BN  = 256;
    constexpr int LDA = KC + 8;
    constexpr int LDB = BN + 8;
    constexpr int NCHUNK = KPAD / KC;
    __half* aS  = (__half*)dyn;
    __half* bHi = aS + 128 * LDA;
    __half* bLo = bHi + KC * LDB;

    const int tid = threadIdx.x;
    const int mb = blockIdx.x;
    const int m0 = mb * 128;

    const int wid = tid >> 5, lane = tid & 31;
    const int wm = wid >> 2, wn = wid & 3;
    const int mW = wm * 32, nW = wn * 64;
    constexpr int NT = 8;
    constexpr int KSTEPS_C = KC / 16;

    float acc[2][NT][4];
#pragma unroll
    for (int i = 0; i < 2; i++)
#pragma unroll
        for (int j = 0; j < NT; j++)
#pragma unroll
            for (int q = 0; q < 4; q++) acc[i][j][q] = 0.f;

    const uint32_t aU   = smem_u32(aS)  + (uint32_t)(mW + (lane & 15)) * (LDA * 2) + (lane >> 4) * 16;
    const uint32_t bHiU = smem_u32(bHi) + (uint32_t)(lane & 15) * (LDB * 2) + (uint32_t)nW * 2 + (lane >> 4) * 16;
    const uint32_t bLoU = smem_u32(bLo) + (uint32_t)(lane & 15) * (LDB * 2) + (uint32_t)nW * 2 + (lane >> 4) * 16;

    for (int ch = 0; ch < NCHUNK; ch++) {
        const int kbase = ch * KC;
        if (ch > 0) __syncthreads();

        constexpr int AIT = 128 * (KC / 2);
        for (int idx = tid; idx < AIT; idx += 512) {
            const int r  = idx / (KC / 2);
            const int p  = idx - r * (KC / 2);
            const int kl = 2 * p;
            const int kk = kbase + kl;
            const uint32_t w = A[((size_t)(m0 + r) * KORIG + kk) >> 1];
            const float2 f = __half22float2(*(const __half2*)&w);
            float v0 = fmaxf(fmaf(f.x, __ldg(scale + kk),     __ldg(shift + kk)),     0.f);
            float v1 = fmaxf(fmaf(f.y, __ldg(scale + kk + 1), __ldg(shift + kk + 1)), 0.f);
            *(uint32_t*)(aS + r * LDA + kl) = packh2(v0, v1);
        }
        constexpr int BIT = KC * (BN / 2);
        for (int idx = tid; idx < BIT; idx += 512) {
            const int k = idx / (BN / 2);
            const int n = 2 * (idx - k * (BN / 2));
            *(uint32_t*)(bHi + k * LDB + n) = *(const uint32_t*)(BH + (size_t)(kbase + k) * BN + n);
            *(uint32_t*)(bLo + k * LDB + n) = *(const uint32_t*)(BL + (size_t)(kbase + k) * BN + n);
        }
        __syncthreads();

#pragma unroll
        for (int ks = 0; ks < KSTEPS_C; ks++) {
            uint32_t a0[4], a1[4];
            ldsm4(a0, aU + ks * 32);
            ldsm4(a1, aU + 16 * LDA * 2 + ks * 32);
#pragma unroll
            for (int ng = 0; ng < NT / 2; ng++) {
                uint32_t bh[4], bl[4];
                const uint32_t bo = (uint32_t)ks * (16 * LDB * 2) + ng * 32;
                ldsm4t(bh, bHiU + bo);
                ldsm4t(bl, bLoU + bo);
                mma_f16(acc[0][ng*2+0], a0, bh[0], bh[1]);
                mma_f16(acc[0][ng*2+0], a0, bl[0], bl[1]);
                mma_f16(acc[0][ng*2+1], a0, bh[2], bh[3]);
                mma_f16(acc[0][ng*2+1], a0, bl[2], bl[3]);
                mma_f16(acc[1][ng*2+0], a1, bh[0], bh[1]);
                mma_f16(acc[1][ng*2+0], a1, bl[0], bl[1]);
                mma_f16(acc[1][ng*2+1], a1, bh[2], bh[3]);
                mma_f16(acc[1][ng*2+1], a1, bl[2], bl[3]);
            }
        }
    }
    __syncthreads();

    float* sSum = (float*)dyn;
    float* sSq  = sSum + 4 * BN;

#pragma unroll
    for (int nt = 0; nt < NT; nt++) {
        const int colLocal = nW + nt * 8 + (lane & 3) * 2;
        const float b0 = __ldg(bias + colLocal);
        const float b1 = __ldg(bias + colLocal + 1);
        float v0 = acc[0][nt][0] + b0, v1 = acc[0][nt][1] + b1;
        float v2 = acc[0][nt][2] + b0, v3 = acc[0][nt][3] + b1;
        float v4 = acc[1][nt][0] + b0, v5 = acc[1][nt][1] + b1;
        float v6 = acc[1][nt][2] + b0, v7 = acc[1][nt][3] + b1;
        float s0 = v0+v2+v4+v6,              s1 = v1+v3+v5+v7;
        float q0 = v0*v0+v2*v2+v4*v4+v6*v6,  q1 = v1*v1+v3*v3+v5*v5+v7*v7;
        float mx0 = fmaxf(fmaxf(v0,v2), fmaxf(v4,v6)), mx1 = fmaxf(fmaxf(v1,v3), fmaxf(v5,v7));
        float mn0 = fminf(fminf(v0,v2), fminf(v4,v6)), mn1 = fminf(fminf(v1,v3), fminf(v5,v7));
#pragma unroll
        for (int d = 4; d < 32; d <<= 1) {
            s0 += __shfl_xor_sync(0xffffffffu, s0, d);
            s1 += __shfl_xor_sync(0xffffffffu, s1, d);
            q0 += __shfl_xor_sync(0xffffffffu, q0, d);
            q1 += __shfl_xor_sync(0xffffffffu, q1, d);
            mx0 = fmaxf(mx0, __shfl_xor_sync(0xffffffffu, mx0, d));
            mx1 = fmaxf(mx1, __shfl_xor_sync(0xffffffffu, mx1, d));
            mn0 = fminf(mn0, __shfl_xor_sync(0xffffffffu, mn0, d));
            mn1 = fminf(mn1, __shfl_xor_sync(0xffffffffu, mn1, d));
        }
        if (lane < 4) {
            sSum[wm*BN + colLocal] = s0;  sSum[wm*BN + colLocal + 1] = s1;
            sSq [wm*BN + colLocal] = q0;  sSq [wm*BN + colLocal + 1] = q1;
            const size_t grp = (size_t)(mb * 4 + wm) * CH3 + colLocal;
            gmax[grp]     = mx0;  gmax[grp + 1] = mx1;
            gmin[grp]     = mn0;  gmin[grp + 1] = mn1;
        }
    }
    __syncthreads();
    for (int n = tid; n < BN; n += 512) {
        float s = sSum[n] + sSum[BN + n] + sSum[2*BN + n] + sSum[3*BN + n];
        float q = sSq [n] + sSq [BN + n] + sSq [2*BN + n] + sSq [3*BN + n];
        partSum[(size_t)n * MBLK + mb] = s;
        partSq [(size_t)n * MBLK + mb] = q;
    }
}

// ---------------- fold partials -> scale/shift ----------------
__global__ __launch_bounds__(256) void stats_kernel(const float* __restrict__ partSum,
                                                    const float* __restrict__ partSq,
                                                    int N,
                                                    const float* __restrict__ g,
                                                    const float* __restrict__ bt,
                                                    float* __restrict__ scale,
                                                    float* __restrict__ shift)
{
    const int c = blockIdx.x, tid = threadIdx.x;
    __shared__ float ss[256], sq[256];
    float a = 0.f, b2 = 0.f;
    const float* ps = partSum + (size_t)c * MBLK;
    const float* pq = partSq  + (size_t)c * MBLK;
    for (int mb = tid; mb < MBLK; mb += 256) {
        a  += ps[mb];
        b2 += pq[mb];
    }
    ss[tid] = a; sq[tid] = b2;
    __syncthreads();
    for (int s = 128; s > 0; s >>= 1) {
        if (tid < s) { ss[tid] += ss[tid+s]; sq[tid] += sq[tid+s]; }
        __syncthreads();
    }
    if (tid == 0) {
        const float invM = 1.0f / (float)MTOT;
        float mean = ss[0] * invM;
        float var  = sq[0] * invM - mean * mean;
        float sc   = g[c] / sqrtf(var + BNEPS);
        scale[c] = sc;
        shift[c] = bt[c] - mean * sc;
    }
}

// ---------------- final: pick max/min by sign(scale), affine+relu ----------------
__global__ __launch_bounds__(256) void finalpool_kernel(const float* __restrict__ gmax,
                                                        const float* __restrict__ gmin,
                                                        const float* __restrict__ scale,
                                                        const float* __restrict__ shift,
                                                        float* __restrict__ out)
{
    const int g = blockIdx.x, c = threadIdx.x;
    const float sc = scale[c], sh = shift[c];
    const float v = (sc >= 0.f) ? gmax[(size_t)g * CH3 + c] : gmin[(size_t)g * CH3 + c];
    out[(size_t)g * CH3 + c] = fmaxf(fmaf(v, sc, sh), 0.f);
}

// ---------------- launch ----------------
extern "C" void kernel_launch(void* const* d_in, const int* in_sizes, int n_in,
                              void* d_out, int out_size)
{
    const float* xyz    = (const float*)d_in[0];
    const float* points = (const float*)d_in[1];
    const float* w0  = (const float*)d_in[2];
    const float* b0  = (const float*)d_in[3];
    const float* g0  = (const float*)d_in[4];
    const float* bt0 = (const float*)d_in[5];
    const float* w1  = (const float*)d_in[6];
    const float* b1  = (const float*)d_in[7];
    const float* g1  = (const float*)d_in[8];
    const float* bt1 = (const float*)d_in[9];
    const float* w2  = (const float*)d_in[10];
    const float* b2  = (const float*)d_in[11];
    const float* g2  = (const float*)d_in[12];
    const float* bt2 = (const float*)d_in[13];

    float* out        = (float*)d_out;
    float* new_xyz    = out;
    float* new_points = out + (size_t)BATCH*SPTS*3;

    float *part, *scale, *shift, *gmax, *gmin;
    uint32_t *y1, *y2;
    int* gidx;
    __half *bh0, *bl0, *bh1, *bl1, *bh2, *bl2;
    cudaGetSymbolAddress((void**)&y1,    g_y1);
    cudaGetSymbolAddress((void**)&y2,    g_y2);
    cudaGetSymbolAddress((void**)&part,  g_part);
    cudaGetSymbolAddress((void**)&scale, g_scale);
    cudaGetSymbolAddress((void**)&shift, g_shift);
    cudaGetSymbolAddress((void**)&gidx,  g_gidx);
    cudaGetSymbolAddress((void**)&gmax,  g_gmax);
    cudaGetSymbolAddress((void**)&gmin,  g_gmin);
    cudaGetSymbolAddress((void**)&bh0,   g_bh0);
    cudaGetSymbolAddress((void**)&bl0,   g_bl0);
    cudaGetSymbolAddress((void**)&bh1,   g_bh1);
    cudaGetSymbolAddress((void**)&bl1,   g_bl1);
    cudaGetSymbolAddress((void**)&bh2,   g_bh2);
    cudaGetSymbolAddress((void**)&bl2,   g_bl2);

    float* partSum = part;
    float* partSq  = part + (size_t)MBLK * CH3;

    // smem bytes: (128*LDA + 2*KC*LDB) * 2
    constexpr int SM1 = (128*(80+8) + 2*80*(64+8))  * 2;   //  45,568
    constexpr int SM2 = (128*(64+8) + 2*64*(128+8)) * 2;   //  53,248
    constexpr int SMW = (128*(64+8) + 2*64*(256+8)) * 2;   //  86,016

    static bool attrDone = false;
    if (!attrDone) {
        cudaFuncSetAttribute(gemm_mma<64, 64, 80, 80, 67, 0, false, true, false, 2>,
                             cudaFuncAttributeMaxDynamicSharedMemorySize, SM1);
        cudaFuncSetAttribute(gemm_mma<128, 128, 64, 64, 64, 1, true, true, false, 2>,
                             cudaFuncAttributeMaxDynamicSharedMemorySize, SM2);
        cudaFuncSetAttribute(gemm_mma_w3<128, 64, 128>,
                             cudaFuncAttributeMaxDynamicSharedMemorySize, SMW);
        attrDone = true;
    }

    prep_kernel<<<(80*64 + 255)/256, 256>>>(w0, CH0, CH1, 80, bh0, bl0);
    prep_kernel<<<(64*128 + 255)/256, 256>>>(w1, CH1, CH2, 64, bh1, bl1);
    prep_kernel<<<(128*256 + 255)/256, 256>>>(w2, CH2, CH3, 128, bh2, bl2);

    fps_kernel<<<BATCH, 1024>>>(xyz, new_xyz);
    ballquery_kernel<<<BATCH*SPTS/8, 256>>>(xyz, new_xyz, gidx);

    // layer 1: 67 -> 64, gather fused into A-stage
    gemm_mma<64, 64, 80, 80, 67, 0, false, true, false, 2><<<dim3(1, MBLK), 256, SM1>>>(
        nullptr, gidx, xyz, points, new_xyz,
        bh0, bl0, b0, nullptr, nullptr, y1, partSum, partSq, nullptr, nullptr);
    stats_kernel<<<CH1, 256>>>(partSum, partSq, CH1, g0, bt0, scale, shift);

    // layer 2: 64 -> 128 (consumes fp16 y1)
    gemm_mma<128, 128, 64, 64, 64, 1, true, true, false, 2><<<dim3(1, MBLK), 256, SM2>>>(
        y1, nullptr, nullptr, nullptr, nullptr,
        bh1, bl1, b1, scale, shift, y2, partSum, partSq, nullptr, nullptr);
    stats_kernel<<<CH2, 256>>>(partSum, partSq, CH2, g1, bt1, scale, shift);

    // layer 3: 128 -> 256 wide CTA (consumes fp16 y2; fused per-group min/max)
    gemm_mma_w3<128, 64, 128><<<MBLK, 512, SMW>>>(
        y2, bh2, bl2, b2, scale, shift, partSum, partSq, gmax, gmin);
    stats_kernel<<<CH3, 256>>>(partSum, partSq, CH3, g2, bt2, scale, shift);

    finalpool_kernel<<<BATCH*SPTS, 256>>>(gmax, gmin, scale, shift, new_points);
}

// round 12
// speedup vs baseline: 2.3794x; 1.1286x over previous
#include <cuda_runtime.h>
#include <cuda_fp16.h>
#include <math.h>
#include <stdint.h>

// ---------------- problem constants ----------------
#define BATCH 16
#define NPTS  4096
#define DFEAT 64
#define SPTS  1024
#define NSAMP 32
#define CH0   67
#define CH1   64
#define CH2   128
#define CH3   256
#define MTOT  (BATCH*SPTS*NSAMP)   // 524288
#define MBLK  (MTOT/128)           // 4096
#define RAD2  0.04f
#define BNEPS 1e-5f

typedef unsigned long long ull;

// ---------------- device scratch ----------------
__device__ float    g_G[(size_t)BATCH*NPTS*CH1];   // per-point partial layer1 (f32, 16.7MB)
__device__ uint32_t g_y1[(size_t)MTOT*CH1/2];      // fp16 pairs
__device__ uint32_t g_y2[(size_t)MTOT*CH2/2];      // fp16 pairs
__device__ int   g_gidx[BATCH*SPTS*NSAMP];
__device__ float g_part[2*(size_t)MBLK*CH3];       // transposed [n][MBLK]
__device__ float g_scale[CH3];
__device__ float g_shift[CH3];
__device__ float g_gmax[(size_t)BATCH*SPTS*CH3];
__device__ float g_gmin[(size_t)BATCH*SPTS*CH3];
// weights prepped k-major [KPAD][N], fp16 hi/lo
__device__ __half g_bh0[80*64],   g_bl0[80*64];    // reused for W0 point-part [64][64]
__device__ __half g_bh1[64*128],  g_bl1[64*128];
__device__ __half g_bh2[128*256], g_bl2[128*256];

// ---------------- helpers ----------------
__device__ __forceinline__ uint32_t smem_u32(const void* p) {
    uint32_t a;
    asm("{ .reg .u64 t; cvta.to.shared.u64 t, %1; cvt.u32.u64 %0, t; }" : "=r"(a) : "l"(p));
    return a;
}
__device__ __forceinline__ void ldsm4(uint32_t* r, uint32_t a) {
    asm volatile("ldmatrix.sync.aligned.m8n8.x4.shared.b16 {%0,%1,%2,%3}, [%4];"
                 : "=r"(r[0]), "=r"(r[1]), "=r"(r[2]), "=r"(r[3]) : "r"(a));
}
__device__ __forceinline__ void ldsm4t(uint32_t* r, uint32_t a) {
    asm volatile("ldmatrix.sync.aligned.m8n8.x4.trans.shared.b16 {%0,%1,%2,%3}, [%4];"
                 : "=r"(r[0]), "=r"(r[1]), "=r"(r[2]), "=r"(r[3]) : "r"(a));
}
__device__ __forceinline__ void mma_f16(float* c, const uint32_t* a, uint32_t b0, uint32_t b1) {
    asm volatile(
        "mma.sync.aligned.m16n8k16.row.col.f32.f16.f16.f32 "
        "{%0,%1,%2,%3}, {%4,%5,%6,%7}, {%8,%9}, {%0,%1,%2,%3};"
        : "+f"(c[0]), "+f"(c[1]), "+f"(c[2]), "+f"(c[3])
        : "r"(a[0]), "r"(a[1]), "r"(a[2]), "r"(a[3]), "r"(b0), "r"(b1));
}
__device__ __forceinline__ uint32_t packh2(float v0, float v1) {
    __half2 h = __floats2half2_rn(v0, v1);   // v0 -> low, v1 -> high
    return *(uint32_t*)&h;
}

// ---------------- FPS (512 threads, packed f32x2, REDUX tails — R8 best) ----------------
__global__ __launch_bounds__(512) void fps_kernel(const float* __restrict__ xyz,
                                                  float* __restrict__ new_xyz)
{
    __shared__ float sx[NPTS], sy[NPTS], sz[NPTS];
    __shared__ unsigned s_val[2][16], s_low[2][16];
    const int b = blockIdx.x, tid = threadIdx.x;
    const int lane = tid & 31, wid = tid >> 5;
    const float* X = xyz + (size_t)b * NPTS * 3;

    ull pxp[4], pyp[4], pzp[4];
    float dist[8];
#pragma unroll
    for (int t = 0; t < 8; t++) dist[t] = 1e10f;
#pragma unroll
    for (int t = 0; t < 4; t++) {
        const int j0 = tid + (2*t) * 512, j1 = tid + (2*t+1) * 512;
        float x0 = X[3*j0], y0 = X[3*j0+1], z0 = X[3*j0+2];
        float x1 = X[3*j1], y1 = X[3*j1+1], z1 = X[3*j1+2];
        sx[j0] = x0; sy[j0] = y0; sz[j0] = z0;
        sx[j1] = x1; sy[j1] = y1; sz[j1] = z1;
        asm("mov.b64 %0, {%1,%2};" : "=l"(pxp[t]) : "f"(x0), "f"(x1));
        asm("mov.b64 %0, {%1,%2};" : "=l"(pyp[t]) : "f"(y0), "f"(y1));
        asm("mov.b64 %0, {%1,%2};" : "=l"(pzp[t]) : "f"(z0), "f"(z1));
    }
    __syncthreads();

    int far = 0;
    for (int i = 0; i < SPTS; i++) {
        const float cx = sx[far], cy = sy[far], cz = sz[far];
        if (tid == 0) {
            float* o = new_xyz + ((size_t)b * SPTS + i) * 3;
            o[0] = cx; o[1] = cy; o[2] = cz;
        }
        if (i == SPTS - 1) break;

        const float mx = -cx, my = -cy, mz = -cz;
        ull ncx, ncy, ncz;
        asm("mov.b64 %0, {%1,%1};" : "=l"(ncx) : "f"(mx));
        asm("mov.b64 %0, {%1,%1};" : "=l"(ncy) : "f"(my));
        asm("mov.b64 %0, {%1,%1};" : "=l"(ncz) : "f"(mz));

        float bv = -1.0f; int bi = 0;
#pragma unroll
        for (int t = 0; t < 4; t++) {
            ull dx, dy, dz, dd;
            asm("add.rn.f32x2 %0, %1, %2;" : "=l"(dx) : "l"(pxp[t]), "l"(ncx));
            asm("add.rn.f32x2 %0, %1, %2;" : "=l"(dy) : "l"(pyp[t]), "l"(ncy));
            asm("add.rn.f32x2 %0, %1, %2;" : "=l"(dz) : "l"(pzp[t]), "l"(ncz));
            asm("mul.rn.f32x2 %0, %1, %2;" : "=l"(dd) : "l"(dx), "l"(dx));
            asm("fma.rn.f32x2 %0, %1, %2, %3;" : "=l"(dd) : "l"(dy), "l"(dy), "l"(dd));
            asm("fma.rn.f32x2 %0, %1, %2, %3;" : "=l"(dd) : "l"(dz), "l"(dz), "l"(dd));
            float d0, d1;
            asm("mov.b64 {%0,%1}, %2;" : "=f"(d0), "=f"(d1) : "l"(dd));
            const float nd0 = fminf(dist[2*t],   d0);
            const float nd1 = fminf(dist[2*t+1], d1);
            dist[2*t]   = nd0;
            dist[2*t+1] = nd1;
            if (nd0 > bv) { bv = nd0; bi = tid + (2*t)   * 512; }
            if (nd1 > bv) { bv = nd1; bi = tid + (2*t+1) * 512; }
        }
        const unsigned vb = __float_as_uint(bv);
        const unsigned m  = __reduce_max_sync(0xffffffffu, vb);
        const unsigned lw = __reduce_max_sync(0xffffffffu,
                                              (vb == m) ? (0xFFFFu - (unsigned)bi) : 0u);
        const int buf = i & 1;
        if (lane == 0) { s_val[buf][wid] = m; s_low[buf][wid] = lw; }
        __syncthreads();

        const unsigned v2 = s_val[buf][lane & 15];
        const unsigned l2 = s_low[buf][lane & 15];
        const unsigned M  = __reduce_max_sync(0xffffffffu, v2);
        const unsigned LW = __reduce_max_sync(0xffffffffu, (v2 == M) ? l2 : 0u);
        far = 0xFFFF - (int)LW;
    }
}

// ---------------- ball query ----------------
__global__ __launch_bounds__(256) void ballquery_kernel(const float* __restrict__ xyz,
                                                        const float* __restrict__ new_xyz,
                                                        int* __restrict__ gidx)
{
    const int w    = blockIdx.x * 8 + (threadIdx.x >> 5);
    const int lane = threadIdx.x & 31;
    const int b    = w >> 10;
    const float* X = xyz + (size_t)b * NPTS * 3;

    const float cx = new_xyz[(size_t)w*3+0];
    const float cy = new_xyz[(size_t)w*3+1];
    const float cz = new_xyz[(size_t)w*3+2];
    const float ss = cx*cx + cy*cy + cz*cz;

    int cnt = 0, firstIdx = 0;
    int* out = gidx + (size_t)w * NSAMP;

    for (int base = 0; base < NPTS && cnt < NSAMP; base += 32) {
        const int j = base + lane;
        const float x = X[3*j], y = X[3*j+1], z = X[3*j+2];
        const float pp  = x*x + y*y + z*z;
        const float dot = x*cx + y*cy + z*cz;
        const float d   = (-2.0f*dot + ss) + pp;
        const bool  in  = !(d > RAD2);
        unsigned mask = __ballot_sync(0xffffffffu, in);
        if (cnt == 0 && mask) firstIdx = base + (__ffs(mask) - 1);
        int rank = __popc(mask & ((1u << lane) - 1u));
        int slot = cnt + rank;
        if (in && slot < NSAMP) out[slot] = j;
        cnt += __popc(mask);
    }
    for (int t = cnt + lane; t < NSAMP; t += 32) out[t] = firstIdx;
}

// ---------------- weight prep: W rows [KOFF, KOFF+K) -> [KPAD][N] fp16 hi/lo ----------------
__global__ __launch_bounds__(256) void prep_kernel(const float* __restrict__ W, int K, int N,
                                                   int KPAD, int KOFF,
                                                   __half* __restrict__ bh,
                                                   __half* __restrict__ bl)
{
    int i = blockIdx.x * 256 + threadIdx.x;
    if (i >= N * KPAD) return;
    int k = i / N, n = i - k * N;
    float v = (k < K) ? W[(size_t)(k + KOFF) * N + n] : 0.f;
    __half h = __float2half_rn(v);
    bh[i] = h;
    bl[i] = __float2half_rn(v - __half2float(h));
}

// ---------------- HMMA GEMM (fp16, A-single + B-split: 2 MMAs), 256 threads ----------------
// AMODE: 1 = fp16-pair u32 input, 2 = f32 row-major input (via fA).
template<int BN, int NTOT, int KPAD, int KC, int KORIG, int AMODE,
         bool TRANSFORM, bool STORE_Y, bool YF32, bool PART, int MINB>
__global__ void __launch_bounds__(256, MINB) gemm_mma(
    const uint32_t* __restrict__ A, const float* __restrict__ fA,
    const __half* __restrict__ BH, const __half* __restrict__ BL,
    const float* __restrict__ bias,
    const float* __restrict__ scale, const float* __restrict__ shift,
    uint32_t* __restrict__ Y,
    float* __restrict__ partSum, float* __restrict__ partSq)
{
    extern __shared__ __align__(16) char dyn[];
    constexpr int LDA = KC + 8;     // halfs
    constexpr int LDB = BN + 8;
    constexpr int NCHUNK = KPAD / KC;
    __half* aS  = (__half*)dyn;
    __half* bHi = aS + 128 * LDA;
    __half* bLo = bHi + KC * LDB;

    const int tid = threadIdx.x;
    const int nb = blockIdx.x, mb = blockIdx.y;
    const int m0 = mb * 128, n0 = nb * BN;

    const int wid = tid >> 5, lane = tid & 31;
    const int wm = wid >> 1, wn = wid & 1;
    const int mW = wm * 32, nW = wn * (BN / 2);
    constexpr int NT = BN / 16;
    constexpr int KSTEPS_C = KC / 16;

    float acc[2][NT][4];
#pragma unroll
    for (int i = 0; i < 2; i++)
#pragma unroll
        for (int j = 0; j < NT; j++)
#pragma unroll
            for (int q = 0; q < 4; q++) acc[i][j][q] = 0.f;

    const uint32_t aU   = smem_u32(aS)  + (uint32_t)(mW + (lane & 15)) * (LDA * 2) + (lane >> 4) * 16;
    const uint32_t bHiU = smem_u32(bHi) + (uint32_t)(lane & 15) * (LDB * 2) + (uint32_t)nW * 2 + (lane >> 4) * 16;
    const uint32_t bLoU = smem_u32(bLo) + (uint32_t)(lane & 15) * (LDB * 2) + (uint32_t)nW * 2 + (lane >> 4) * 16;

    for (int ch = 0; ch < NCHUNK; ch++) {
        const int kbase = ch * KC;
        if (ch > 0) __syncthreads();

        // ---- stage A chunk -> fp16 (single) ----
        constexpr int AIT = 128 * (KC / 2);
        for (int idx = tid; idx < AIT; idx += 256) {
            const int r  = idx / (KC / 2);
            const int p  = idx - r * (KC / 2);
            const int kl = 2 * p;
            const int kk = kbase + kl;
            float v0, v1;
            if (AMODE == 2) {
                const float2 f = *(const float2*)(fA + (size_t)(m0 + r) * KORIG + kk);
                v0 = f.x; v1 = f.y;
            } else {
                const uint32_t w = A[((size_t)(m0 + r) * KORIG + kk) >> 1];
                const float2 f = __half22float2(*(const __half2*)&w);
                v0 = f.x; v1 = f.y;
                if (TRANSFORM) {
                    v0 = fmaxf(fmaf(v0, __ldg(scale + kk),     __ldg(shift + kk)),     0.f);
                    v1 = fmaxf(fmaf(v1, __ldg(scale + kk + 1), __ldg(shift + kk + 1)), 0.f);
                }
            }
            *(uint32_t*)(aS + r * LDA + kl) = packh2(v0, v1);
        }
        // ---- stage B chunk ----
        constexpr int BIT = KC * (BN / 2);
        for (int idx = tid; idx < BIT; idx += 256) {
            const int k = idx / (BN / 2);
            const int n = 2 * (idx - k * (BN / 2));
            *(uint32_t*)(bHi + k * LDB + n) = *(const uint32_t*)(BH + (size_t)(kbase + k) * NTOT + n0 + n);
            *(uint32_t*)(bLo + k * LDB + n) = *(const uint32_t*)(BL + (size_t)(kbase + k) * NTOT + n0 + n);
        }
        __syncthreads();

        // ---- compute chunk: 2 MMAs per fragment pair ----
#pragma unroll
        for (int ks = 0; ks < KSTEPS_C; ks++) {
            uint32_t a0[4], a1[4];
            ldsm4(a0, aU + ks * 32);
            ldsm4(a1, aU + 16 * LDA * 2 + ks * 32);
#pragma unroll
            for (int ng = 0; ng < NT / 2; ng++) {
                uint32_t bh[4], bl[4];
                const uint32_t bo = (uint32_t)ks * (16 * LDB * 2) + ng * 32;
                ldsm4t(bh, bHiU + bo);
                ldsm4t(bl, bLoU + bo);
                mma_f16(acc[0][ng*2+0], a0, bh[0], bh[1]);
                mma_f16(acc[0][ng*2+0], a0, bl[0], bl[1]);
                mma_f16(acc[0][ng*2+1], a0, bh[2], bh[3]);
                mma_f16(acc[0][ng*2+1], a0, bl[2], bl[3]);
                mma_f16(acc[1][ng*2+0], a1, bh[0], bh[1]);
                mma_f16(acc[1][ng*2+0], a1, bl[0], bl[1]);
                mma_f16(acc[1][ng*2+1], a1, bh[2], bh[3]);
                mma_f16(acc[1][ng*2+1], a1, bl[2], bl[3]);
            }
        }
    }
    __syncthreads();

    // ---- epilogue ----
    float* sSum = (float*)dyn;            // [4][BN]
    float* sSq  = sSum + 4 * BN;          // [4][BN]

    const int r0 = lane >> 2;
#pragma unroll
    for (int nt = 0; nt < NT; nt++) {
        const int colLocal = nW + nt * 8 + (lane & 3) * 2;
        const float b0 = __ldg(bias + n0 + colLocal);
        const float b1 = __ldg(bias + n0 + colLocal + 1);
        float v0 = acc[0][nt][0] + b0, v1 = acc[0][nt][1] + b1;
        float v2 = acc[0][nt][2] + b0, v3 = acc[0][nt][3] + b1;
        float v4 = acc[1][nt][0] + b0, v5 = acc[1][nt][1] + b1;
        float v6 = acc[1][nt][2] + b0, v7 = acc[1][nt][3] + b1;
        if (STORE_Y) {
            if (YF32) {
                float* yf = (float*)Y;
                const size_t base = (size_t)(m0 + mW + r0) * NTOT + n0 + colLocal;
                *(float2*)(yf + base)            = make_float2(v0, v1);
                *(float2*)(yf + base +  8*NTOT)  = make_float2(v2, v3);
                *(float2*)(yf + base + 16*NTOT)  = make_float2(v4, v5);
                *(float2*)(yf + base + 24*NTOT)  = make_float2(v6, v7);
            } else {
                const size_t base = ((size_t)(m0 + mW + r0) * NTOT + n0 + colLocal) >> 1;
                const size_t rstep = (size_t)8 * NTOT >> 1;
                Y[base]             = packh2(v0, v1);
                Y[base +     rstep] = packh2(v2, v3);
                Y[base + 2 * rstep] = packh2(v4, v5);
                Y[base + 3 * rstep] = packh2(v6, v7);
            }
        }
        if (PART) {
            float s0 = v0+v2+v4+v6,              s1 = v1+v3+v5+v7;
            float q0 = v0*v0+v2*v2+v4*v4+v6*v6,  q1 = v1*v1+v3*v3+v5*v5+v7*v7;
#pragma unroll
            for (int d = 4; d < 32; d <<= 1) {
                s0 += __shfl_xor_sync(0xffffffffu, s0, d);
                s1 += __shfl_xor_sync(0xffffffffu, s1, d);
                q0 += __shfl_xor_sync(0xffffffffu, q0, d);
                q1 += __shfl_xor_sync(0xffffffffu, q1, d);
            }
            if (lane < 4) {
                sSum[wm*BN + colLocal] = s0;  sSum[wm*BN + colLocal + 1] = s1;
                sSq [wm*BN + colLocal] = q0;  sSq [wm*BN + colLocal + 1] = q1;
            }
        }
    }
    if (PART) {
        __syncthreads();
        for (int n = tid; n < BN; n += 256) {
            float s = sSum[n] + sSum[BN + n] + sSum[2*BN + n] + sSum[3*BN + n];
            float q = sSq [n] + sSq [BN + n] + sSq [2*BN + n] + sSq [3*BN + n];
            partSum[(size_t)(n0 + n) * MBLK + mb] = s;
            partSq [(size_t)(n0 + n) * MBLK + mb] = q;
        }
    }
}

// ---------------- HMMA GEMM wide: 512 threads, BN=256 (layer 3) ----------------
template<int KPAD, int KC, int KORIG>
__global__ void __launch_bounds__(512, 1) gemm_mma_w3(
    const uint32_t* __restrict__ A,
    const __half* __restrict__ BH, const __half* __restrict__ BL,
    const float* __restrict__ bias,
    const float* __restrict__ scale, const float* __restrict__ shift,
    float* __restrict__ partSum, float* __restrict__ partSq,
    float* __restrict__ gmax, float* __restrict__ gmin)
{
    extern __shared__ __align__(16) char dyn[];
    constexpr int BN  = 256;
    constexpr int LDA = KC + 8;
    constexpr int LDB = BN + 8;
    constexpr int NCHUNK = KPAD / KC;
    __half* aS  = (__half*)dyn;
    __half* bHi = aS + 128 * LDA;
    __half* bLo = bHi + KC * LDB;

    const int tid = threadIdx.x;
    const int mb = blockIdx.x;
    const int m0 = mb * 128;

    const int wid = tid >> 5, lane = tid & 31;
    const int wm = wid >> 2, wn = wid & 3;
    const int mW = wm * 32, nW = wn * 64;
    constexpr int NT = 8;
    constexpr int KSTEPS_C = KC / 16;

    float acc[2][NT][4];
#pragma unroll
    for (int i = 0; i < 2; i++)
#pragma unroll
        for (int j = 0; j < NT; j++)
#pragma unroll
            for (int q = 0; q < 4; q++) acc[i][j][q] = 0.f;

    const uint32_t aU   = smem_u32(aS)  + (uint32_t)(mW + (lane & 15)) * (LDA * 2) + (lane >> 4) * 16;
    const uint32_t bHiU = smem_u32(bHi) + (uint32_t)(lane & 15) * (LDB * 2) + (uint32_t)nW * 2 + (lane >> 4) * 16;
    const uint32_t bLoU = smem_u32(bLo) + (uint32_t)(lane & 15) * (LDB * 2) + (uint32_t)nW * 2 + (lane >> 4) * 16;

    for (int ch = 0; ch < NCHUNK; ch++) {
        const int kbase = ch * KC;
        if (ch > 0) __syncthreads();

        constexpr int AIT = 128 * (KC / 2);
        for (int idx = tid; idx < AIT; idx += 512) {
            const int r  = idx / (KC / 2);
            const int p  = idx - r * (KC / 2);
            const int kl = 2 * p;
            const int kk = kbase + kl;
            const uint32_t w = A[((size_t)(m0 + r) * KORIG + kk) >> 1];
            const float2 f = __half22float2(*(const __half2*)&w);
            float v0 = fmaxf(fmaf(f.x, __ldg(scale + kk),     __ldg(shift + kk)),     0.f);
            float v1 = fmaxf(fmaf(f.y, __ldg(scale + kk + 1), __ldg(shift + kk + 1)), 0.f);
            *(uint32_t*)(aS + r * LDA + kl) = packh2(v0, v1);
        }
        constexpr int BIT = KC * (BN / 2);
        for (int idx = tid; idx < BIT; idx += 512) {
            const int k = idx / (BN / 2);
            const int n = 2 * (idx - k * (BN / 2));
            *(uint32_t*)(bHi + k * LDB + n) = *(const uint32_t*)(BH + (size_t)(kbase + k) * BN + n);
            *(uint32_t*)(bLo + k * LDB + n) = *(const uint32_t*)(BL + (size_t)(kbase + k) * BN + n);
        }
        __syncthreads();

#pragma unroll
        for (int ks = 0; ks < KSTEPS_C; ks++) {
            uint32_t a0[4], a1[4];
            ldsm4(a0, aU + ks * 32);
            ldsm4(a1, aU + 16 * LDA * 2 + ks * 32);
#pragma unroll
            for (int ng = 0; ng < NT / 2; ng++) {
                uint32_t bh[4], bl[4];
                const uint32_t bo = (uint32_t)ks * (16 * LDB * 2) + ng * 32;
                ldsm4t(bh, bHiU + bo);
                ldsm4t(bl, bLoU + bo);
                mma_f16(acc[0][ng*2+0], a0, bh[0], bh[1]);
                mma_f16(acc[0][ng*2+0], a0, bl[0], bl[1]);
                mma_f16(acc[0][ng*2+1], a0, bh[2], bh[3]);
                mma_f16(acc[0][ng*2+1], a0, bl[2], bl[3]);
                mma_f16(acc[1][ng*2+0], a1, bh[0], bh[1]);
                mma_f16(acc[1][ng*2+0], a1, bl[0], bl[1]);
                mma_f16(acc[1][ng*2+1], a1, bh[2], bh[3]);
                mma_f16(acc[1][ng*2+1], a1, bl[2], bl[3]);
            }
        }
    }
    __syncthreads();

    float* sSum = (float*)dyn;
    float* sSq  = sSum + 4 * BN;

#pragma unroll
    for (int nt = 0; nt < NT; nt++) {
        const int colLocal = nW + nt * 8 + (lane & 3) * 2;
        const float b0 = __ldg(bias + colLocal);
        const float b1 = __ldg(bias + colLocal + 1);
        float v0 = acc[0][nt][0] + b0, v1 = acc[0][nt][1] + b1;
        float v2 = acc[0][nt][2] + b0, v3 = acc[0][nt][3] + b1;
        float v4 = acc[1][nt][0] + b0, v5 = acc[1][nt][1] + b1;
        float v6 = acc[1][nt][2] + b0, v7 = acc[1][nt][3] + b1;
        float s0 = v0+v2+v4+v6,              s1 = v1+v3+v5+v7;
        float q0 = v0*v0+v2*v2+v4*v4+v6*v6,  q1 = v1*v1+v3*v3+v5*v5+v7*v7;
        float mx0 = fmaxf(fmaxf(v0,v2), fmaxf(v4,v6)), mx1 = fmaxf(fmaxf(v1,v3), fmaxf(v5,v7));
        float mn0 = fminf(fminf(v0,v2), fminf(v4,v6)), mn1 = fminf(fminf(v1,v3), fminf(v5,v7));
#pragma unroll
        for (int d = 4; d < 32; d <<= 1) {
            s0 += __shfl_xor_sync(0xffffffffu, s0, d);
            s1 += __shfl_xor_sync(0xffffffffu, s1, d);
            q0 += __shfl_xor_sync(0xffffffffu, q0, d);
            q1 += __shfl_xor_sync(0xffffffffu, q1, d);
            mx0 = fmaxf(mx0, __shfl_xor_sync(0xffffffffu, mx0, d));
            mx1 = fmaxf(mx1, __shfl_xor_sync(0xffffffffu, mx1, d));
            mn0 = fminf(mn0, __shfl_xor_sync(0xffffffffu, mn0, d));
            mn1 = fminf(mn1, __shfl_xor_sync(0xffffffffu, mn1, d));
        }
        if (lane < 4) {
            sSum[wm*BN + colLocal] = s0;  sSum[wm*BN + colLocal + 1] = s1;
            sSq [wm*BN + colLocal] = q0;  sSq [wm*BN + colLocal + 1] = q1;
            const size_t grp = (size_t)(mb * 4 + wm) * CH3 + colLocal;
            gmax[grp]     = mx0;  gmax[grp + 1] = mx1;
            gmin[grp]     = mn0;  gmin[grp + 1] = mn1;
        }
    }
    __syncthreads();
    for (int n = tid; n < BN; n += 512) {
        float s = sSum[n] + sSum[BN + n] + sSum[2*BN + n] + sSum[3*BN + n];
        float q = sSq [n] + sSq [BN + n] + sSq [2*BN + n] + sSq [3*BN + n];
        partSum[(size_t)n * MBLK + mb] = s;
        partSq [(size_t)n * MBLK + mb] = q;
    }
}

// ---------------- y1build: y1 = G[j] + xyz_norm . W0[0:3]  (+ BN partials) ----------------
__global__ __launch_bounds__(256) void y1build_kernel(
    const float* __restrict__ G, const int* __restrict__ gidx,
    const float* __restrict__ xyz, const float* __restrict__ nxyz,
    const float* __restrict__ w0,
    uint32_t* __restrict__ y1,
    float* __restrict__ partSum, float* __restrict__ partSq)
{
    __shared__ int   sIdx[128];
    __shared__ float sCen[12];
    __shared__ float sW[192];          // W0 rows 0..2, [3][64]
    __shared__ float sXn[128*3];
    __shared__ float sRed[1024];       // [2][8][64]
    const int mb = blockIdx.x, m0 = mb * 128, tid = threadIdx.x;
    const int b = mb >> 8;             // 256 M-blocks per batch

    if (tid < 128) sIdx[tid] = gidx[m0 + tid];
    if (tid < 12)  sCen[tid] = nxyz[(size_t)(mb * 4) * 3 + tid];
    if (tid < 192) sW[tid]   = w0[tid];
    __syncthreads();
    if (tid < 128) {
        const int g = tid >> 5;
        const int j = sIdx[tid];
        const float* xp = xyz + ((size_t)b * NPTS + j) * 3;
        sXn[tid*3+0] = xp[0] - sCen[g*3+0];
        sXn[tid*3+1] = xp[1] - sCen[g*3+1];
        sXn[tid*3+2] = xp[2] - sCen[g*3+2];
    }
    __syncthreads();

    const int cp = tid & 31;           // column pair (cols 2cp, 2cp+1)
    const int rg = tid >> 5;           // row group 0..7 (16 rows each)
    const int c0 = 2 * cp;
    const float wx0 = sW[c0],      wy0 = sW[64+c0],   wz0 = sW[128+c0];
    const float wx1 = sW[c0+1],    wy1 = sW[64+c0+1], wz1 = sW[128+c0+1];

    float s0 = 0.f, s1 = 0.f, q0 = 0.f, q1 = 0.f;
#pragma unroll 4
    for (int rr = 0; rr < 16; rr++) {
        const int r = rg * 16 + rr;
        const int j = sIdx[r];
        const float xn = sXn[r*3], yn = sXn[r*3+1], zn = sXn[r*3+2];
        const float2 gv = *(const float2*)(G + ((size_t)b * NPTS + j) * CH1 + c0);
        float v0 = fmaf(zn, wz0, fmaf(yn, wy0, fmaf(xn, wx0, gv.x)));
        float v1 = fmaf(zn, wz1, fmaf(yn, wy1, fmaf(xn, wx1, gv.y)));
        y1[(size_t)(m0 + r) * (CH1/2) + cp] = packh2(v0, v1);
        s0 += v0; s1 += v1; q0 += v0*v0; q1 += v1*v1;
    }
    sRed[rg*64 + c0]       = s0;  sRed[rg*64 + c0 + 1]       = s1;
    sRed[512 + rg*64 + c0] = q0;  sRed[512 + rg*64 + c0 + 1] = q1;
    __syncthreads();
    if (rg == 0) {
        float S0 = 0.f, S1 = 0.f, Q0 = 0.f, Q1 = 0.f;
#pragma unroll
        for (int g2 = 0; g2 < 8; g2++) {
            S0 += sRed[g2*64 + c0];       S1 += sRed[g2*64 + c0 + 1];
            Q0 += sRed[512 + g2*64 + c0]; Q1 += sRed[512 + g2*64 + c0 + 1];
        }
        partSum[(size_t)c0 * MBLK + mb]       = S0;
        partSum[(size_t)(c0 + 1) * MBLK + mb] = S1;
        partSq [(size_t)c0 * MBLK + mb]       = Q0;
        partSq [(size_t)(c0 + 1) * MBLK + mb] = Q1;
    }
}

// ---------------- fold partials -> scale/shift ----------------
__global__ __launch_bounds__(256) void stats_kernel(const float* __restrict__ partSum,
                                                    const float* __restrict__ partSq,
                                                    int N,
                                                    const float* __restrict__ g,
                                                    const float* __restrict__ bt,
                                                    float* __restrict__ scale,
                                                    float* __restrict__ shift)
{
    const int c = blockIdx.x, tid = threadIdx.x;
    __shared__ float ss[256], sq[256];
    float a = 0.f, b2 = 0.f;
    const float* ps = partSum + (size_t)c * MBLK;
    const float* pq = partSq  + (size_t)c * MBLK;
    for (int mb = tid; mb < MBLK; mb += 256) {
        a  += ps[mb];
        b2 += pq[mb];
    }
    ss[tid] = a; sq[tid] = b2;
    __syncthreads();
    for (int s = 128; s > 0; s >>= 1) {
        if (tid < s) { ss[tid] += ss[tid+s]; sq[tid] += sq[tid+s]; }
        __syncthreads();
    }
    if (tid == 0) {
        const float invM = 1.0f / (float)MTOT;
        float mean = ss[0] * invM;
        float var  = sq[0] * invM - mean * mean;
        float sc   = g[c] / sqrtf(var + BNEPS);
        scale[c] = sc;
        shift[c] = bt[c] - mean * sc;
    }
}

// ---------------- final: pick max/min by sign(scale), affine+relu ----------------
__global__ __launch_bounds__(256) void finalpool_kernel(const float* __restrict__ gmax,
                                                        const float* __restrict__ gmin,
                                                        const float* __restrict__ scale,
                                                        const float* __restrict__ shift,
                                                        float* __restrict__ out)
{
    const int g = blockIdx.x, c = threadIdx.x;
    const float sc = scale[c], sh = shift[c];
    const float v = (sc >= 0.f) ? gmax[(size_t)g * CH3 + c] : gmin[(size_t)g * CH3 + c];
    out[(size_t)g * CH3 + c] = fmaxf(fmaf(v, sc, sh), 0.f);
}

// ---------------- launch ----------------
extern "C" void kernel_launch(void* const* d_in, const int* in_sizes, int n_in,
                              void* d_out, int out_size)
{
    const float* xyz    = (const float*)d_in[0];
    const float* points = (const float*)d_in[1];
    const float* w0  = (const float*)d_in[2];
    const float* b0  = (const float*)d_in[3];
    const float* g0  = (const float*)d_in[4];
    const float* bt0 = (const float*)d_in[5];
    const float* w1  = (const float*)d_in[6];
    const float* b1  = (const float*)d_in[7];
    const float* g1  = (const float*)d_in[8];
    const float* bt1 = (const float*)d_in[9];
    const float* w2  = (const float*)d_in[10];
    const float* b2  = (const float*)d_in[11];
    const float* g2  = (const float*)d_in[12];
    const float* bt2 = (const float*)d_in[13];

    float* out        = (float*)d_out;
    float* new_xyz    = out;
    float* new_points = out + (size_t)BATCH*SPTS*3;

    float *Gp, *part, *scale, *shift, *gmax, *gmin;
    uint32_t *y1, *y2;
    int* gidx;
    __half *bh0, *bl0, *bh1, *bl1, *bh2, *bl2;
    cudaGetSymbolAddress((void**)&Gp,    g_G);
    cudaGetSymbolAddress((void**)&y1,    g_y1);
    cudaGetSymbolAddress((void**)&y2,    g_y2);
    cudaGetSymbolAddress((void**)&part,  g_part);
    cudaGetSymbolAddress((void**)&scale, g_scale);
    cudaGetSymbolAddress((void**)&shift, g_shift);
    cudaGetSymbolAddress((void**)&gidx,  g_gidx);
    cudaGetSymbolAddress((void**)&gmax,  g_gmax);
    cudaGetSymbolAddress((void**)&gmin,  g_gmin);
    cudaGetSymbolAddress((void**)&bh0,   g_bh0);
    cudaGetSymbolAddress((void**)&bl0,   g_bl0);
    cudaGetSymbolAddress((void**)&bh1,   g_bh1);
    cudaGetSymbolAddress((void**)&bl1,   g_bl1);
    cudaGetSymbolAddress((void**)&bh2,   g_bh2);
    cudaGetSymbolAddress((void**)&bl2,   g_bl2);

    float* partSum = part;
    float* partSq  = part + (size_t)MBLK * CH3;

    // smem bytes: (128*LDA + 2*KC*LDB) * 2
    constexpr int SMG = (128*(64+8) + 2*64*(64+8))  * 2;   //  36,864
    constexpr int SM2 = (128*(64+8) + 2*64*(128+8)) * 2;   //  53,248
    constexpr int SMW = (128*(64+8) + 2*64*(256+8)) * 2;   //  86,016

    static bool attrDone = false;
    if (!attrDone) {
        cudaFuncSetAttribute(gemm_mma<64, 64, 64, 64, 64, 2, false, true, true, false, 2>,
                             cudaFuncAttributeMaxDynamicSharedMemorySize, SMG);
        cudaFuncSetAttribute(gemm_mma<128, 128, 64, 64, 64, 1, true, true, false, true, 2>,
                             cudaFuncAttributeMaxDynamicSharedMemorySize, SM2);
        cudaFuncSetAttribute(gemm_mma_w3<128, 64, 128>,
                             cudaFuncAttributeMaxDynamicSharedMemorySize, SMW);
        attrDone = true;
    }

    // weight prep: W0 point-part rows 3..66, W1, W2
    prep_kernel<<<(64*64 + 255)/256, 256>>>(w0, 64, CH1, 64, 3, bh0, bl0);
    prep_kernel<<<(64*128 + 255)/256, 256>>>(w1, CH1, CH2, 64, 0, bh1, bl1);
    prep_kernel<<<(128*256 + 255)/256, 256>>>(w2, CH2, CH3, 128, 0, bh2, bl2);

    // G = points . W0[3:67] + b0   (M = BATCH*NPTS = 65536, f32 output)
    gemm_mma<64, 64, 64, 64, 64, 2, false, true, true, false, 2><<<dim3(1, 512), 256, SMG>>>(
        nullptr, points, bh0, bl0, b0, nullptr, nullptr, (uint32_t*)Gp, nullptr, nullptr);

    fps_kernel<<<BATCH, 512>>>(xyz, new_xyz);
    ballquery_kernel<<<BATCH*SPTS/8, 256>>>(xyz, new_xyz, gidx);

    // layer 1: y1 = gather(G) + xyz_norm . W0[0:3]  (K=3 scalar part, no MMA)
    y1build_kernel<<<MBLK, 256>>>(Gp, gidx, xyz, new_xyz, w0, y1, partSum, partSq);
    stats_kernel<<<CH1, 256>>>(partSum, partSq, CH1, g0, bt0, scale, shift);

    // layer 2: 64 -> 128 (consumes fp16 y1)
    gemm_mma<128, 128, 64, 64, 64, 1, true, true, false, true, 2><<<dim3(1, MBLK), 256, SM2>>>(
        y1, nullptr, bh1, bl1, b1, scale, shift, y2, partSum, partSq);
    stats_kernel<<<CH2, 256>>>(partSum, partSq, CH2, g1, bt1, scale, shift);

    // layer 3: 128 -> 256 wide CTA (consumes fp16 y2; fused per-group min/max)
    gemm_mma_w3<128, 64, 128><<<MBLK, 512, SMW>>>(
        y2, bh2, bl2, b2, scale, shift, partSum, partSq, gmax, gmin);
    stats_kernel<<<CH3, 256>>>(partSum, partSq, CH3, g2, bt2, scale, shift);

    finalpool_kernel<<<BATCH*SPTS, 256>>>(gmax, gmin, scale, shift, new_points);
}

// round 13
// speedup vs baseline: 2.6674x; 1.1210x over previous
#include <cuda_runtime.h>
#include <cuda_fp16.h>
#include <math.h>
#include <stdint.h>

// ---------------- problem constants ----------------
#define BATCH 16
#define NPTS  4096
#define DFEAT 64
#define SPTS  1024
#define NSAMP 32
#define CH0   67
#define CH1   64
#define CH2   128
#define CH3   256
#define MTOT  (BATCH*SPTS*NSAMP)   // 524288
#define MBLK  (MTOT/128)           // 4096
#define RAD2  0.04f
#define BNEPS 1e-5f

typedef unsigned long long ull;

// ---------------- device scratch ----------------
__device__ float    g_G[(size_t)BATCH*NPTS*CH1];
__device__ uint32_t g_y1[(size_t)MTOT*CH1/2];      // fp16 pairs
__device__ uint32_t g_y2[(size_t)MTOT*CH2/2];      // fp16 pairs
__device__ int   g_gidx[BATCH*SPTS*NSAMP];
__device__ float g_part[2*(size_t)MBLK*CH3];       // transposed [n][MBLK]
__device__ float g_scale[CH3];
__device__ float g_shift[CH3];
__device__ float g_gmax[(size_t)BATCH*SPTS*CH3];
__device__ float g_gmin[(size_t)BATCH*SPTS*CH3];
__device__ __half g_bh0[64*64],   g_bl0[64*64];
__device__ __half g_bh1[64*128],  g_bl1[64*128];
__device__ __half g_bh2[128*256], g_bl2[128*256];

// ---------------- helpers ----------------
__device__ __forceinline__ uint32_t smem_u32(const void* p) {
    uint32_t a;
    asm("{ .reg .u64 t; cvta.to.shared.u64 t, %1; cvt.u32.u64 %0, t; }" : "=r"(a) : "l"(p));
    return a;
}
__device__ __forceinline__ void ldsm4(uint32_t* r, uint32_t a) {
    asm volatile("ldmatrix.sync.aligned.m8n8.x4.shared.b16 {%0,%1,%2,%3}, [%4];"
                 : "=r"(r[0]), "=r"(r[1]), "=r"(r[2]), "=r"(r[3]) : "r"(a));
}
__device__ __forceinline__ void ldsm4t(uint32_t* r, uint32_t a) {
    asm volatile("ldmatrix.sync.aligned.m8n8.x4.trans.shared.b16 {%0,%1,%2,%3}, [%4];"
                 : "=r"(r[0]), "=r"(r[1]), "=r"(r[2]), "=r"(r[3]) : "r"(a));
}
__device__ __forceinline__ void mma_f16(float* c, const uint32_t* a, uint32_t b0, uint32_t b1) {
    asm volatile(
        "mma.sync.aligned.m16n8k16.row.col.f32.f16.f16.f32 "
        "{%0,%1,%2,%3}, {%4,%5,%6,%7}, {%8,%9}, {%0,%1,%2,%3};"
        : "+f"(c[0]), "+f"(c[1]), "+f"(c[2]), "+f"(c[3])
        : "r"(a[0]), "r"(a[1]), "r"(a[2]), "r"(a[3]), "r"(b0), "r"(b1));
}
__device__ __forceinline__ uint32_t packh2(float v0, float v1) {
    __half2 h = __floats2half2_rn(v0, v1);
    return *(uint32_t*)&h;
}

// ---------------- FPS (512 threads, packed f32x2, REDUX tails) ----------------
__global__ __launch_bounds__(512) void fps_kernel(const float* __restrict__ xyz,
                                                  float* __restrict__ new_xyz)
{
    __shared__ float sx[NPTS], sy[NPTS], sz[NPTS];
    __shared__ unsigned s_val[2][16], s_low[2][16];
    const int b = blockIdx.x, tid = threadIdx.x;
    const int lane = tid & 31, wid = tid >> 5;
    const float* X = xyz + (size_t)b * NPTS * 3;

    ull pxp[4], pyp[4], pzp[4];
    float dist[8];
#pragma unroll
    for (int t = 0; t < 8; t++) dist[t] = 1e10f;
#pragma unroll
    for (int t = 0; t < 4; t++) {
        const int j0 = tid + (2*t) * 512, j1 = tid + (2*t+1) * 512;
        float x0 = X[3*j0], y0 = X[3*j0+1], z0 = X[3*j0+2];
        float x1 = X[3*j1], y1 = X[3*j1+1], z1 = X[3*j1+2];
        sx[j0] = x0; sy[j0] = y0; sz[j0] = z0;
        sx[j1] = x1; sy[j1] = y1; sz[j1] = z1;
        asm("mov.b64 %0, {%1,%2};" : "=l"(pxp[t]) : "f"(x0), "f"(x1));
        asm("mov.b64 %0, {%1,%2};" : "=l"(pyp[t]) : "f"(y0), "f"(y1));
        asm("mov.b64 %0, {%1,%2};" : "=l"(pzp[t]) : "f"(z0), "f"(z1));
    }
    __syncthreads();

    int far = 0;
    for (int i = 0; i < SPTS; i++) {
        const float cx = sx[far], cy = sy[far], cz = sz[far];
        if (tid == 0) {
            float* o = new_xyz + ((size_t)b * SPTS + i) * 3;
            o[0] = cx; o[1] = cy; o[2] = cz;
        }
        if (i == SPTS - 1) break;

        const float mx = -cx, my = -cy, mz = -cz;
        ull ncx, ncy, ncz;
        asm("mov.b64 %0, {%1,%1};" : "=l"(ncx) : "f"(mx));
        asm("mov.b64 %0, {%1,%1};" : "=l"(ncy) : "f"(my));
        asm("mov.b64 %0, {%1,%1};" : "=l"(ncz) : "f"(mz));

        float bv = -1.0f; int bi = 0;
#pragma unroll
        for (int t = 0; t < 4; t++) {
            ull dx, dy, dz, dd;
            asm("add.rn.f32x2 %0, %1, %2;" : "=l"(dx) : "l"(pxp[t]), "l"(ncx));
            asm("add.rn.f32x2 %0, %1, %2;" : "=l"(dy) : "l"(pyp[t]), "l"(ncy));
            asm("add.rn.f32x2 %0, %1, %2;" : "=l"(dz) : "l"(pzp[t]), "l"(ncz));
            asm("mul.rn.f32x2 %0, %1, %2;" : "=l"(dd) : "l"(dx), "l"(dx));
            asm("fma.rn.f32x2 %0, %1, %2, %3;" : "=l"(dd) : "l"(dy), "l"(dy), "l"(dd));
            asm("fma.rn.f32x2 %0, %1, %2, %3;" : "=l"(dd) : "l"(dz), "l"(dz), "l"(dd));
            float d0, d1;
            asm("mov.b64 {%0,%1}, %2;" : "=f"(d0), "=f"(d1) : "l"(dd));
            const float nd0 = fminf(dist[2*t],   d0);
            const float nd1 = fminf(dist[2*t+1], d1);
            dist[2*t]   = nd0;
            dist[2*t+1] = nd1;
            if (nd0 > bv) { bv = nd0; bi = tid + (2*t)   * 512; }
            if (nd1 > bv) { bv = nd1; bi = tid + (2*t+1) * 512; }
        }
        const unsigned vb = __float_as_uint(bv);
        const unsigned m  = __reduce_max_sync(0xffffffffu, vb);
        const unsigned lw = __reduce_max_sync(0xffffffffu,
                                              (vb == m) ? (0xFFFFu - (unsigned)bi) : 0u);
        const int buf = i & 1;
        if (lane == 0) { s_val[buf][wid] = m; s_low[buf][wid] = lw; }
        __syncthreads();

        const unsigned v2 = s_val[buf][lane & 15];
        const unsigned l2 = s_low[buf][lane & 15];
        const unsigned M  = __reduce_max_sync(0xffffffffu, v2);
        const unsigned LW = __reduce_max_sync(0xffffffffu, (v2 == M) ? l2 : 0u);
        far = 0xFFFF - (int)LW;
    }
}

// ---------------- ball query ----------------
__global__ __launch_bounds__(256) void ballquery_kernel(const float* __restrict__ xyz,
                                                        const float* __restrict__ new_xyz,
                                                        int* __restrict__ gidx)
{
    const int w    = blockIdx.x * 8 + (threadIdx.x >> 5);
    const int lane = threadIdx.x & 31;
    const int b    = w >> 10;
    const float* X = xyz + (size_t)b * NPTS * 3;

    const float cx = new_xyz[(size_t)w*3+0];
    const float cy = new_xyz[(size_t)w*3+1];
    const float cz = new_xyz[(size_t)w*3+2];
    const float ss = cx*cx + cy*cy + cz*cz;

    int cnt = 0, firstIdx = 0;
    int* out = gidx + (size_t)w * NSAMP;

    for (int base = 0; base < NPTS && cnt < NSAMP; base += 32) {
        const int j = base + lane;
        const float x = X[3*j], y = X[3*j+1], z = X[3*j+2];
        const float pp  = x*x + y*y + z*z;
        const float dot = x*cx + y*cy + z*cz;
        const float d   = (-2.0f*dot + ss) + pp;
        const bool  in  = !(d > RAD2);
        unsigned mask = __ballot_sync(0xffffffffu, in);
        if (cnt == 0 && mask) firstIdx = base + (__ffs(mask) - 1);
        int rank = __popc(mask & ((1u << lane) - 1u));
        int slot = cnt + rank;
        if (in && slot < NSAMP) out[slot] = j;
        cnt += __popc(mask);
    }
    for (int t = cnt + lane; t < NSAMP; t += 32) out[t] = firstIdx;
}

// ---------------- weight prep ----------------
__global__ __launch_bounds__(256) void prep_kernel(const float* __restrict__ W, int K, int N,
                                                   int KPAD, int KOFF,
                                                   __half* __restrict__ bh,
                                                   __half* __restrict__ bl)
{
    int i = blockIdx.x * 256 + threadIdx.x;
    if (i >= N * KPAD) return;
    int k = i / N, n = i - k * N;
    float v = (k < K) ? W[(size_t)(k + KOFF) * N + n] : 0.f;
    __half h = __float2half_rn(v);
    bh[i] = h;
    bl[i] = __float2half_rn(v - __half2float(h));
}

// ---------------- HMMA GEMM, 256 threads ----------------
// AMODE: 1 = fp16-pair u32 input, 2 = f32 row-major input (via fA).
// BSPLIT: true = B hi+lo (2 MMAs), false = single fp16 B (1 MMA).
template<int BN, int NTOT, int KPAD, int KC, int KORIG, int AMODE, bool BSPLIT,
         bool TRANSFORM, bool STORE_Y, bool YF32, bool PART, int MINB>
__global__ void __launch_bounds__(256, MINB) gemm_mma(
    const uint32_t* __restrict__ A, const float* __restrict__ fA,
    const __half* __restrict__ BH, const __half* __restrict__ BL,
    const float* __restrict__ bias,
    const float* __restrict__ scale, const float* __restrict__ shift,
    uint32_t* __restrict__ Y,
    float* __restrict__ partSum, float* __restrict__ partSq)
{
    extern __shared__ __align__(16) char dyn[];
    constexpr int LDA = KC + 8;
    constexpr int LDB = BN + 8;
    constexpr int NCHUNK = KPAD / KC;
    __half* aS  = (__half*)dyn;
    __half* bHi = aS + 128 * LDA;
    __half* bLo = BSPLIT ? (bHi + KC * LDB) : bHi;

    const int tid = threadIdx.x;
    const int nb = blockIdx.x, mb = blockIdx.y;
    const int m0 = mb * 128, n0 = nb * BN;

    const int wid = tid >> 5, lane = tid & 31;
    const int wm = wid >> 1, wn = wid & 1;
    const int mW = wm * 32, nW = wn * (BN / 2);
    constexpr int NT = BN / 16;
    constexpr int KSTEPS_C = KC / 16;

    float acc[2][NT][4];
#pragma unroll
    for (int i = 0; i < 2; i++)
#pragma unroll
        for (int j = 0; j < NT; j++)
#pragma unroll
            for (int q = 0; q < 4; q++) acc[i][j][q] = 0.f;

    const uint32_t aU   = smem_u32(aS)  + (uint32_t)(mW + (lane & 15)) * (LDA * 2) + (lane >> 4) * 16;
    const uint32_t bHiU = smem_u32(bHi) + (uint32_t)(lane & 15) * (LDB * 2) + (uint32_t)nW * 2 + (lane >> 4) * 16;
    const uint32_t bLoU = smem_u32(bLo) + (uint32_t)(lane & 15) * (LDB * 2) + (uint32_t)nW * 2 + (lane >> 4) * 16;

    for (int ch = 0; ch < NCHUNK; ch++) {
        const int kbase = ch * KC;
        if (ch > 0) __syncthreads();

        constexpr int AIT = 128 * (KC / 2);
        for (int idx = tid; idx < AIT; idx += 256) {
            const int r  = idx / (KC / 2);
            const int p  = idx - r * (KC / 2);
            const int kl = 2 * p;
            const int kk = kbase + kl;
            float v0, v1;
            if (AMODE == 2) {
                const float2 f = *(const float2*)(fA + (size_t)(m0 + r) * KORIG + kk);
                v0 = f.x; v1 = f.y;
            } else {
                const uint32_t w = A[((size_t)(m0 + r) * KORIG + kk) >> 1];
                const float2 f = __half22float2(*(const __half2*)&w);
                v0 = f.x; v1 = f.y;
                if (TRANSFORM) {
                    v0 = fmaxf(fmaf(v0, __ldg(scale + kk),     __ldg(shift + kk)),     0.f);
                    v1 = fmaxf(fmaf(v1, __ldg(scale + kk + 1), __ldg(shift + kk + 1)), 0.f);
                }
            }
            *(uint32_t*)(aS + r * LDA + kl) = packh2(v0, v1);
        }
        constexpr int BIT = KC * (BN / 2);
        for (int idx = tid; idx < BIT; idx += 256) {
            const int k = idx / (BN / 2);
            const int n = 2 * (idx - k * (BN / 2));
            *(uint32_t*)(bHi + k * LDB + n) = *(const uint32_t*)(BH + (size_t)(kbase + k) * NTOT + n0 + n);
            if (BSPLIT)
                *(uint32_t*)(bLo + k * LDB + n) = *(const uint32_t*)(BL + (size_t)(kbase + k) * NTOT + n0 + n);
        }
        __syncthreads();

#pragma unroll
        for (int ks = 0; ks < KSTEPS_C; ks++) {
            uint32_t a0[4], a1[4];
            ldsm4(a0, aU + ks * 32);
            ldsm4(a1, aU + 16 * LDA * 2 + ks * 32);
#pragma unroll
            for (int ng = 0; ng < NT / 2; ng++) {
                uint32_t bh[4];
                const uint32_t bo = (uint32_t)ks * (16 * LDB * 2) + ng * 32;
                ldsm4t(bh, bHiU + bo);
                mma_f16(acc[0][ng*2+0], a0, bh[0], bh[1]);
                mma_f16(acc[0][ng*2+1], a0, bh[2], bh[3]);
                mma_f16(acc[1][ng*2+0], a1, bh[0], bh[1]);
                mma_f16(acc[1][ng*2+1], a1, bh[2], bh[3]);
                if (BSPLIT) {
                    uint32_t bl[4];
                    ldsm4t(bl, bLoU + bo);
                    mma_f16(acc[0][ng*2+0], a0, bl[0], bl[1]);
                    mma_f16(acc[0][ng*2+1], a0, bl[2], bl[3]);
                    mma_f16(acc[1][ng*2+0], a1, bl[0], bl[1]);
                    mma_f16(acc[1][ng*2+1], a1, bl[2], bl[3]);
                }
            }
        }
    }
    __syncthreads();

    float* sSum = (float*)dyn;            // [4][BN]
    float* sSq  = sSum + 4 * BN;

    const int r0 = lane >> 2;
#pragma unroll
    for (int nt = 0; nt < NT; nt++) {
        const int colLocal = nW + nt * 8 + (lane & 3) * 2;
        const float b0 = __ldg(bias + n0 + colLocal);
        const float b1 = __ldg(bias + n0 + colLocal + 1);
        float v0 = acc[0][nt][0] + b0, v1 = acc[0][nt][1] + b1;
        float v2 = acc[0][nt][2] + b0, v3 = acc[0][nt][3] + b1;
        float v4 = acc[1][nt][0] + b0, v5 = acc[1][nt][1] + b1;
        float v6 = acc[1][nt][2] + b0, v7 = acc[1][nt][3] + b1;
        if (STORE_Y) {
            if (YF32) {
                float* yf = (float*)Y;
                const size_t base = (size_t)(m0 + mW + r0) * NTOT + n0 + colLocal;
                *(float2*)(yf + base)            = make_float2(v0, v1);
                *(float2*)(yf + base +  8*NTOT)  = make_float2(v2, v3);
                *(float2*)(yf + base + 16*NTOT)  = make_float2(v4, v5);
                *(float2*)(yf + base + 24*NTOT)  = make_float2(v6, v7);
            } else {
                const size_t base = ((size_t)(m0 + mW + r0) * NTOT + n0 + colLocal) >> 1;
                const size_t rstep = (size_t)8 * NTOT >> 1;
                Y[base]             = packh2(v0, v1);
                Y[base +     rstep] = packh2(v2, v3);
                Y[base + 2 * rstep] = packh2(v4, v5);
                Y[base + 3 * rstep] = packh2(v6, v7);
            }
        }
        if (PART) {
            float s0 = v0+v2+v4+v6,              s1 = v1+v3+v5+v7;
            float q0 = v0*v0+v2*v2+v4*v4+v6*v6,  q1 = v1*v1+v3*v3+v5*v5+v7*v7;
#pragma unroll
            for (int d = 4; d < 32; d <<= 1) {
                s0 += __shfl_xor_sync(0xffffffffu, s0, d);
                s1 += __shfl_xor_sync(0xffffffffu, s1, d);
                q0 += __shfl_xor_sync(0xffffffffu, q0, d);
                q1 += __shfl_xor_sync(0xffffffffu, q1, d);
            }
            if (lane < 4) {
                sSum[wm*BN + colLocal] = s0;  sSum[wm*BN + colLocal + 1] = s1;
                sSq [wm*BN + colLocal] = q0;  sSq [wm*BN + colLocal + 1] = q1;
            }
        }
    }
    if (PART) {
        __syncthreads();
        for (int n = tid; n < BN; n += 256) {
            float s = sSum[n] + sSum[BN + n] + sSum[2*BN + n] + sSum[3*BN + n];
            float q = sSq [n] + sSq [BN + n] + sSq [2*BN + n] + sSq [3*BN + n];
            partSum[(size_t)(n0 + n) * MBLK + mb] = s;
            partSq [(size_t)(n0 + n) * MBLK + mb] = q;
        }
    }
}

// ---------------- HMMA GEMM wide: 512 threads, BN=256, single fp16 B (layer 3) ----------------
template<int KPAD, int KC, int KORIG>
__global__ void __launch_bounds__(512, 1) gemm_mma_w3(
    const uint32_t* __restrict__ A,
    const __half* __restrict__ BH,
    const float* __restrict__ bias,
    const float* __restrict__ scale, const float* __restrict__ shift,
    float* __restrict__ partSum, float* __restrict__ partSq,
    float* __restrict__ gmax, float* __restrict__ gmin)
{
    extern __shared__ __align__(16) char dyn[];
    constexpr int BN  = 256;
    constexpr int LDA = KC + 8;
    constexpr int LDB = BN + 8;
    constexpr int NCHUNK = KPAD / KC;
    __half* aS  = (__half*)dyn;
    __half* bHi = aS + 128 * LDA;

    const int tid = threadIdx.x;
    const int mb = blockIdx.x;
    const int m0 = mb * 128;

    const int wid = tid >> 5, lane = tid & 31;
    const int wm = wid >> 2, wn = wid & 3;
    const int mW = wm * 32, nW = wn * 64;
    constexpr int NT = 8;
    constexpr int KSTEPS_C = KC / 16;

    float acc[2][NT][4];
#pragma unroll
    for (int i = 0; i < 2; i++)
#pragma unroll
        for (int j = 0; j < NT; j++)
#pragma unroll
            for (int q = 0; q < 4; q++) acc[i][j][q] = 0.f;

    const uint32_t aU   = smem_u32(aS)  + (uint32_t)(mW + (lane & 15)) * (LDA * 2) + (lane >> 4) * 16;
    const uint32_t bHiU = smem_u32(bHi) + (uint32_t)(lane & 15) * (LDB * 2) + (uint32_t)nW * 2 + (lane >> 4) * 16;

    for (int ch = 0; ch < NCHUNK; ch++) {
        const int kbase = ch * KC;
        if (ch > 0) __syncthreads();

        constexpr int AIT = 128 * (KC / 2);
        for (int idx = tid; idx < AIT; idx += 512) {
            const int r  = idx / (KC / 2);
            const int p  = idx - r * (KC / 2);
            const int kl = 2 * p;
            const int kk = kbase + kl;
            const uint32_t w = A[((size_t)(m0 + r) * KORIG + kk) >> 1];
            const float2 f = __half22float2(*(const __half2*)&w);
            float v0 = fmaxf(fmaf(f.x, __ldg(scale + kk),     __ldg(shift + kk)),     0.f);
            float v1 = fmaxf(fmaf(f.y, __ldg(scale + kk + 1), __ldg(shift + kk + 1)), 0.f);
            *(uint32_t*)(aS + r * LDA + kl) = packh2(v0, v1);
        }
        constexpr int BIT = KC * (BN / 2);
        for (int idx = tid; idx < BIT; idx += 512) {
            const int k = idx / (BN / 2);
            const int n = 2 * (idx - k * (BN / 2));
            *(uint32_t*)(bHi + k * LDB + n) = *(const uint32_t*)(BH + (size_t)(kbase + k) * BN + n);
        }
        __syncthreads();

#pragma unroll
        for (int ks = 0; ks < KSTEPS_C; ks++) {
            uint32_t a0[4], a1[4];
            ldsm4(a0, aU + ks * 32);
            ldsm4(a1, aU + 16 * LDA * 2 + ks * 32);
#pragma unroll
            for (int ng = 0; ng < NT / 2; ng++) {
                uint32_t bh[4];
                const uint32_t bo = (uint32_t)ks * (16 * LDB * 2) + ng * 32;
                ldsm4t(bh, bHiU + bo);
                mma_f16(acc[0][ng*2+0], a0, bh[0], bh[1]);
                mma_f16(acc[0][ng*2+1], a0, bh[2], bh[3]);
                mma_f16(acc[1][ng*2+0], a1, bh[0], bh[1]);
                mma_f16(acc[1][ng*2+1], a1, bh[2], bh[3]);
            }
        }
    }
    __syncthreads();

    float* sSum = (float*)dyn;
    float* sSq  = sSum + 4 * BN;

#pragma unroll
    for (int nt = 0; nt < NT; nt++) {
        const int colLocal = nW + nt * 8 + (lane & 3) * 2;
        const float b0 = __ldg(bias + colLocal);
        const float b1 = __ldg(bias + colLocal + 1);
        float v0 = acc[0][nt][0] + b0, v1 = acc[0][nt][1] + b1;
        float v2 = acc[0][nt][2] + b0, v3 = acc[0][nt][3] + b1;
        float v4 = acc[1][nt][0] + b0, v5 = acc[1][nt][1] + b1;
        float v6 = acc[1][nt][2] + b0, v7 = acc[1][nt][3] + b1;
        float s0 = v0+v2+v4+v6,              s1 = v1+v3+v5+v7;
        float q0 = v0*v0+v2*v2+v4*v4+v6*v6,  q1 = v1*v1+v3*v3+v5*v5+v7*v7;
        float mx0 = fmaxf(fmaxf(v0,v2), fmaxf(v4,v6)), mx1 = fmaxf(fmaxf(v1,v3), fmaxf(v5,v7));
        float mn0 = fminf(fminf(v0,v2), fminf(v4,v6)), mn1 = fminf(fminf(v1,v3), fminf(v5,v7));
#pragma unroll
        for (int d = 4; d < 32; d <<= 1) {
            s0 += __shfl_xor_sync(0xffffffffu, s0, d);
            s1 += __shfl_xor_sync(0xffffffffu, s1, d);
            q0 += __shfl_xor_sync(0xffffffffu, q0, d);
            q1 += __shfl_xor_sync(0xffffffffu, q1, d);
            mx0 = fmaxf(mx0, __shfl_xor_sync(0xffffffffu, mx0, d));
            mx1 = fmaxf(mx1, __shfl_xor_sync(0xffffffffu, mx1, d));
            mn0 = fminf(mn0, __shfl_xor_sync(0xffffffffu, mn0, d));
            mn1 = fminf(mn1, __shfl_xor_sync(0xffffffffu, mn1, d));
        }
        if (lane < 4) {
            sSum[wm*BN + colLocal] = s0;  sSum[wm*BN + colLocal + 1] = s1;
            sSq [wm*BN + colLocal] = q0;  sSq [wm*BN + colLocal + 1] = q1;
            const size_t grp = (size_t)(mb * 4 + wm) * CH3 + colLocal;
            gmax[grp]     = mx0;  gmax[grp + 1] = mx1;
            gmin[grp]     = mn0;  gmin[grp + 1] = mn1;
        }
    }
    __syncthreads();
    for (int n = tid; n < BN; n += 512) {
        float s = sSum[n] + sSum[BN + n] + sSum[2*BN + n] + sSum[3*BN + n];
        float q = sSq [n] + sSq [BN + n] + sSq [2*BN + n] + sSq [3*BN + n];
        partSum[(size_t)n * MBLK + mb] = s;
        partSq [(size_t)n * MBLK + mb] = q;
    }
}

// ---------------- y1build ----------------
__global__ __launch_bounds__(256) void y1build_kernel(
    const float* __restrict__ G, const int* __restrict__ gidx,
    const float* __restrict__ xyz, const float* __restrict__ nxyz,
    const float* __restrict__ w0,
    uint32_t* __restrict__ y1,
    float* __restrict__ partSum, float* __restrict__ partSq)
{
    __shared__ int   sIdx[128];
    __shared__ float sCen[12];
    __shared__ float sW[192];
    __shared__ float sXn[128*3];
    __shared__ float sRed[1024];
    const int mb = blockIdx.x, m0 = mb * 128, tid = threadIdx.x;
    const int b = mb >> 8;

    if (tid < 128) sIdx[tid] = gidx[m0 + tid];
    if (tid < 12)  sCen[tid] = nxyz[(size_t)(mb * 4) * 3 + tid];
    if (tid < 192) sW[tid]   = w0[tid];
    __syncthreads();
    if (tid < 128) {
        const int g = tid >> 5;
        const int j = sIdx[tid];
        const float* xp = xyz + ((size_t)b * NPTS + j) * 3;
        sXn[tid*3+0] = xp[0] - sCen[g*3+0];
        sXn[tid*3+1] = xp[1] - sCen[g*3+1];
        sXn[tid*3+2] = xp[2] - sCen[g*3+2];
    }
    __syncthreads();

    const int cp = tid & 31;
    const int rg = tid >> 5;
    const int c0 = 2 * cp;
    const float wx0 = sW[c0],   wy0 = sW[64+c0],   wz0 = sW[128+c0];
    const float wx1 = sW[c0+1], wy1 = sW[64+c0+1], wz1 = sW[128+c0+1];

    float s0 = 0.f, s1 = 0.f, q0 = 0.f, q1 = 0.f;
#pragma unroll 4
    for (int rr = 0; rr < 16; rr++) {
        const int r = rg * 16 + rr;
        const int j = sIdx[r];
        const float xn = sXn[r*3], yn = sXn[r*3+1], zn = sXn[r*3+2];
        const float2 gv = *(const float2*)(G + ((size_t)b * NPTS + j) * CH1 + c0);
        float v0 = fmaf(zn, wz0, fmaf(yn, wy0, fmaf(xn, wx0, gv.x)));
        float v1 = fmaf(zn, wz1, fmaf(yn, wy1, fmaf(xn, wx1, gv.y)));
        y1[(size_t)(m0 + r) * (CH1/2) + cp] = packh2(v0, v1);
        s0 += v0; s1 += v1; q0 += v0*v0; q1 += v1*v1;
    }
    sRed[rg*64 + c0]       = s0;  sRed[rg*64 + c0 + 1]       = s1;
    sRed[512 + rg*64 + c0] = q0;  sRed[512 + rg*64 + c0 + 1] = q1;
    __syncthreads();
    if (rg == 0) {
        float S0 = 0.f, S1 = 0.f, Q0 = 0.f, Q1 = 0.f;
#pragma unroll
        for (int g2 = 0; g2 < 8; g2++) {
            S0 += sRed[g2*64 + c0];       S1 += sRed[g2*64 + c0 + 1];
            Q0 += sRed[512 + g2*64 + c0]; Q1 += sRed[512 + g2*64 + c0 + 1];
        }
        partSum[(size_t)c0 * MBLK + mb]       = S0;
        partSum[(size_t)(c0 + 1) * MBLK + mb] = S1;
        partSq [(size_t)c0 * MBLK + mb]       = Q0;
        partSq [(size_t)(c0 + 1) * MBLK + mb] = Q1;
    }
}

// ---------------- fold partials -> scale/shift ----------------
__global__ __launch_bounds__(256) void stats_kernel(const float* __restrict__ partSum,
                                                    const float* __restrict__ partSq,
                                                    int N,
                                                    const float* __restrict__ g,
                                                    const float* __restrict__ bt,
                                                    float* __restrict__ scale,
                                                    float* __restrict__ shift)
{
    const int c = blockIdx.x, tid = threadIdx.x;
    __shared__ float ss[256], sq[256];
    float a = 0.f, b2 = 0.f;
    const float* ps = partSum + (size_t)c * MBLK;
    const float* pq = partSq  + (size_t)c * MBLK;
    for (int mb = tid; mb < MBLK; mb += 256) {
        a  += ps[mb];
        b2 += pq[mb];
    }
    ss[tid] = a; sq[tid] = b2;
    __syncthreads();
    for (int s = 128; s > 0; s >>= 1) {
        if (tid < s) { ss[tid] += ss[tid+s]; sq[tid] += sq[tid+s]; }
        __syncthreads();
    }
    if (tid == 0) {
        const float invM = 1.0f / (float)MTOT;
        float mean = ss[0] * invM;
        float var  = sq[0] * invM - mean * mean;
        float sc   = g[c] / sqrtf(var + BNEPS);
        scale[c] = sc;
        shift[c] = bt[c] - mean * sc;
    }
}

// ---------------- final pool ----------------
__global__ __launch_bounds__(256) void finalpool_kernel(const float* __restrict__ gmax,
                                                        const float* __restrict__ gmin,
                                                        const float* __restrict__ scale,
                                                        const float* __restrict__ shift,
                                                        float* __restrict__ out)
{
    const int g = blockIdx.x, c = threadIdx.x;
    const float sc = scale[c], sh = shift[c];
    const float v = (sc >= 0.f) ? gmax[(size_t)g * CH3 + c] : gmin[(size_t)g * CH3 + c];
    out[(size_t)g * CH3 + c] = fmaxf(fmaf(v, sc, sh), 0.f);
}

// ---------------- launch ----------------
extern "C" void kernel_launch(void* const* d_in, const int* in_sizes, int n_in,
                              void* d_out, int out_size)
{
    const float* xyz    = (const float*)d_in[0];
    const float* points = (const float*)d_in[1];
    const float* w0  = (const float*)d_in[2];
    const float* b0  = (const float*)d_in[3];
    const float* g0  = (const float*)d_in[4];
    const float* bt0 = (const float*)d_in[5];
    const float* w1  = (const float*)d_in[6];
    const float* b1  = (const float*)d_in[7];
    const float* g1  = (const float*)d_in[8];
    const float* bt1 = (const float*)d_in[9];
    const float* w2  = (const float*)d_in[10];
    const float* b2  = (const float*)d_in[11];
    const float* g2  = (const float*)d_in[12];
    const float* bt2 = (const float*)d_in[13];

    float* out        = (float*)d_out;
    float* new_xyz    = out;
    float* new_points = out + (size_t)BATCH*SPTS*3;

    float *Gp, *part, *scale, *shift, *gmax, *gmin;
    uint32_t *y1, *y2;
    int* gidx;
    __half *bh0, *bl0, *bh1, *bl1, *bh2, *bl2;
    cudaGetSymbolAddress((void**)&Gp,    g_G);
    cudaGetSymbolAddress((void**)&y1,    g_y1);
    cudaGetSymbolAddress((void**)&y2,    g_y2);
    cudaGetSymbolAddress((void**)&part,  g_part);
    cudaGetSymbolAddress((void**)&scale, g_scale);
    cudaGetSymbolAddress((void**)&shift, g_shift);
    cudaGetSymbolAddress((void**)&gidx,  g_gidx);
    cudaGetSymbolAddress((void**)&gmax,  g_gmax);
    cudaGetSymbolAddress((void**)&gmin,  g_gmin);
    cudaGetSymbolAddress((void**)&bh0,   g_bh0);
    cudaGetSymbolAddress((void**)&bl0,   g_bl0);
    cudaGetSymbolAddress((void**)&bh1,   g_bh1);
    cudaGetSymbolAddress((void**)&bl1,   g_bl1);
    cudaGetSymbolAddress((void**)&bh2,   g_bh2);
    cudaGetSymbolAddress((void**)&bl2,   g_bl2);

    float* partSum = part;
    float* partSq  = part + (size_t)MBLK * CH3;

    constexpr int SMG = (128*(64+8) + 2*64*(64+8))  * 2;   //  36,864 (B split)
    constexpr int SM2 = (128*(64+8) + 64*(128+8))   * 2;   //  35,840 (single B)
    constexpr int SMW = (128*(64+8) + 64*(256+8))   * 2;   //  52,224 (single B)

    static bool attrDone = false;
    if (!attrDone) {
        cudaFuncSetAttribute(gemm_mma<64, 64, 64, 64, 64, 2, true, false, true, true, false, 2>,
                             cudaFuncAttributeMaxDynamicSharedMemorySize, SMG);
        cudaFuncSetAttribute(gemm_mma<128, 128, 64, 64, 64, 1, false, true, true, false, true, 2>,
                             cudaFuncAttributeMaxDynamicSharedMemorySize, SM2);
        cudaFuncSetAttribute(gemm_mma_w3<128, 64, 128>,
                             cudaFuncAttributeMaxDynamicSharedMemorySize, SMW);
        attrDone = true;
    }

    prep_kernel<<<(64*64 + 255)/256, 256>>>(w0, 64, CH1, 64, 3, bh0, bl0);
    prep_kernel<<<(64*128 + 255)/256, 256>>>(w1, CH1, CH2, 64, 0, bh1, bl1);
    prep_kernel<<<(128*256 + 255)/256, 256>>>(w2, CH2, CH3, 128, 0, bh2, bl2);

    // G = points . W0[3:67] + b0  (B-split kept: error at the source stays small)
    gemm_mma<64, 64, 64, 64, 64, 2, true, false, true, true, false, 2><<<dim3(1, 512), 256, SMG>>>(
        nullptr, points, bh0, bl0, b0, nullptr, nullptr, (uint32_t*)Gp, nullptr, nullptr);

    fps_kernel<<<BATCH, 512>>>(xyz, new_xyz);
    ballquery_kernel<<<BATCH*SPTS/8, 256>>>(xyz, new_xyz, gidx);

    y1build_kernel<<<MBLK, 256>>>(Gp, gidx, xyz, new_xyz, w0, y1, partSum, partSq);
    stats_kernel<<<CH1, 256>>>(partSum, partSq, CH1, g0, bt0, scale, shift);

    // layer 2: 64 -> 128, single fp16 B
    gemm_mma<128, 128, 64, 64, 64, 1, false, true, true, false, true, 2><<<dim3(1, MBLK), 256, SM2>>>(
        y1, nullptr, bh1, bl1, b1, scale, shift, y2, partSum, partSq);
    stats_kernel<<<CH2, 256>>>(partSum, partSq, CH2, g1, bt1, scale, shift);

    // layer 3: 128 -> 256 wide CTA, single fp16 B
    gemm_mma_w3<128, 64, 128><<<MBLK, 512, SMW>>>(
        y2, bh2, b2, scale, shift, partSum, partSq, gmax, gmin);
    stats_kernel<<<CH3, 256>>>(partSum, partSq, CH3, g2, bt2, scale, shift);

    finalpool_kernel<<<BATCH*SPTS, 256>>>(gmax, gmin, scale, shift, new_points);
}